// round 11
// baseline (speedup 1.0000x reference)
#include <cuda_runtime.h>
#include <cstddef>

// Problem constants
#define B_  4
#define LQ  512
#define LK  2048
#define E_  1024
#define H_  16
#define DH  64
#define F_  4096
#define MQ  (B_*LQ)    // 2048
#define MK  (B_*LK)    // 8192

// ---------------- scratch (device globals; no allocation allowed) ----------
__device__ float g_q[MQ * E_];
__device__ float g_k[MK * E_];
__device__ float g_v[MK * E_];
__device__ float g_vt[MK * E_];
__device__ float g_ctx[MQ * E_];
__device__ float g_attnout[MQ * E_];
__device__ float g_q2[MQ * E_];
__device__ float g_ffn1[MQ * F_];
__device__ float g_ffn2[MQ * E_];
// tf32-rounded copies of external inputs
__device__ float r_query[MQ * E_];
__device__ float r_kv[MK * E_];
__device__ float r_wq[E_ * E_];
__device__ float r_wk[E_ * E_];
__device__ float r_wv[E_ * E_];
__device__ float r_wo[E_ * E_];
__device__ float r_w1[F_ * E_];
__device__ float r_w2[E_ * F_];
// softmax statistics
__device__ float2 g_sstats[64 * 16 * 512];

// ---------------------------------------------------------------------------
// helpers
// ---------------------------------------------------------------------------
__device__ __forceinline__ unsigned cvt_tf32(float x) {
    unsigned r;
    asm("cvt.rna.tf32.f32 %0, %1;" : "=r"(r) : "f"(x));
    return r;
}
__device__ __forceinline__ float round_tf32(float x) {
    return __uint_as_float(cvt_tf32(x));
}

__device__ __forceinline__ void cp_async16(unsigned saddr, const void* gptr) {
    asm volatile("cp.async.cg.shared.global [%0], [%1], 16;" :: "r"(saddr), "l"(gptr));
}
__device__ __forceinline__ void cp_commit() {
    asm volatile("cp.async.commit_group;");
}
template<int N>
__device__ __forceinline__ void cp_wait() {
    asm volatile("cp.async.wait_group %0;" :: "n"(N));
}

__device__ __forceinline__ void ldsm4(unsigned &r0, unsigned &r1,
                                      unsigned &r2, unsigned &r3, unsigned addr) {
    asm volatile("ldmatrix.sync.aligned.m8n8.x4.shared.b16 {%0,%1,%2,%3}, [%4];"
                 : "=r"(r0), "=r"(r1), "=r"(r2), "=r"(r3) : "r"(addr));
}

__device__ __forceinline__ void mma_tf32(float c[4], const unsigned a[4],
                                         const unsigned b[2]) {
    asm volatile(
        "mma.sync.aligned.m16n8k8.row.col.f32.tf32.tf32.f32 "
        "{%0,%1,%2,%3}, {%4,%5,%6,%7}, {%8,%9}, {%0,%1,%2,%3};"
        : "+f"(c[0]), "+f"(c[1]), "+f"(c[2]), "+f"(c[3])
        : "r"(a[0]), "r"(a[1]), "r"(a[2]), "r"(a[3]), "r"(b[0]), "r"(b[1]));
}

// ---------------------------------------------------------------------------
// tf32 round-copy over a list of segments (two instances: early / late)
// ---------------------------------------------------------------------------
struct RCArgs {
    const float4* src[5];
    float4*       dst[5];
    int           off[6];   // prefix offsets in float4 units; off[n]=total
    int           nseg;
};

__global__ __launch_bounds__(256)
void round_copy_seg(RCArgs rc)
{
    const int total = rc.off[rc.nseg];
    for (int i = blockIdx.x * blockDim.x + threadIdx.x; i < total;
         i += gridDim.x * blockDim.x) {
        int seg = 0;
        #pragma unroll
        for (int s = 1; s < 5; s++) if (s < rc.nseg && i >= rc.off[s]) seg = s;
        int j = i - rc.off[seg];
        float4 v = rc.src[seg][j];
        v.x = round_tf32(v.x); v.y = round_tf32(v.y);
        v.z = round_tf32(v.z); v.w = round_tf32(v.w);
        rc.dst[seg][j] = v;
    }
}

// ---------------------------------------------------------------------------
// Pipelined NT GEMM, tf32 tensor cores, BK=32, 3 stages, ONE sync per k-iter.
// Inputs pre-rounded to tf32.
// ---------------------------------------------------------------------------
template<int BM, int BN, int WM, int WN, int ROUND>
__global__ __launch_bounds__(256)
void tf32_gemm(const float* __restrict__ A, int lda,
               const float* __restrict__ B, int ldb,
               const float* __restrict__ bias,
               float* __restrict__ C, int ldc,
               int K, float scale, int relu)
{
    constexpr int WARPS_N = BN / WN;
    constexpr int MS = WM / 16, NS = WN / 8;
    constexpr int ASZ = BM * 32;
    constexpr int BSZ = BN * 32;

    extern __shared__ __align__(16) float sm[];
    float* As = sm;
    float* Bs = sm + 3 * ASZ;

    const int bm = blockIdx.y * BM, bn = blockIdx.x * BN;
    const int tid = threadIdx.x, warp = tid >> 5, lane = tid & 31;
    const int wm = (warp / WARPS_N) * WM, wn = (warp % WARPS_N) * WN;

    const unsigned as0 = (unsigned)__cvta_generic_to_shared(As);
    const unsigned bs0 = (unsigned)__cvta_generic_to_shared(Bs);

    const int ld_r = tid >> 3;
    const int ld_c = tid & 7;

    auto load_stage = [&](int buf, int k0) {
        #pragma unroll
        for (int i = 0; i < BM / 32; i++) {
            int r = ld_r + i * 32;
            int ph = ld_c ^ (r & 7);
            cp_async16(as0 + (unsigned)(buf * ASZ + r * 32 + ph * 4) * 4u,
                       A + (size_t)(bm + r) * lda + k0 + ld_c * 4);
        }
        #pragma unroll
        for (int i = 0; i < BN / 32; i++) {
            int r = ld_r + i * 32;
            int ph = ld_c ^ (r & 7);
            cp_async16(bs0 + (unsigned)(buf * BSZ + r * 32 + ph * 4) * 4u,
                       B + (size_t)(bn + r) * ldb + k0 + ld_c * 4);
        }
    };

    float acc[MS][NS][4];
    #pragma unroll
    for (int i = 0; i < MS; i++)
        #pragma unroll
        for (int j = 0; j < NS; j++)
            #pragma unroll
            for (int r = 0; r < 4; r++) acc[i][j][r] = 0.f;

    const int a_row = (lane & 7) + ((lane >> 3) & 1) * 8;
    const int a_ch  = lane >> 4;
    const int b_row = (lane & 7) + ((lane >= 16) ? 8 : 0);
    const int b_ch  = (lane >> 3) & 1;

    const int nk = K >> 5;
    load_stage(0, 0);  cp_commit();
    load_stage(1, 32); cp_commit();

    for (int ks = 0; ks < nk; ks++) {
        cp_wait<1>();
        __syncthreads();
        const int buf = ks % 3;
        if (ks + 2 < nk) load_stage((ks + 2) % 3, (ks + 2) << 5);
        cp_commit();

        #pragma unroll
        for (int k8 = 0; k8 < 4; k8++) {
            const int cb = k8 * 2;
            unsigned a[MS][4], b[NS][2];
            #pragma unroll
            for (int i = 0; i < MS; i++) {
                int r = wm + 16 * i + a_row;
                int ph = (cb + a_ch) ^ (r & 7);
                ldsm4(a[i][0], a[i][1], a[i][2], a[i][3],
                      as0 + (unsigned)(buf * ASZ + r * 32 + ph * 4) * 4u);
            }
            #pragma unroll
            for (int j = 0; j < NS / 2; j++) {
                int r = wn + 16 * j + b_row;
                int ph = (cb + b_ch) ^ (r & 7);
                ldsm4(b[2*j][0], b[2*j][1], b[2*j+1][0], b[2*j+1][1],
                      bs0 + (unsigned)(buf * BSZ + r * 32 + ph * 4) * 4u);
            }
            #pragma unroll
            for (int i = 0; i < MS; i++)
                #pragma unroll
                for (int j = 0; j < NS; j++)
                    mma_tf32(acc[i][j], a[i], b[j]);
        }
    }

    #pragma unroll
    for (int i = 0; i < MS; i++) {
        const int r = bm + wm + 16 * i + (lane >> 2);
        #pragma unroll
        for (int j = 0; j < NS; j++) {
            const int cn = bn + wn + 8 * j + 2 * (lane & 3);
            float bx = 0.f, by = 0.f;
            if (bias) { float2 bb = *(const float2*)&bias[cn]; bx = bb.x; by = bb.y; }
            float v0 = acc[i][j][0] * scale + bx;
            float v1 = acc[i][j][1] * scale + by;
            float v2 = acc[i][j][2] * scale + bx;
            float v3 = acc[i][j][3] * scale + by;
            if (relu) {
                v0 = fmaxf(v0, 0.f); v1 = fmaxf(v1, 0.f);
                v2 = fmaxf(v2, 0.f); v3 = fmaxf(v3, 0.f);
            }
            if (ROUND) {
                v0 = round_tf32(v0); v1 = round_tf32(v1);
                v2 = round_tf32(v2); v3 = round_tf32(v3);
            }
            *(float2*)&C[(size_t)r * ldc + cn]       = make_float2(v0, v1);
            *(float2*)&C[(size_t)(r + 8) * ldc + cn] = make_float2(v2, v3);
        }
    }
}

// ---------------------------------------------------------------------------
// Scores GEMM + per-slab softmax statistics.
// ---------------------------------------------------------------------------
__global__ __launch_bounds__(256)
void scores_stats(const float* __restrict__ q, const float* __restrict__ k,
                  float* __restrict__ attn, float2* __restrict__ sstats)
{
    constexpr int BM = 128, BN = 128, WM = 64, WN = 32;
    constexpr int WARPS_N = BN / WN;
    constexpr int MS = WM / 16, NS = WN / 8;
    constexpr int ASZ = BM * 16, BSZ = BN * 16;

    __shared__ __align__(16) float As[3 * ASZ];
    __shared__ __align__(16) float Bs[3 * BSZ];

    const int z = blockIdx.z;
    const int b = z >> 4, h = z & 15;
    const float* A = q + (size_t)b * LQ * E_ + h * DH;
    const float* B = k + (size_t)b * LK * E_ + h * DH;
    float* C = attn + (size_t)z * LQ * LK;

    const int bm = blockIdx.y * BM, bn = blockIdx.x * BN;
    const int tid = threadIdx.x, warp = tid >> 5, lane = tid & 31;
    const int wm = (warp / WARPS_N) * WM, wn = (warp % WARPS_N) * WN;

    const unsigned as0 = (unsigned)__cvta_generic_to_shared(As);
    const unsigned bs0 = (unsigned)__cvta_generic_to_shared(Bs);
    const int ld_r = tid >> 2, ld_c = tid & 3;

    auto load_stage = [&](int buf, int k0) {
        #pragma unroll
        for (int i = 0; i < 2; i++) {
            int r = ld_r + i * 64;
            int ph = ld_c ^ ((r >> 1) & 3);
            cp_async16(as0 + (unsigned)(buf * ASZ + r * 16 + ph * 4) * 4u,
                       A + (size_t)(bm + r) * E_ + k0 + ld_c * 4);
            cp_async16(bs0 + (unsigned)(buf * BSZ + r * 16 + ph * 4) * 4u,
                       B + (size_t)(bn + r) * E_ + k0 + ld_c * 4);
        }
    };

    float acc[MS][NS][4];
    #pragma unroll
    for (int i = 0; i < MS; i++)
        #pragma unroll
        for (int j = 0; j < NS; j++)
            #pragma unroll
            for (int r = 0; r < 4; r++) acc[i][j][r] = 0.f;

    const int a_row = (lane & 7) + ((lane >> 3) & 1) * 8;
    const int a_ch  = lane >> 4;
    const int b_row = (lane & 7) + ((lane >= 16) ? 8 : 0);
    const int b_ch  = (lane >> 3) & 1;

    const int nk = DH >> 4;
    load_stage(0, 0);  cp_commit();
    load_stage(1, 16); cp_commit();

    for (int ks = 0; ks < nk; ks++) {
        cp_wait<1>();
        __syncthreads();
        const int buf = ks % 3;
        if (ks + 2 < nk) load_stage((ks + 2) % 3, (ks + 2) << 4);
        cp_commit();

        #pragma unroll
        for (int k8 = 0; k8 < 2; k8++) {
            const int cb = k8 * 2;
            unsigned a[MS][4], bfr[NS][2];
            #pragma unroll
            for (int i = 0; i < MS; i++) {
                int r = wm + 16 * i + a_row;
                int ph = (cb + a_ch) ^ ((r >> 1) & 3);
                ldsm4(a[i][0], a[i][1], a[i][2], a[i][3],
                      as0 + (unsigned)(buf * ASZ + r * 16 + ph * 4) * 4u);
            }
            #pragma unroll
            for (int j = 0; j < NS / 2; j++) {
                int r = wn + 16 * j + b_row;
                int ph = (cb + b_ch) ^ ((r >> 1) & 3);
                ldsm4(bfr[2*j][0], bfr[2*j][1], bfr[2*j+1][0], bfr[2*j+1][1],
                      bs0 + (unsigned)(buf * BSZ + r * 16 + ph * 4) * 4u);
            }
            #pragma unroll
            for (int i = 0; i < MS; i++)
                #pragma unroll
                for (int j = 0; j < NS; j++)
                    mma_tf32(acc[i][j], a[i], bfr[j]);
        }
        __syncthreads();
    }

    #pragma unroll
    for (int i = 0; i < MS; i++)
        #pragma unroll
        for (int j = 0; j < NS; j++)
            #pragma unroll
            for (int r = 0; r < 4; r++) acc[i][j][r] *= 0.125f;

    #pragma unroll
    for (int i = 0; i < MS; i++) {
        const int r = bm + wm + 16 * i + (lane >> 2);
        #pragma unroll
        for (int j = 0; j < NS; j++) {
            const int cn = bn + wn + 8 * j + 2 * (lane & 3);
            *(float2*)&C[(size_t)r * LK + cn]       = make_float2(acc[i][j][0], acc[i][j][1]);
            *(float2*)&C[(size_t)(r + 8) * LK + cn] = make_float2(acc[i][j][2], acc[i][j][3]);
        }
    }

    float* sm_m = As;
    float* sm_s = As + 512;
    __syncthreads();

    const int ng = warp % WARPS_N;
    #pragma unroll
    for (int i = 0; i < MS; i++) {
        #pragma unroll
        for (int hh = 0; hh < 2; hh++) {
            float v[8];
            #pragma unroll
            for (int j = 0; j < NS; j++) {
                v[2*j]   = acc[i][j][2*hh];
                v[2*j+1] = acc[i][j][2*hh+1];
            }
            float m = v[0];
            #pragma unroll
            for (int e = 1; e < 8; e++) m = fmaxf(m, v[e]);
            m = fmaxf(m, __shfl_xor_sync(0xffffffffu, m, 1));
            m = fmaxf(m, __shfl_xor_sync(0xffffffffu, m, 2));
            float se = 0.f;
            #pragma unroll
            for (int e = 0; e < 8; e++) se += __expf(v[e] - m);
            se += __shfl_xor_sync(0xffffffffu, se, 1);
            se += __shfl_xor_sync(0xffffffffu, se, 2);
            if ((lane & 3) == 0) {
                int row = wm + 16 * i + (lane >> 2) + 8 * hh;
                sm_m[ng * 128 + row] = m;
                sm_s[ng * 128 + row] = se;
            }
        }
    }
    __syncthreads();

    if (tid < 128) {
        float m0 = sm_m[tid], m1 = sm_m[128 + tid];
        float m2 = sm_m[256 + tid], m3 = sm_m[384 + tid];
        float M = fmaxf(fmaxf(m0, m1), fmaxf(m2, m3));
        float S = sm_s[tid]       * __expf(m0 - M)
                + sm_s[128 + tid] * __expf(m1 - M)
                + sm_s[256 + tid] * __expf(m2 - M)
                + sm_s[384 + tid] * __expf(m3 - M);
        sstats[((size_t)z * 16 + blockIdx.x) * LQ + bm + tid] = make_float2(M, S);
    }
}

// ---------------------------------------------------------------------------
// Fused rowcombine + normalize + ctx GEMM.
// ---------------------------------------------------------------------------
__global__ __launch_bounds__(256)
void ctx_fused(const float2* __restrict__ sstats,
               float* __restrict__ attn,
               const float* __restrict__ vt,
               float* __restrict__ ctx)
{
    constexpr int BM = 128, BN = 64, WM = 32, WN = 32;
    constexpr int WARPS_N = BN / WN;
    constexpr int MS = WM / 16, NS = WN / 8;
    constexpr int ASZ = BM * 16, BSZ = BN * 16;

    __shared__ __align__(16) float As[2 * ASZ];
    __shared__ __align__(16) float Bs[3 * BSZ];
    __shared__ float2 rs[BM];

    const int z = blockIdx.y;
    const int b = z >> 4, h = z & 15;
    const int bm = blockIdx.x * BM;
    float* Sp = attn + ((size_t)z * LQ + bm) * LK;
    const float* Vb = vt + ((size_t)b * E_ + h * DH) * LK;
    float* Cp = ctx + ((size_t)b * LQ + bm) * E_ + h * DH;

    const int tid = threadIdx.x, warp = tid >> 5, lane = tid & 31;
    const int wm = (warp / WARPS_N) * WM, wn = (warp % WARPS_N) * WN;

    const unsigned as0 = (unsigned)__cvta_generic_to_shared(As);
    const unsigned bs0 = (unsigned)__cvta_generic_to_shared(Bs);
    const int ld_r = tid >> 2, ld_c = tid & 3;
    const int ph0 = ld_c ^ ((ld_r >> 1) & 3);
    const int ph1 = ld_c ^ (((ld_r + 64) >> 1) & 3);

    auto loadB = [&](int buf, int k0) {
        int ph = ld_c ^ ((ld_r >> 1) & 3);
        cp_async16(bs0 + (unsigned)(buf * BSZ + ld_r * 16 + ph * 4) * 4u,
                   Vb + (size_t)ld_r * LK + k0 + ld_c * 4);
    };

    loadB(0, 0);  cp_commit();
    loadB(1, 16); cp_commit();

    // inline rowcombine: per-row merge of 16 slab stats -> (M, 1/S)
    if (tid < BM) {
        const float2* p = sstats + (size_t)z * 16 * LQ + bm + tid;
        float2 v[16];
        #pragma unroll
        for (int s = 0; s < 16; s++) v[s] = p[(size_t)s * LQ];
        float M = v[0].x;
        #pragma unroll
        for (int s = 1; s < 16; s++) M = fmaxf(M, v[s].x);
        float S = 0.f;
        #pragma unroll
        for (int s = 0; s < 16; s++) S += v[s].y * __expf(v[s].x - M);
        rs[tid] = make_float2(M, 1.0f / S);
    }

    float4 s0 = *(const float4*)&Sp[(size_t)ld_r * LK + ld_c * 4];
    float4 s1 = *(const float4*)&Sp[(size_t)(ld_r + 64) * LK + ld_c * 4];

    __syncthreads();
    const float2 st0 = rs[ld_r];
    const float2 st1 = rs[ld_r + 64];

    float acc[MS][NS][4];
    #pragma unroll
    for (int i = 0; i < MS; i++)
        #pragma unroll
        for (int j = 0; j < NS; j++)
            #pragma unroll
            for (int r = 0; r < 4; r++) acc[i][j][r] = 0.f;

    const int a_row = (lane & 7) + ((lane >> 3) & 1) * 8;
    const int a_ch  = lane >> 4;
    const int b_row = (lane & 7) + ((lane >= 16) ? 8 : 0);
    const int b_ch  = (lane >> 3) & 1;

    const int nk = LK >> 4;
    for (int t = 0; t < nk; t++) {
        const int abuf = t & 1;
        float4 p0, p1;
        p0.x = round_tf32(__expf(s0.x - st0.x) * st0.y);
        p0.y = round_tf32(__expf(s0.y - st0.x) * st0.y);
        p0.z = round_tf32(__expf(s0.z - st0.x) * st0.y);
        p0.w = round_tf32(__expf(s0.w - st0.x) * st0.y);
        p1.x = round_tf32(__expf(s1.x - st1.x) * st1.y);
        p1.y = round_tf32(__expf(s1.y - st1.x) * st1.y);
        p1.z = round_tf32(__expf(s1.z - st1.x) * st1.y);
        p1.w = round_tf32(__expf(s1.w - st1.x) * st1.y);
        *(float4*)&As[abuf * ASZ + ld_r * 16 + ph0 * 4]        = p0;
        *(float4*)&As[abuf * ASZ + (ld_r + 64) * 16 + ph1 * 4] = p1;
        *(float4*)&Sp[(size_t)ld_r * LK + t * 16 + ld_c * 4]        = p0;
        *(float4*)&Sp[(size_t)(ld_r + 64) * LK + t * 16 + ld_c * 4] = p1;
        if (t + 1 < nk) {
            s0 = *(const float4*)&Sp[(size_t)ld_r * LK + (t + 1) * 16 + ld_c * 4];
            s1 = *(const float4*)&Sp[(size_t)(ld_r + 64) * LK + (t + 1) * 16 + ld_c * 4];
        }
        cp_wait<1>();
        __syncthreads();
        if (t + 2 < nk) loadB((t + 2) % 3, (t + 2) * 16);
        cp_commit();

        const int bbuf = t % 3;
        #pragma unroll
        for (int k8 = 0; k8 < 2; k8++) {
            const int cb = k8 * 2;
            unsigned a[MS][4], bfr[NS][2];
            #pragma unroll
            for (int i = 0; i < MS; i++) {
                int r = wm + 16 * i + a_row;
                int ph = (cb + a_ch) ^ ((r >> 1) & 3);
                ldsm4(a[i][0], a[i][1], a[i][2], a[i][3],
                      as0 + (unsigned)(abuf * ASZ + r * 16 + ph * 4) * 4u);
            }
            #pragma unroll
            for (int j = 0; j < NS / 2; j++) {
                int r = wn + 16 * j + b_row;
                int ph = (cb + b_ch) ^ ((r >> 1) & 3);
                ldsm4(bfr[2*j][0], bfr[2*j][1], bfr[2*j+1][0], bfr[2*j+1][1],
                      bs0 + (unsigned)(bbuf * BSZ + r * 16 + ph * 4) * 4u);
            }
            #pragma unroll
            for (int i = 0; i < MS; i++)
                #pragma unroll
                for (int j = 0; j < NS; j++)
                    mma_tf32(acc[i][j], a[i], bfr[j]);
        }
    }

    #pragma unroll
    for (int i = 0; i < MS; i++) {
        const int r = wm + 16 * i + (lane >> 2);
        #pragma unroll
        for (int j = 0; j < NS; j++) {
            const int cn = wn + 8 * j + 2 * (lane & 3);
            float v0 = round_tf32(acc[i][j][0]);
            float v1 = round_tf32(acc[i][j][1]);
            float v2 = round_tf32(acc[i][j][2]);
            float v3 = round_tf32(acc[i][j][3]);
            *(float2*)&Cp[(size_t)r * E_ + cn]       = make_float2(v0, v1);
            *(float2*)&Cp[(size_t)(r + 8) * E_ + cn] = make_float2(v2, v3);
        }
    }
}

// ---------------------------------------------------------------------------
// Per-batch transpose of V
// ---------------------------------------------------------------------------
__global__ __launch_bounds__(256)
void transpose_v(const float* __restrict__ v, float* __restrict__ vt)
{
    __shared__ float t[32][33];
    const int b  = blockIdx.z;
    const int k0 = blockIdx.x * 32;
    const int n0 = blockIdx.y * 32;
    const int tx = threadIdx.x, ty = threadIdx.y;

    #pragma unroll
    for (int i = ty; i < 32; i += 8)
        t[i][tx] = v[((size_t)b * LK + k0 + i) * E_ + n0 + tx];
    __syncthreads();
    #pragma unroll
    for (int i = ty; i < 32; i += 8)
        vt[((size_t)b * E_ + n0 + i) * LK + k0 + tx] = t[tx][i];
}

// ---------------------------------------------------------------------------
// out = LayerNorm(a + b) * g + beta
// ---------------------------------------------------------------------------
template<int ROUND>
__global__ __launch_bounds__(256)
void ln_residual(const float* __restrict__ A, const float* __restrict__ Bx,
                 const float* __restrict__ g, const float* __restrict__ be,
                 float* __restrict__ out)
{
    const size_t row = blockIdx.x;
    const int t = threadIdx.x;

    float4 a = ((const float4*)(A  + row * E_))[t];
    float4 b = ((const float4*)(Bx + row * E_))[t];
    float4 x = make_float4(a.x + b.x, a.y + b.y, a.z + b.z, a.w + b.w);

    float s  = x.x + x.y + x.z + x.w;
    float ss = x.x*x.x + x.y*x.y + x.z*x.z + x.w*x.w;

    __shared__ float rs_[8], rss[8];
    #pragma unroll
    for (int o = 16; o > 0; o >>= 1) {
        s  += __shfl_xor_sync(0xffffffffu, s,  o);
        ss += __shfl_xor_sync(0xffffffffu, ss, o);
    }
    if ((t & 31) == 0) { rs_[t >> 5] = s; rss[t >> 5] = ss; }
    __syncthreads();
    s = 0.f; ss = 0.f;
    #pragma unroll
    for (int i = 0; i < 8; i++) { s += rs_[i]; ss += rss[i]; }

    const float mean = s * (1.0f / E_);
    const float var  = ss * (1.0f / E_) - mean * mean;
    const float inv  = rsqrtf(var + 1e-5f);

    float4 gg = ((const float4*)g)[t];
    float4 bb = ((const float4*)be)[t];
    float4 o;
    o.x = (x.x - mean) * inv * gg.x + bb.x;
    o.y = (x.y - mean) * inv * gg.y + bb.y;
    o.z = (x.z - mean) * inv * gg.z + bb.z;
    o.w = (x.w - mean) * inv * gg.w + bb.w;
    if (ROUND) {
        o.x = round_tf32(o.x); o.y = round_tf32(o.y);
        o.z = round_tf32(o.z); o.w = round_tf32(o.w);
    }
    ((float4*)(out + row * E_))[t] = o;
}

// ---------------------------------------------------------------------------
extern "C" void kernel_launch(void* const* d_in, const int* in_sizes, int n_in,
                              void* d_out, int out_size)
{
    const float* query = (const float*)d_in[0];
    const float* keyv  = (const float*)d_in[1];
    const float* wq = (const float*)d_in[2];
    const float* wk = (const float*)d_in[3];
    const float* wv = (const float*)d_in[4];
    const float* bq = (const float*)d_in[5];
    const float* bk = (const float*)d_in[6];
    const float* bv = (const float*)d_in[7];
    const float* wo = (const float*)d_in[8];
    const float* bo = (const float*)d_in[9];
    const float* g1 = (const float*)d_in[10];
    const float* be1 = (const float*)d_in[11];
    const float* w1 = (const float*)d_in[12];
    const float* b1 = (const float*)d_in[13];
    const float* w2 = (const float*)d_in[14];
    const float* b2 = (const float*)d_in[15];
    const float* g2 = (const float*)d_in[16];
    const float* be2 = (const float*)d_in[17];

    float* out = (float*)d_out;
    float* q3_out = out;
    float* attn   = out + (size_t)MQ * E_;

    float *gq, *gk, *gv, *gvt, *gctx, *gao, *gq2, *gf1, *gf2;
    float *rq, *rkv, *rwq, *rwk, *rwv, *rwo, *rw1, *rw2;
    float2 *sst;
    cudaGetSymbolAddress((void**)&gq,  g_q);
    cudaGetSymbolAddress((void**)&gk,  g_k);
    cudaGetSymbolAddress((void**)&gv,  g_v);
    cudaGetSymbolAddress((void**)&gvt, g_vt);
    cudaGetSymbolAddress((void**)&gctx, g_ctx);
    cudaGetSymbolAddress((void**)&gao, g_attnout);
    cudaGetSymbolAddress((void**)&gq2, g_q2);
    cudaGetSymbolAddress((void**)&gf1, g_ffn1);
    cudaGetSymbolAddress((void**)&gf2, g_ffn2);
    cudaGetSymbolAddress((void**)&rq,  r_query);
    cudaGetSymbolAddress((void**)&rkv, r_kv);
    cudaGetSymbolAddress((void**)&rwq, r_wq);
    cudaGetSymbolAddress((void**)&rwk, r_wk);
    cudaGetSymbolAddress((void**)&rwv, r_wv);
    cudaGetSymbolAddress((void**)&rwo, r_wo);
    cudaGetSymbolAddress((void**)&rw1, r_w1);
    cudaGetSymbolAddress((void**)&rw2, r_w2);
    cudaGetSymbolAddress((void**)&sst, g_sstats);

    // one-time setup: smem attrs + side streams/events for capture forks
    static cudaStream_t s1 = nullptr, s2 = nullptr;
    static cudaEvent_t e0, e1, e2, e3;
    if (!s1) {
        cudaFuncSetAttribute(tf32_gemm<128,128,64,32,0>,
                             cudaFuncAttributeMaxDynamicSharedMemorySize, 98304);
        cudaFuncSetAttribute(tf32_gemm<128,128,64,32,1>,
                             cudaFuncAttributeMaxDynamicSharedMemorySize, 98304);
        cudaFuncSetAttribute(tf32_gemm<128,64,32,32,0>,
                             cudaFuncAttributeMaxDynamicSharedMemorySize, 73728);
        cudaFuncSetAttribute(tf32_gemm<128,64,32,32,1>,
                             cudaFuncAttributeMaxDynamicSharedMemorySize, 73728);
        cudaStreamCreateWithFlags(&s1, cudaStreamNonBlocking);
        cudaStreamCreateWithFlags(&s2, cudaStreamNonBlocking);
        cudaEventCreateWithFlags(&e0, cudaEventDisableTiming);
        cudaEventCreateWithFlags(&e1, cudaEventDisableTiming);
        cudaEventCreateWithFlags(&e2, cudaEventDisableTiming);
        cudaEventCreateWithFlags(&e3, cudaEventDisableTiming);
    }
    const int GS128 = 98304;
    const int GS64  = 73728;

    // ---- early prepass: only what the Q/K/V projections need ----
    {
        RCArgs rc;
        rc.src[0] = (const float4*)query; rc.dst[0] = (float4*)rq;
        rc.src[1] = (const float4*)keyv;  rc.dst[1] = (float4*)rkv;
        rc.src[2] = (const float4*)wq;    rc.dst[2] = (float4*)rwq;
        rc.src[3] = (const float4*)wk;    rc.dst[3] = (float4*)rwk;
        rc.src[4] = (const float4*)wv;    rc.dst[4] = (float4*)rwv;
        rc.off[0] = 0;
        rc.off[1] = MQ*E_/4;
        rc.off[2] = rc.off[1] + MK*E_/4;
        rc.off[3] = rc.off[2] + E_*E_/4;
        rc.off[4] = rc.off[3] + E_*E_/4;
        rc.off[5] = rc.off[4] + E_*E_/4;
        rc.nseg = 5;
        round_copy_seg<<<2048, 256>>>(rc);
    }

    // fork: default = K proj, s1 = V proj + transpose, s2 = Q proj + late prepass
    cudaEventRecord(e0, 0);
    cudaStreamWaitEvent(s1, e0, 0);
    cudaStreamWaitEvent(s2, e0, 0);

    tf32_gemm<128,128,64,32,1><<<dim3(E_/128, MK/128), 256, GS128>>>(
        rkv, E_,  rwk, E_,  bk,  gk, E_,  E_, 1.f, 0);

    tf32_gemm<128,128,64,32,1><<<dim3(E_/128, MK/128), 256, GS128, s1>>>(
        rkv, E_,  rwv, E_,  bv,  gv, E_,  E_, 1.f, 0);
    transpose_v<<<dim3(LK/32, E_/32, B_), dim3(32, 8), 0, s1>>>(gv, gvt);
    cudaEventRecord(e1, s1);

    tf32_gemm<128,64,32,32,1><<<dim3(E_/64, MQ/128), 256, GS64, s2>>>(
        rq,  E_,  rwq, E_,  bq,  gq, E_,  E_, 1.f, 0);
    cudaEventRecord(e2, s2);

    // late prepass on s2 (wo, w1, w2), hidden under K-proj/scores
    {
        RCArgs rc;
        rc.src[0] = (const float4*)wo; rc.dst[0] = (float4*)rwo;
        rc.src[1] = (const float4*)w1; rc.dst[1] = (float4*)rw1;
        rc.src[2] = (const float4*)w2; rc.dst[2] = (float4*)rw2;
        rc.off[0] = 0;
        rc.off[1] = E_*E_/4;
        rc.off[2] = rc.off[1] + F_*E_/4;
        rc.off[3] = rc.off[2] + E_*F_/4;
        rc.off[4] = rc.off[3];
        rc.off[5] = rc.off[3];
        rc.nseg = 3;
        round_copy_seg<<<1024, 256, 0, s2>>>(rc);
    }
    cudaEventRecord(e3, s2);

    // join: scores needs Q (s2) and K (default)
    cudaStreamWaitEvent(0, e2, 0);
    scores_stats<<<dim3(LK/128, LQ/128, B_*H_), 256>>>(gq, gk, attn, sst);

    // ctx needs transpose (s1); rowcombine folded into ctx_fused
    cudaStreamWaitEvent(0, e1, 0);
    ctx_fused<<<dim3(LQ/128, B_*H_), 256>>>(sst, attn, gvt, gctx);

    // ---- output projection + LN1 (needs late weights: e3) ----
    cudaStreamWaitEvent(0, e3, 0);
    tf32_gemm<128,64,32,32,0><<<dim3(E_/64, MQ/128), 256, GS64>>>(
        gctx, E_,  rwo, E_,  bo,  gao, E_,  E_, 1.f, 0);
    ln_residual<1><<<MQ, 256>>>(query, gao, g1, be1, gq2);

    // ---- FFN + LN2 ----
    tf32_gemm<128,128,64,32,1><<<dim3(F_/128, MQ/128), 256, GS128>>>(
        gq2, E_,  rw1, E_,  b1,  gf1, F_,  E_, 1.f, 1);
    tf32_gemm<128,64,32,32,0><<<dim3(E_/64, MQ/128), 256, GS64>>>(
        gf1, F_,  rw2, F_,  b2,  gf2, E_,  F_, 1.f, 0);
    ln_residual<0><<<MQ, 256>>>(gq2, gf2, g2, be2, q3_out);
}

// round 12
// speedup vs baseline: 1.5465x; 1.5465x over previous
#include <cuda_runtime.h>
#include <cstddef>

// Problem constants
#define B_  4
#define LQ  512
#define LK  2048
#define E_  1024
#define H_  16
#define DH  64
#define F_  4096
#define MQ  (B_*LQ)    // 2048
#define MK  (B_*LK)    // 8192

// ---------------- scratch (device globals; no allocation allowed) ----------
__device__ float g_q[MQ * E_];
__device__ float g_k[MK * E_];
__device__ float g_v[MK * E_];
__device__ float g_vt[MK * E_];
__device__ float g_ctx[MQ * E_];
__device__ float g_attnout[MQ * E_];
__device__ float g_q2[MQ * E_];
__device__ float g_ffn1[MQ * F_];
__device__ float g_ffn2[MQ * E_];
// tf32-rounded copies of external inputs
__device__ float r_query[MQ * E_];
__device__ float r_kv[MK * E_];
__device__ float r_wq[E_ * E_];
__device__ float r_wk[E_ * E_];
__device__ float r_wv[E_ * E_];
__device__ float r_wo[E_ * E_];
__device__ float r_w1[F_ * E_];
__device__ float r_w2[E_ * F_];
// softmax statistics
__device__ float2 g_sstats[64 * 16 * 512];
__device__ float2 g_rowstats[64 * 512];

// ---------------------------------------------------------------------------
// helpers
// ---------------------------------------------------------------------------
__device__ __forceinline__ unsigned cvt_tf32(float x) {
    unsigned r;
    asm("cvt.rna.tf32.f32 %0, %1;" : "=r"(r) : "f"(x));
    return r;
}
__device__ __forceinline__ float round_tf32(float x) {
    return __uint_as_float(cvt_tf32(x));
}

__device__ __forceinline__ void cp_async16(unsigned saddr, const void* gptr) {
    asm volatile("cp.async.cg.shared.global [%0], [%1], 16;" :: "r"(saddr), "l"(gptr));
}
__device__ __forceinline__ void cp_commit() {
    asm volatile("cp.async.commit_group;");
}
template<int N>
__device__ __forceinline__ void cp_wait() {
    asm volatile("cp.async.wait_group %0;" :: "n"(N));
}

__device__ __forceinline__ void ldsm4(unsigned &r0, unsigned &r1,
                                      unsigned &r2, unsigned &r3, unsigned addr) {
    asm volatile("ldmatrix.sync.aligned.m8n8.x4.shared.b16 {%0,%1,%2,%3}, [%4];"
                 : "=r"(r0), "=r"(r1), "=r"(r2), "=r"(r3) : "r"(addr));
}

__device__ __forceinline__ void mma_tf32(float c[4], const unsigned a[4],
                                         const unsigned b[2]) {
    asm volatile(
        "mma.sync.aligned.m16n8k8.row.col.f32.tf32.tf32.f32 "
        "{%0,%1,%2,%3}, {%4,%5,%6,%7}, {%8,%9}, {%0,%1,%2,%3};"
        : "+f"(c[0]), "+f"(c[1]), "+f"(c[2]), "+f"(c[3])
        : "r"(a[0]), "r"(a[1]), "r"(a[2]), "r"(a[3]), "r"(b[0]), "r"(b[1]));
}

// ---------------------------------------------------------------------------
// Merged tf32 round-copy for all external inputs (one kernel)
// ---------------------------------------------------------------------------
struct RCArgs {
    const float4* src[8];
    float4*       dst[8];
};
#define RC_N0 (MQ*E_/4)
#define RC_N1 (MK*E_/4)
#define RC_NW (E_*E_/4)
#define RC_NF (F_*E_/4)
__constant__ int rc_off[9] = {
    0,
    RC_N0,
    RC_N0 + RC_N1,
    RC_N0 + RC_N1 + RC_NW,
    RC_N0 + RC_N1 + 2*RC_NW,
    RC_N0 + RC_N1 + 3*RC_NW,
    RC_N0 + RC_N1 + 4*RC_NW,
    RC_N0 + RC_N1 + 4*RC_NW + RC_NF,
    RC_N0 + RC_N1 + 4*RC_NW + 2*RC_NF
};

__global__ __launch_bounds__(256)
void round_copy_all(RCArgs rc, int total)
{
    for (int i = blockIdx.x * blockDim.x + threadIdx.x; i < total;
         i += gridDim.x * blockDim.x) {
        int seg = 0;
        #pragma unroll
        for (int s = 1; s < 8; s++) if (i >= rc_off[s]) seg = s;
        int j = i - rc_off[seg];
        float4 v = rc.src[seg][j];
        v.x = round_tf32(v.x); v.y = round_tf32(v.y);
        v.z = round_tf32(v.z); v.w = round_tf32(v.w);
        rc.dst[seg][j] = v;
    }
}

// ---------------------------------------------------------------------------
// Pipelined NT GEMM, tf32 tensor cores, BK=32, 3 stages, ONE sync per k-iter.
// Inputs pre-rounded to tf32.
// ---------------------------------------------------------------------------
template<int BM, int BN, int WM, int WN, int ROUND>
__global__ __launch_bounds__(256)
void tf32_gemm(const float* __restrict__ A, int lda,
               const float* __restrict__ B, int ldb,
               const float* __restrict__ bias,
               float* __restrict__ C, int ldc,
               int K, float scale, int relu)
{
    constexpr int WARPS_N = BN / WN;
    constexpr int MS = WM / 16, NS = WN / 8;
    constexpr int ASZ = BM * 32;
    constexpr int BSZ = BN * 32;

    extern __shared__ __align__(16) float sm[];
    float* As = sm;
    float* Bs = sm + 3 * ASZ;

    const int bm = blockIdx.y * BM, bn = blockIdx.x * BN;
    const int tid = threadIdx.x, warp = tid >> 5, lane = tid & 31;
    const int wm = (warp / WARPS_N) * WM, wn = (warp % WARPS_N) * WN;

    const unsigned as0 = (unsigned)__cvta_generic_to_shared(As);
    const unsigned bs0 = (unsigned)__cvta_generic_to_shared(Bs);

    const int ld_r = tid >> 3;
    const int ld_c = tid & 7;

    auto load_stage = [&](int buf, int k0) {
        #pragma unroll
        for (int i = 0; i < BM / 32; i++) {
            int r = ld_r + i * 32;
            int ph = ld_c ^ (r & 7);
            cp_async16(as0 + (unsigned)(buf * ASZ + r * 32 + ph * 4) * 4u,
                       A + (size_t)(bm + r) * lda + k0 + ld_c * 4);
        }
        #pragma unroll
        for (int i = 0; i < BN / 32; i++) {
            int r = ld_r + i * 32;
            int ph = ld_c ^ (r & 7);
            cp_async16(bs0 + (unsigned)(buf * BSZ + r * 32 + ph * 4) * 4u,
                       B + (size_t)(bn + r) * ldb + k0 + ld_c * 4);
        }
    };

    float acc[MS][NS][4];
    #pragma unroll
    for (int i = 0; i < MS; i++)
        #pragma unroll
        for (int j = 0; j < NS; j++)
            #pragma unroll
            for (int r = 0; r < 4; r++) acc[i][j][r] = 0.f;

    const int a_row = (lane & 7) + ((lane >> 3) & 1) * 8;
    const int a_ch  = lane >> 4;
    const int b_row = (lane & 7) + ((lane >= 16) ? 8 : 0);
    const int b_ch  = (lane >> 3) & 1;

    const int nk = K >> 5;
    load_stage(0, 0);  cp_commit();
    load_stage(1, 32); cp_commit();

    for (int ks = 0; ks < nk; ks++) {
        cp_wait<1>();
        __syncthreads();
        const int buf = ks % 3;
        if (ks + 2 < nk) load_stage((ks + 2) % 3, (ks + 2) << 5);
        cp_commit();

        #pragma unroll
        for (int k8 = 0; k8 < 4; k8++) {
            const int cb = k8 * 2;
            unsigned a[MS][4], b[NS][2];
            #pragma unroll
            for (int i = 0; i < MS; i++) {
                int r = wm + 16 * i + a_row;
                int ph = (cb + a_ch) ^ (r & 7);
                ldsm4(a[i][0], a[i][1], a[i][2], a[i][3],
                      as0 + (unsigned)(buf * ASZ + r * 32 + ph * 4) * 4u);
            }
            #pragma unroll
            for (int j = 0; j < NS / 2; j++) {
                int r = wn + 16 * j + b_row;
                int ph = (cb + b_ch) ^ (r & 7);
                ldsm4(b[2*j][0], b[2*j][1], b[2*j+1][0], b[2*j+1][1],
                      bs0 + (unsigned)(buf * BSZ + r * 32 + ph * 4) * 4u);
            }
            #pragma unroll
            for (int i = 0; i < MS; i++)
                #pragma unroll
                for (int j = 0; j < NS; j++)
                    mma_tf32(acc[i][j], a[i], b[j]);
        }
    }

    #pragma unroll
    for (int i = 0; i < MS; i++) {
        const int r = bm + wm + 16 * i + (lane >> 2);
        #pragma unroll
        for (int j = 0; j < NS; j++) {
            const int cn = bn + wn + 8 * j + 2 * (lane & 3);
            float bx = 0.f, by = 0.f;
            if (bias) { float2 bb = *(const float2*)&bias[cn]; bx = bb.x; by = bb.y; }
            float v0 = acc[i][j][0] * scale + bx;
            float v1 = acc[i][j][1] * scale + by;
            float v2 = acc[i][j][2] * scale + bx;
            float v3 = acc[i][j][3] * scale + by;
            if (relu) {
                v0 = fmaxf(v0, 0.f); v1 = fmaxf(v1, 0.f);
                v2 = fmaxf(v2, 0.f); v3 = fmaxf(v3, 0.f);
            }
            if (ROUND) {
                v0 = round_tf32(v0); v1 = round_tf32(v1);
                v2 = round_tf32(v2); v3 = round_tf32(v3);
            }
            *(float2*)&C[(size_t)r * ldc + cn]       = make_float2(v0, v1);
            *(float2*)&C[(size_t)(r + 8) * ldc + cn] = make_float2(v2, v3);
        }
    }
}

// ---------------------------------------------------------------------------
// Scores GEMM + per-slab softmax statistics.
// ---------------------------------------------------------------------------
__global__ __launch_bounds__(256)
void scores_stats(const float* __restrict__ q, const float* __restrict__ k,
                  float* __restrict__ attn, float2* __restrict__ sstats)
{
    constexpr int BM = 128, BN = 128, WM = 64, WN = 32;
    constexpr int WARPS_N = BN / WN;
    constexpr int MS = WM / 16, NS = WN / 8;
    constexpr int ASZ = BM * 16, BSZ = BN * 16;

    __shared__ __align__(16) float As[3 * ASZ];
    __shared__ __align__(16) float Bs[3 * BSZ];

    const int z = blockIdx.z;
    const int b = z >> 4, h = z & 15;
    const float* A = q + (size_t)b * LQ * E_ + h * DH;
    const float* B = k + (size_t)b * LK * E_ + h * DH;
    float* C = attn + (size_t)z * LQ * LK;

    const int bm = blockIdx.y * BM, bn = blockIdx.x * BN;
    const int tid = threadIdx.x, warp = tid >> 5, lane = tid & 31;
    const int wm = (warp / WARPS_N) * WM, wn = (warp % WARPS_N) * WN;

    const unsigned as0 = (unsigned)__cvta_generic_to_shared(As);
    const unsigned bs0 = (unsigned)__cvta_generic_to_shared(Bs);
    const int ld_r = tid >> 2, ld_c = tid & 3;

    auto load_stage = [&](int buf, int k0) {
        #pragma unroll
        for (int i = 0; i < 2; i++) {
            int r = ld_r + i * 64;
            int ph = ld_c ^ ((r >> 1) & 3);
            cp_async16(as0 + (unsigned)(buf * ASZ + r * 16 + ph * 4) * 4u,
                       A + (size_t)(bm + r) * E_ + k0 + ld_c * 4);
            cp_async16(bs0 + (unsigned)(buf * BSZ + r * 16 + ph * 4) * 4u,
                       B + (size_t)(bn + r) * E_ + k0 + ld_c * 4);
        }
    };

    float acc[MS][NS][4];
    #pragma unroll
    for (int i = 0; i < MS; i++)
        #pragma unroll
        for (int j = 0; j < NS; j++)
            #pragma unroll
            for (int r = 0; r < 4; r++) acc[i][j][r] = 0.f;

    const int a_row = (lane & 7) + ((lane >> 3) & 1) * 8;
    const int a_ch  = lane >> 4;
    const int b_row = (lane & 7) + ((lane >= 16) ? 8 : 0);
    const int b_ch  = (lane >> 3) & 1;

    const int nk = DH >> 4;
    load_stage(0, 0);  cp_commit();
    load_stage(1, 16); cp_commit();

    for (int ks = 0; ks < nk; ks++) {
        cp_wait<1>();
        __syncthreads();
        const int buf = ks % 3;
        if (ks + 2 < nk) load_stage((ks + 2) % 3, (ks + 2) << 4);
        cp_commit();

        #pragma unroll
        for (int k8 = 0; k8 < 2; k8++) {
            const int cb = k8 * 2;
            unsigned a[MS][4], bfr[NS][2];
            #pragma unroll
            for (int i = 0; i < MS; i++) {
                int r = wm + 16 * i + a_row;
                int ph = (cb + a_ch) ^ ((r >> 1) & 3);
                ldsm4(a[i][0], a[i][1], a[i][2], a[i][3],
                      as0 + (unsigned)(buf * ASZ + r * 16 + ph * 4) * 4u);
            }
            #pragma unroll
            for (int j = 0; j < NS / 2; j++) {
                int r = wn + 16 * j + b_row;
                int ph = (cb + b_ch) ^ ((r >> 1) & 3);
                ldsm4(bfr[2*j][0], bfr[2*j][1], bfr[2*j+1][0], bfr[2*j+1][1],
                      bs0 + (unsigned)(buf * BSZ + r * 16 + ph * 4) * 4u);
            }
            #pragma unroll
            for (int i = 0; i < MS; i++)
                #pragma unroll
                for (int j = 0; j < NS; j++)
                    mma_tf32(acc[i][j], a[i], bfr[j]);
        }
        __syncthreads();
    }

    #pragma unroll
    for (int i = 0; i < MS; i++)
        #pragma unroll
        for (int j = 0; j < NS; j++)
            #pragma unroll
            for (int r = 0; r < 4; r++) acc[i][j][r] *= 0.125f;

    #pragma unroll
    for (int i = 0; i < MS; i++) {
        const int r = bm + wm + 16 * i + (lane >> 2);
        #pragma unroll
        for (int j = 0; j < NS; j++) {
            const int cn = bn + wn + 8 * j + 2 * (lane & 3);
            *(float2*)&C[(size_t)r * LK + cn]       = make_float2(acc[i][j][0], acc[i][j][1]);
            *(float2*)&C[(size_t)(r + 8) * LK + cn] = make_float2(acc[i][j][2], acc[i][j][3]);
        }
    }

    float* sm_m = As;
    float* sm_s = As + 512;
    __syncthreads();

    const int ng = warp % WARPS_N;
    #pragma unroll
    for (int i = 0; i < MS; i++) {
        #pragma unroll
        for (int hh = 0; hh < 2; hh++) {
            float v[8];
            #pragma unroll
            for (int j = 0; j < NS; j++) {
                v[2*j]   = acc[i][j][2*hh];
                v[2*j+1] = acc[i][j][2*hh+1];
            }
            float m = v[0];
            #pragma unroll
            for (int e = 1; e < 8; e++) m = fmaxf(m, v[e]);
            m = fmaxf(m, __shfl_xor_sync(0xffffffffu, m, 1));
            m = fmaxf(m, __shfl_xor_sync(0xffffffffu, m, 2));
            float se = 0.f;
            #pragma unroll
            for (int e = 0; e < 8; e++) se += __expf(v[e] - m);
            se += __shfl_xor_sync(0xffffffffu, se, 1);
            se += __shfl_xor_sync(0xffffffffu, se, 2);
            if ((lane & 3) == 0) {
                int row = wm + 16 * i + (lane >> 2) + 8 * hh;
                sm_m[ng * 128 + row] = m;
                sm_s[ng * 128 + row] = se;
            }
        }
    }
    __syncthreads();

    if (tid < 128) {
        float m0 = sm_m[tid], m1 = sm_m[128 + tid];
        float m2 = sm_m[256 + tid], m3 = sm_m[384 + tid];
        float M = fmaxf(fmaxf(m0, m1), fmaxf(m2, m3));
        float S = sm_s[tid]       * __expf(m0 - M)
                + sm_s[128 + tid] * __expf(m1 - M)
                + sm_s[256 + tid] * __expf(m2 - M)
                + sm_s[384 + tid] * __expf(m3 - M);
        sstats[((size_t)z * 16 + blockIdx.x) * LQ + bm + tid] = make_float2(M, S);
    }
}

// ---------------------------------------------------------------------------
// Combine 16 slab stats per row -> (M, 1/S)
// ---------------------------------------------------------------------------
__global__ __launch_bounds__(256)
void rowcombine(const float2* __restrict__ sstats, float2* __restrict__ rowstats)
{
    int idx = blockIdx.x * 256 + threadIdx.x;
    int z = idx >> 9, row = idx & 511;
    const float2* p = sstats + (size_t)z * 16 * LQ + row;
    float2 v[16];
    #pragma unroll
    for (int s = 0; s < 16; s++) v[s] = p[(size_t)s * LQ];
    float M = v[0].x;
    #pragma unroll
    for (int s = 1; s < 16; s++) M = fmaxf(M, v[s].x);
    float S = 0.f;
    #pragma unroll
    for (int s = 0; s < 16; s++) S += v[s].y * __expf(v[s].x - M);
    rowstats[idx] = make_float2(M, 1.0f / S);
}

// ---------------------------------------------------------------------------
// Fused normalize + ctx GEMM.
// ---------------------------------------------------------------------------
__global__ __launch_bounds__(256)
void ctx_fused(const float2* __restrict__ rowstats,
               float* __restrict__ attn,
               const float* __restrict__ vt,
               float* __restrict__ ctx)
{
    constexpr int BM = 128, BN = 64, WM = 32, WN = 32;
    constexpr int WARPS_N = BN / WN;
    constexpr int MS = WM / 16, NS = WN / 8;
    constexpr int ASZ = BM * 16, BSZ = BN * 16;

    __shared__ __align__(16) float As[2 * ASZ];
    __shared__ __align__(16) float Bs[3 * BSZ];
    __shared__ float2 rs[BM];

    const int z = blockIdx.y;
    const int b = z >> 4, h = z & 15;
    const int bm = blockIdx.x * BM;
    float* Sp = attn + ((size_t)z * LQ + bm) * LK;
    const float* Vb = vt + ((size_t)b * E_ + h * DH) * LK;
    float* Cp = ctx + ((size_t)b * LQ + bm) * E_ + h * DH;

    const int tid = threadIdx.x, warp = tid >> 5, lane = tid & 31;
    const int wm = (warp / WARPS_N) * WM, wn = (warp % WARPS_N) * WN;

    if (tid < BM) rs[tid] = rowstats[(size_t)z * LQ + bm + tid];

    const unsigned as0 = (unsigned)__cvta_generic_to_shared(As);
    const unsigned bs0 = (unsigned)__cvta_generic_to_shared(Bs);
    const int ld_r = tid >> 2, ld_c = tid & 3;
    const int ph0 = ld_c ^ ((ld_r >> 1) & 3);
    const int ph1 = ld_c ^ (((ld_r + 64) >> 1) & 3);

    auto loadB = [&](int buf, int k0) {
        int ph = ld_c ^ ((ld_r >> 1) & 3);
        cp_async16(bs0 + (unsigned)(buf * BSZ + ld_r * 16 + ph * 4) * 4u,
                   Vb + (size_t)ld_r * LK + k0 + ld_c * 4);
    };

    loadB(0, 0);  cp_commit();
    loadB(1, 16); cp_commit();

    float4 s0 = *(const float4*)&Sp[(size_t)ld_r * LK + ld_c * 4];
    float4 s1 = *(const float4*)&Sp[(size_t)(ld_r + 64) * LK + ld_c * 4];

    __syncthreads();
    const float2 st0 = rs[ld_r];
    const float2 st1 = rs[ld_r + 64];

    float acc[MS][NS][4];
    #pragma unroll
    for (int i = 0; i < MS; i++)
        #pragma unroll
        for (int j = 0; j < NS; j++)
            #pragma unroll
            for (int r = 0; r < 4; r++) acc[i][j][r] = 0.f;

    const int a_row = (lane & 7) + ((lane >> 3) & 1) * 8;
    const int a_ch  = lane >> 4;
    const int b_row = (lane & 7) + ((lane >= 16) ? 8 : 0);
    const int b_ch  = (lane >> 3) & 1;

    const int nk = LK >> 4;
    for (int t = 0; t < nk; t++) {
        const int abuf = t & 1;
        float4 p0, p1;
        p0.x = round_tf32(__expf(s0.x - st0.x) * st0.y);
        p0.y = round_tf32(__expf(s0.y - st0.x) * st0.y);
        p0.z = round_tf32(__expf(s0.z - st0.x) * st0.y);
        p0.w = round_tf32(__expf(s0.w - st0.x) * st0.y);
        p1.x = round_tf32(__expf(s1.x - st1.x) * st1.y);
        p1.y = round_tf32(__expf(s1.y - st1.x) * st1.y);
        p1.z = round_tf32(__expf(s1.z - st1.x) * st1.y);
        p1.w = round_tf32(__expf(s1.w - st1.x) * st1.y);
        *(float4*)&As[abuf * ASZ + ld_r * 16 + ph0 * 4]        = p0;
        *(float4*)&As[abuf * ASZ + (ld_r + 64) * 16 + ph1 * 4] = p1;
        *(float4*)&Sp[(size_t)ld_r * LK + t * 16 + ld_c * 4]        = p0;
        *(float4*)&Sp[(size_t)(ld_r + 64) * LK + t * 16 + ld_c * 4] = p1;
        if (t + 1 < nk) {
            s0 = *(const float4*)&Sp[(size_t)ld_r * LK + (t + 1) * 16 + ld_c * 4];
            s1 = *(const float4*)&Sp[(size_t)(ld_r + 64) * LK + (t + 1) * 16 + ld_c * 4];
        }
        cp_wait<1>();
        __syncthreads();
        if (t + 2 < nk) loadB((t + 2) % 3, (t + 2) * 16);
        cp_commit();

        const int bbuf = t % 3;
        #pragma unroll
        for (int k8 = 0; k8 < 2; k8++) {
            const int cb = k8 * 2;
            unsigned a[MS][4], bfr[NS][2];
            #pragma unroll
            for (int i = 0; i < MS; i++) {
                int r = wm + 16 * i + a_row;
                int ph = (cb + a_ch) ^ ((r >> 1) & 3);
                ldsm4(a[i][0], a[i][1], a[i][2], a[i][3],
                      as0 + (unsigned)(abuf * ASZ + r * 16 + ph * 4) * 4u);
            }
            #pragma unroll
            for (int j = 0; j < NS / 2; j++) {
                int r = wn + 16 * j + b_row;
                int ph = (cb + b_ch) ^ ((r >> 1) & 3);
                ldsm4(bfr[2*j][0], bfr[2*j][1], bfr[2*j+1][0], bfr[2*j+1][1],
                      bs0 + (unsigned)(bbuf * BSZ + r * 16 + ph * 4) * 4u);
            }
            #pragma unroll
            for (int i = 0; i < MS; i++)
                #pragma unroll
                for (int j = 0; j < NS; j++)
                    mma_tf32(acc[i][j], a[i], bfr[j]);
        }
    }

    #pragma unroll
    for (int i = 0; i < MS; i++) {
        const int r = wm + 16 * i + (lane >> 2);
        #pragma unroll
        for (int j = 0; j < NS; j++) {
            const int cn = wn + 8 * j + 2 * (lane & 3);
            float v0 = round_tf32(acc[i][j][0]);
            float v1 = round_tf32(acc[i][j][1]);
            float v2 = round_tf32(acc[i][j][2]);
            float v3 = round_tf32(acc[i][j][3]);
            *(float2*)&Cp[(size_t)r * E_ + cn]       = make_float2(v0, v1);
            *(float2*)&Cp[(size_t)(r + 8) * E_ + cn] = make_float2(v2, v3);
        }
    }
}

// ---------------------------------------------------------------------------
// Per-batch transpose of V (float4 vectorized): vt[b][n][k] = v[b][k][n]
// Tile: 32 (k) x 128 (n). Reads 512B/row, writes 128B/warp-row, both coalesced.
// ---------------------------------------------------------------------------
__global__ __launch_bounds__(256)
void transpose_v(const float* __restrict__ v, float* __restrict__ vt)
{
    __shared__ float t[32][129];
    const int b  = blockIdx.z;
    const int k0 = blockIdx.x * 32;
    const int n0 = blockIdx.y * 128;
    const int tx = threadIdx.x;        // 0..31
    const int ty = threadIdx.y;        // 0..7

    // load 32 rows x 128 cols, float4 per thread
    #pragma unroll
    for (int i = ty; i < 32; i += 8) {
        float4 val = *(const float4*)&v[((size_t)b * LK + k0 + i) * E_ + n0 + tx * 4];
        t[i][tx * 4 + 0] = val.x;
        t[i][tx * 4 + 1] = val.y;
        t[i][tx * 4 + 2] = val.z;
        t[i][tx * 4 + 3] = val.w;
    }
    __syncthreads();

    // write 128 n-rows x 32 k each; tx indexes k (contiguous, 128B per row)
    #pragma unroll
    for (int i = ty; i < 128; i += 8)
        vt[((size_t)b * E_ + n0 + i) * LK + k0 + tx] = t[tx][i];
}

// ---------------------------------------------------------------------------
// out = LayerNorm(a + b) * g + beta
// ---------------------------------------------------------------------------
template<int ROUND>
__global__ __launch_bounds__(256)
void ln_residual(const float* __restrict__ A, const float* __restrict__ Bx,
                 const float* __restrict__ g, const float* __restrict__ be,
                 float* __restrict__ out)
{
    const size_t row = blockIdx.x;
    const int t = threadIdx.x;

    float4 a = ((const float4*)(A  + row * E_))[t];
    float4 b = ((const float4*)(Bx + row * E_))[t];
    float4 x = make_float4(a.x + b.x, a.y + b.y, a.z + b.z, a.w + b.w);

    float s  = x.x + x.y + x.z + x.w;
    float ss = x.x*x.x + x.y*x.y + x.z*x.z + x.w*x.w;

    __shared__ float rs_[8], rss[8];
    #pragma unroll
    for (int o = 16; o > 0; o >>= 1) {
        s  += __shfl_xor_sync(0xffffffffu, s,  o);
        ss += __shfl_xor_sync(0xffffffffu, ss, o);
    }
    if ((t & 31) == 0) { rs_[t >> 5] = s; rss[t >> 5] = ss; }
    __syncthreads();
    s = 0.f; ss = 0.f;
    #pragma unroll
    for (int i = 0; i < 8; i++) { s += rs_[i]; ss += rss[i]; }

    const float mean = s * (1.0f / E_);
    const float var  = ss * (1.0f / E_) - mean * mean;
    const float inv  = rsqrtf(var + 1e-5f);

    float4 gg = ((const float4*)g)[t];
    float4 bb = ((const float4*)be)[t];
    float4 o;
    o.x = (x.x - mean) * inv * gg.x + bb.x;
    o.y = (x.y - mean) * inv * gg.y + bb.y;
    o.z = (x.z - mean) * inv * gg.z + bb.z;
    o.w = (x.w - mean) * inv * gg.w + bb.w;
    if (ROUND) {
        o.x = round_tf32(o.x); o.y = round_tf32(o.y);
        o.z = round_tf32(o.z); o.w = round_tf32(o.w);
    }
    ((float4*)(out + row * E_))[t] = o;
}

// ---------------------------------------------------------------------------
extern "C" void kernel_launch(void* const* d_in, const int* in_sizes, int n_in,
                              void* d_out, int out_size)
{
    const float* query = (const float*)d_in[0];
    const float* keyv  = (const float*)d_in[1];
    const float* wq = (const float*)d_in[2];
    const float* wk = (const float*)d_in[3];
    const float* wv = (const float*)d_in[4];
    const float* bq = (const float*)d_in[5];
    const float* bk = (const float*)d_in[6];
    const float* bv = (const float*)d_in[7];
    const float* wo = (const float*)d_in[8];
    const float* bo = (const float*)d_in[9];
    const float* g1 = (const float*)d_in[10];
    const float* be1 = (const float*)d_in[11];
    const float* w1 = (const float*)d_in[12];
    const float* b1 = (const float*)d_in[13];
    const float* w2 = (const float*)d_in[14];
    const float* b2 = (const float*)d_in[15];
    const float* g2 = (const float*)d_in[16];
    const float* be2 = (const float*)d_in[17];

    float* out = (float*)d_out;
    float* q3_out = out;
    float* attn   = out + (size_t)MQ * E_;

    float *gq, *gk, *gv, *gvt, *gctx, *gao, *gq2, *gf1, *gf2;
    float *rq, *rkv, *rwq, *rwk, *rwv, *rwo, *rw1, *rw2;
    float2 *sst, *rst;
    cudaGetSymbolAddress((void**)&gq,  g_q);
    cudaGetSymbolAddress((void**)&gk,  g_k);
    cudaGetSymbolAddress((void**)&gv,  g_v);
    cudaGetSymbolAddress((void**)&gvt, g_vt);
    cudaGetSymbolAddress((void**)&gctx, g_ctx);
    cudaGetSymbolAddress((void**)&gao, g_attnout);
    cudaGetSymbolAddress((void**)&gq2, g_q2);
    cudaGetSymbolAddress((void**)&gf1, g_ffn1);
    cudaGetSymbolAddress((void**)&gf2, g_ffn2);
    cudaGetSymbolAddress((void**)&rq,  r_query);
    cudaGetSymbolAddress((void**)&rkv, r_kv);
    cudaGetSymbolAddress((void**)&rwq, r_wq);
    cudaGetSymbolAddress((void**)&rwk, r_wk);
    cudaGetSymbolAddress((void**)&rwv, r_wv);
    cudaGetSymbolAddress((void**)&rwo, r_wo);
    cudaGetSymbolAddress((void**)&rw1, r_w1);
    cudaGetSymbolAddress((void**)&rw2, r_w2);
    cudaGetSymbolAddress((void**)&sst, g_sstats);
    cudaGetSymbolAddress((void**)&rst, g_rowstats);

    // one-time setup: smem attrs + side streams/events for capture forks
    static cudaStream_t s1 = nullptr, s2 = nullptr;
    static cudaEvent_t e0, e1, e2;
    if (!s1) {
        cudaFuncSetAttribute(tf32_gemm<128,128,64,32,0>,
                             cudaFuncAttributeMaxDynamicSharedMemorySize, 98304);
        cudaFuncSetAttribute(tf32_gemm<128,128,64,32,1>,
                             cudaFuncAttributeMaxDynamicSharedMemorySize, 98304);
        cudaFuncSetAttribute(tf32_gemm<128,64,32,32,0>,
                             cudaFuncAttributeMaxDynamicSharedMemorySize, 73728);
        cudaFuncSetAttribute(tf32_gemm<128,64,32,32,1>,
                             cudaFuncAttributeMaxDynamicSharedMemorySize, 73728);
        cudaStreamCreateWithFlags(&s1, cudaStreamNonBlocking);
        cudaStreamCreateWithFlags(&s2, cudaStreamNonBlocking);
        cudaEventCreateWithFlags(&e0, cudaEventDisableTiming);
        cudaEventCreateWithFlags(&e1, cudaEventDisableTiming);
        cudaEventCreateWithFlags(&e2, cudaEventDisableTiming);
    }
    const int GS128 = 98304;
    const int GS64  = 73728;

    // ---- prepass: round all external GEMM inputs to tf32 (one kernel) ----
    RCArgs rc;
    rc.src[0] = (const float4*)query; rc.dst[0] = (float4*)rq;
    rc.src[1] = (const float4*)keyv;  rc.dst[1] = (float4*)rkv;
    rc.src[2] = (const float4*)wq;    rc.dst[2] = (float4*)rwq;
    rc.src[3] = (const float4*)wk;    rc.dst[3] = (float4*)rwk;
    rc.src[4] = (const float4*)wv;    rc.dst[4] = (float4*)rwv;
    rc.src[5] = (const float4*)wo;    rc.dst[5] = (float4*)rwo;
    rc.src[6] = (const float4*)w1;    rc.dst[6] = (float4*)rw1;
    rc.src[7] = (const float4*)w2;    rc.dst[7] = (float4*)rw2;
    const int rc_total = RC_N0 + RC_N1 + 4*RC_NW + 2*RC_NF;
    round_copy_all<<<2048, 256>>>(rc, rc_total);

    // fork: default = K proj, s1 = V proj + transpose, s2 = Q proj
    cudaEventRecord(e0, 0);
    cudaStreamWaitEvent(s1, e0, 0);
    cudaStreamWaitEvent(s2, e0, 0);

    tf32_gemm<128,128,64,32,1><<<dim3(E_/128, MK/128), 256, GS128>>>(
        rkv, E_,  rwk, E_,  bk,  gk, E_,  E_, 1.f, 0);

    tf32_gemm<128,128,64,32,1><<<dim3(E_/128, MK/128), 256, GS128, s1>>>(
        rkv, E_,  rwv, E_,  bv,  gv, E_,  E_, 1.f, 0);
    transpose_v<<<dim3(LK/32, E_/128, B_), dim3(32, 8), 0, s1>>>(gv, gvt);
    cudaEventRecord(e1, s1);

    tf32_gemm<128,64,32,32,1><<<dim3(E_/64, MQ/128), 256, GS64, s2>>>(
        rq,  E_,  rwq, E_,  bq,  gq, E_,  E_, 1.f, 0);
    cudaEventRecord(e2, s2);

    // join: scores needs Q (s2) and K (default)
    cudaStreamWaitEvent(0, e2, 0);
    scores_stats<<<dim3(LK/128, LQ/128, B_*H_), 256>>>(gq, gk, attn, sst);
    rowcombine<<<(B_*H_*LQ)/256, 256>>>(sst, rst);

    // ctx needs transpose (s1)
    cudaStreamWaitEvent(0, e1, 0);
    ctx_fused<<<dim3(LQ/128, B_*H_), 256>>>(rst, attn, gvt, gctx);

    // ---- output projection + LN1 ----
    tf32_gemm<128,64,32,32,0><<<dim3(E_/64, MQ/128), 256, GS64>>>(
        gctx, E_,  rwo, E_,  bo,  gao, E_,  E_, 1.f, 0);
    ln_residual<1><<<MQ, 256>>>(query, gao, g1, be1, gq2);

    // ---- FFN + LN2 ----
    tf32_gemm<128,128,64,32,1><<<dim3(F_/128, MQ/128), 256, GS128>>>(
        gq2, E_,  rw1, E_,  b1,  gf1, F_,  E_, 1.f, 1);
    tf32_gemm<128,64,32,32,0><<<dim3(E_/64, MQ/128), 256, GS64>>>(
        gf1, F_,  rw2, F_,  b2,  gf2, E_,  F_, 1.f, 0);
    ln_residual<0><<<MQ, 256>>>(gq2, gf2, g2, be2, q3_out);
}

// round 13
// speedup vs baseline: 1.5535x; 1.0046x over previous
#include <cuda_runtime.h>
#include <cstddef>

// Problem constants
#define B_  4
#define LQ  512
#define LK  2048
#define E_  1024
#define H_  16
#define DH  64
#define F_  4096
#define MQ  (B_*LQ)    // 2048
#define MK  (B_*LK)    // 8192

// ---------------- scratch (device globals; no allocation allowed) ----------
__device__ float g_q[MQ * E_];
__device__ float g_k[MK * E_];
__device__ float g_v[MK * E_];
__device__ float g_vt[MK * E_];
__device__ float g_ctx[MQ * E_];
__device__ float g_attnout[MQ * E_];
__device__ float g_q2[MQ * E_];
__device__ float g_ffn1[MQ * F_];
__device__ float g_ffn2[MQ * E_];
// tf32-rounded copies of external inputs
__device__ float r_query[MQ * E_];
__device__ float r_kv[MK * E_];
__device__ float r_wq[E_ * E_];
__device__ float r_wk[E_ * E_];
__device__ float r_wv[E_ * E_];
__device__ float r_wo[E_ * E_];
__device__ float r_w1[F_ * E_];
__device__ float r_w2[E_ * F_];
// softmax statistics
__device__ float2 g_sstats[64 * 16 * 512];
__device__ float2 g_rowstats[64 * 512];

// ---------------------------------------------------------------------------
// helpers
// ---------------------------------------------------------------------------
__device__ __forceinline__ unsigned cvt_tf32(float x) {
    unsigned r;
    asm("cvt.rna.tf32.f32 %0, %1;" : "=r"(r) : "f"(x));
    return r;
}
__device__ __forceinline__ float round_tf32(float x) {
    return __uint_as_float(cvt_tf32(x));
}

__device__ __forceinline__ void cp_async16(unsigned saddr, const void* gptr) {
    asm volatile("cp.async.cg.shared.global [%0], [%1], 16;" :: "r"(saddr), "l"(gptr));
}
__device__ __forceinline__ void cp_commit() {
    asm volatile("cp.async.commit_group;");
}
template<int N>
__device__ __forceinline__ void cp_wait() {
    asm volatile("cp.async.wait_group %0;" :: "n"(N));
}

__device__ __forceinline__ void ldsm4(unsigned &r0, unsigned &r1,
                                      unsigned &r2, unsigned &r3, unsigned addr) {
    asm volatile("ldmatrix.sync.aligned.m8n8.x4.shared.b16 {%0,%1,%2,%3}, [%4];"
                 : "=r"(r0), "=r"(r1), "=r"(r2), "=r"(r3) : "r"(addr));
}

__device__ __forceinline__ void mma_tf32(float c[4], const unsigned a[4],
                                         const unsigned b[2]) {
    asm volatile(
        "mma.sync.aligned.m16n8k8.row.col.f32.tf32.tf32.f32 "
        "{%0,%1,%2,%3}, {%4,%5,%6,%7}, {%8,%9}, {%0,%1,%2,%3};"
        : "+f"(c[0]), "+f"(c[1]), "+f"(c[2]), "+f"(c[3])
        : "r"(a[0]), "r"(a[1]), "r"(a[2]), "r"(a[3]), "r"(b[0]), "r"(b[1]));
}

// ---------------------------------------------------------------------------
// Merged tf32 round-copy for all external inputs (one kernel)
// ---------------------------------------------------------------------------
struct RCArgs {
    const float4* src[8];
    float4*       dst[8];
};
#define RC_N0 (MQ*E_/4)
#define RC_N1 (MK*E_/4)
#define RC_NW (E_*E_/4)
#define RC_NF (F_*E_/4)
__constant__ int rc_off[9] = {
    0,
    RC_N0,
    RC_N0 + RC_N1,
    RC_N0 + RC_N1 + RC_NW,
    RC_N0 + RC_N1 + 2*RC_NW,
    RC_N0 + RC_N1 + 3*RC_NW,
    RC_N0 + RC_N1 + 4*RC_NW,
    RC_N0 + RC_N1 + 4*RC_NW + RC_NF,
    RC_N0 + RC_N1 + 4*RC_NW + 2*RC_NF
};

__global__ __launch_bounds__(256)
void round_copy_all(RCArgs rc, int total)
{
    for (int i = blockIdx.x * blockDim.x + threadIdx.x; i < total;
         i += gridDim.x * blockDim.x) {
        int seg = 0;
        #pragma unroll
        for (int s = 1; s < 8; s++) if (i >= rc_off[s]) seg = s;
        int j = i - rc_off[seg];
        float4 v = rc.src[seg][j];
        v.x = round_tf32(v.x); v.y = round_tf32(v.y);
        v.z = round_tf32(v.z); v.w = round_tf32(v.w);
        rc.dst[seg][j] = v;
    }
}

// ---------------------------------------------------------------------------
// Pipelined NT GEMM, tf32 tensor cores, BK=32, 3 stages, ONE sync per k-iter.
// Inputs pre-rounded to tf32.
// ---------------------------------------------------------------------------
template<int BM, int BN, int WM, int WN, int ROUND>
__global__ __launch_bounds__(256)
void tf32_gemm(const float* __restrict__ A, int lda,
               const float* __restrict__ B, int ldb,
               const float* __restrict__ bias,
               float* __restrict__ C, int ldc,
               int K, float scale, int relu)
{
    constexpr int WARPS_N = BN / WN;
    constexpr int MS = WM / 16, NS = WN / 8;
    constexpr int ASZ = BM * 32;
    constexpr int BSZ = BN * 32;

    extern __shared__ __align__(16) float sm[];
    float* As = sm;
    float* Bs = sm + 3 * ASZ;

    const int bm = blockIdx.y * BM, bn = blockIdx.x * BN;
    const int tid = threadIdx.x, warp = tid >> 5, lane = tid & 31;
    const int wm = (warp / WARPS_N) * WM, wn = (warp % WARPS_N) * WN;

    const unsigned as0 = (unsigned)__cvta_generic_to_shared(As);
    const unsigned bs0 = (unsigned)__cvta_generic_to_shared(Bs);

    const int ld_r = tid >> 3;
    const int ld_c = tid & 7;

    auto load_stage = [&](int buf, int k0) {
        #pragma unroll
        for (int i = 0; i < BM / 32; i++) {
            int r = ld_r + i * 32;
            int ph = ld_c ^ (r & 7);
            cp_async16(as0 + (unsigned)(buf * ASZ + r * 32 + ph * 4) * 4u,
                       A + (size_t)(bm + r) * lda + k0 + ld_c * 4);
        }
        #pragma unroll
        for (int i = 0; i < BN / 32; i++) {
            int r = ld_r + i * 32;
            int ph = ld_c ^ (r & 7);
            cp_async16(bs0 + (unsigned)(buf * BSZ + r * 32 + ph * 4) * 4u,
                       B + (size_t)(bn + r) * ldb + k0 + ld_c * 4);
        }
    };

    float acc[MS][NS][4];
    #pragma unroll
    for (int i = 0; i < MS; i++)
        #pragma unroll
        for (int j = 0; j < NS; j++)
            #pragma unroll
            for (int r = 0; r < 4; r++) acc[i][j][r] = 0.f;

    const int a_row = (lane & 7) + ((lane >> 3) & 1) * 8;
    const int a_ch  = lane >> 4;
    const int b_row = (lane & 7) + ((lane >= 16) ? 8 : 0);
    const int b_ch  = (lane >> 3) & 1;

    const int nk = K >> 5;
    load_stage(0, 0);  cp_commit();
    load_stage(1, 32); cp_commit();

    for (int ks = 0; ks < nk; ks++) {
        cp_wait<1>();
        __syncthreads();
        const int buf = ks % 3;
        if (ks + 2 < nk) load_stage((ks + 2) % 3, (ks + 2) << 5);
        cp_commit();

        #pragma unroll
        for (int k8 = 0; k8 < 4; k8++) {
            const int cb = k8 * 2;
            unsigned a[MS][4], b[NS][2];
            #pragma unroll
            for (int i = 0; i < MS; i++) {
                int r = wm + 16 * i + a_row;
                int ph = (cb + a_ch) ^ (r & 7);
                ldsm4(a[i][0], a[i][1], a[i][2], a[i][3],
                      as0 + (unsigned)(buf * ASZ + r * 32 + ph * 4) * 4u);
            }
            #pragma unroll
            for (int j = 0; j < NS / 2; j++) {
                int r = wn + 16 * j + b_row;
                int ph = (cb + b_ch) ^ (r & 7);
                ldsm4(b[2*j][0], b[2*j][1], b[2*j+1][0], b[2*j+1][1],
                      bs0 + (unsigned)(buf * BSZ + r * 32 + ph * 4) * 4u);
            }
            #pragma unroll
            for (int i = 0; i < MS; i++)
                #pragma unroll
                for (int j = 0; j < NS; j++)
                    mma_tf32(acc[i][j], a[i], b[j]);
        }
    }

    #pragma unroll
    for (int i = 0; i < MS; i++) {
        const int r = bm + wm + 16 * i + (lane >> 2);
        #pragma unroll
        for (int j = 0; j < NS; j++) {
            const int cn = bn + wn + 8 * j + 2 * (lane & 3);
            float bx = 0.f, by = 0.f;
            if (bias) { float2 bb = *(const float2*)&bias[cn]; bx = bb.x; by = bb.y; }
            float v0 = acc[i][j][0] * scale + bx;
            float v1 = acc[i][j][1] * scale + by;
            float v2 = acc[i][j][2] * scale + bx;
            float v3 = acc[i][j][3] * scale + by;
            if (relu) {
                v0 = fmaxf(v0, 0.f); v1 = fmaxf(v1, 0.f);
                v2 = fmaxf(v2, 0.f); v3 = fmaxf(v3, 0.f);
            }
            if (ROUND) {
                v0 = round_tf32(v0); v1 = round_tf32(v1);
                v2 = round_tf32(v2); v3 = round_tf32(v3);
            }
            *(float2*)&C[(size_t)r * ldc + cn]       = make_float2(v0, v1);
            *(float2*)&C[(size_t)(r + 8) * ldc + cn] = make_float2(v2, v3);
        }
    }
}

// ---------------------------------------------------------------------------
// Scores GEMM + per-slab softmax statistics.
// ---------------------------------------------------------------------------
__global__ __launch_bounds__(256)
void scores_stats(const float* __restrict__ q, const float* __restrict__ k,
                  float* __restrict__ attn, float2* __restrict__ sstats)
{
    constexpr int BM = 128, BN = 128, WM = 64, WN = 32;
    constexpr int WARPS_N = BN / WN;
    constexpr int MS = WM / 16, NS = WN / 8;
    constexpr int ASZ = BM * 16, BSZ = BN * 16;

    __shared__ __align__(16) float As[3 * ASZ];
    __shared__ __align__(16) float Bs[3 * BSZ];

    const int z = blockIdx.z;
    const int b = z >> 4, h = z & 15;
    const float* A = q + (size_t)b * LQ * E_ + h * DH;
    const float* B = k + (size_t)b * LK * E_ + h * DH;
    float* C = attn + (size_t)z * LQ * LK;

    const int bm = blockIdx.y * BM, bn = blockIdx.x * BN;
    const int tid = threadIdx.x, warp = tid >> 5, lane = tid & 31;
    const int wm = (warp / WARPS_N) * WM, wn = (warp % WARPS_N) * WN;

    const unsigned as0 = (unsigned)__cvta_generic_to_shared(As);
    const unsigned bs0 = (unsigned)__cvta_generic_to_shared(Bs);
    const int ld_r = tid >> 2, ld_c = tid & 3;

    auto load_stage = [&](int buf, int k0) {
        #pragma unroll
        for (int i = 0; i < 2; i++) {
            int r = ld_r + i * 64;
            int ph = ld_c ^ ((r >> 1) & 3);
            cp_async16(as0 + (unsigned)(buf * ASZ + r * 16 + ph * 4) * 4u,
                       A + (size_t)(bm + r) * E_ + k0 + ld_c * 4);
            cp_async16(bs0 + (unsigned)(buf * BSZ + r * 16 + ph * 4) * 4u,
                       B + (size_t)(bn + r) * E_ + k0 + ld_c * 4);
        }
    };

    float acc[MS][NS][4];
    #pragma unroll
    for (int i = 0; i < MS; i++)
        #pragma unroll
        for (int j = 0; j < NS; j++)
            #pragma unroll
            for (int r = 0; r < 4; r++) acc[i][j][r] = 0.f;

    const int a_row = (lane & 7) + ((lane >> 3) & 1) * 8;
    const int a_ch  = lane >> 4;
    const int b_row = (lane & 7) + ((lane >= 16) ? 8 : 0);
    const int b_ch  = (lane >> 3) & 1;

    const int nk = DH >> 4;
    load_stage(0, 0);  cp_commit();
    load_stage(1, 16); cp_commit();

    for (int ks = 0; ks < nk; ks++) {
        cp_wait<1>();
        __syncthreads();
        const int buf = ks % 3;
        if (ks + 2 < nk) load_stage((ks + 2) % 3, (ks + 2) << 4);
        cp_commit();

        #pragma unroll
        for (int k8 = 0; k8 < 2; k8++) {
            const int cb = k8 * 2;
            unsigned a[MS][4], bfr[NS][2];
            #pragma unroll
            for (int i = 0; i < MS; i++) {
                int r = wm + 16 * i + a_row;
                int ph = (cb + a_ch) ^ ((r >> 1) & 3);
                ldsm4(a[i][0], a[i][1], a[i][2], a[i][3],
                      as0 + (unsigned)(buf * ASZ + r * 16 + ph * 4) * 4u);
            }
            #pragma unroll
            for (int j = 0; j < NS / 2; j++) {
                int r = wn + 16 * j + b_row;
                int ph = (cb + b_ch) ^ ((r >> 1) & 3);
                ldsm4(bfr[2*j][0], bfr[2*j][1], bfr[2*j+1][0], bfr[2*j+1][1],
                      bs0 + (unsigned)(buf * BSZ + r * 16 + ph * 4) * 4u);
            }
            #pragma unroll
            for (int i = 0; i < MS; i++)
                #pragma unroll
                for (int j = 0; j < NS; j++)
                    mma_tf32(acc[i][j], a[i], bfr[j]);
        }
        __syncthreads();
    }

    #pragma unroll
    for (int i = 0; i < MS; i++)
        #pragma unroll
        for (int j = 0; j < NS; j++)
            #pragma unroll
            for (int r = 0; r < 4; r++) acc[i][j][r] *= 0.125f;

    #pragma unroll
    for (int i = 0; i < MS; i++) {
        const int r = bm + wm + 16 * i + (lane >> 2);
        #pragma unroll
        for (int j = 0; j < NS; j++) {
            const int cn = bn + wn + 8 * j + 2 * (lane & 3);
            *(float2*)&C[(size_t)r * LK + cn]       = make_float2(acc[i][j][0], acc[i][j][1]);
            *(float2*)&C[(size_t)(r + 8) * LK + cn] = make_float2(acc[i][j][2], acc[i][j][3]);
        }
    }

    float* sm_m = As;
    float* sm_s = As + 512;
    __syncthreads();

    const int ng = warp % WARPS_N;
    #pragma unroll
    for (int i = 0; i < MS; i++) {
        #pragma unroll
        for (int hh = 0; hh < 2; hh++) {
            float v[8];
            #pragma unroll
            for (int j = 0; j < NS; j++) {
                v[2*j]   = acc[i][j][2*hh];
                v[2*j+1] = acc[i][j][2*hh+1];
            }
            float m = v[0];
            #pragma unroll
            for (int e = 1; e < 8; e++) m = fmaxf(m, v[e]);
            m = fmaxf(m, __shfl_xor_sync(0xffffffffu, m, 1));
            m = fmaxf(m, __shfl_xor_sync(0xffffffffu, m, 2));
            float se = 0.f;
            #pragma unroll
            for (int e = 0; e < 8; e++) se += __expf(v[e] - m);
            se += __shfl_xor_sync(0xffffffffu, se, 1);
            se += __shfl_xor_sync(0xffffffffu, se, 2);
            if ((lane & 3) == 0) {
                int row = wm + 16 * i + (lane >> 2) + 8 * hh;
                sm_m[ng * 128 + row] = m;
                sm_s[ng * 128 + row] = se;
            }
        }
    }
    __syncthreads();

    if (tid < 128) {
        float m0 = sm_m[tid], m1 = sm_m[128 + tid];
        float m2 = sm_m[256 + tid], m3 = sm_m[384 + tid];
        float M = fmaxf(fmaxf(m0, m1), fmaxf(m2, m3));
        float S = sm_s[tid]       * __expf(m0 - M)
                + sm_s[128 + tid] * __expf(m1 - M)
                + sm_s[256 + tid] * __expf(m2 - M)
                + sm_s[384 + tid] * __expf(m3 - M);
        sstats[((size_t)z * 16 + blockIdx.x) * LQ + bm + tid] = make_float2(M, S);
    }
}

// ---------------------------------------------------------------------------
// Combine 16 slab stats per row -> (M, 1/S)
// ---------------------------------------------------------------------------
__global__ __launch_bounds__(256)
void rowcombine(const float2* __restrict__ sstats, float2* __restrict__ rowstats)
{
    int idx = blockIdx.x * 256 + threadIdx.x;
    int z = idx >> 9, row = idx & 511;
    const float2* p = sstats + (size_t)z * 16 * LQ + row;
    float2 v[16];
    #pragma unroll
    for (int s = 0; s < 16; s++) v[s] = p[(size_t)s * LQ];
    float M = v[0].x;
    #pragma unroll
    for (int s = 1; s < 16; s++) M = fmaxf(M, v[s].x);
    float S = 0.f;
    #pragma unroll
    for (int s = 0; s < 16; s++) S += v[s].y * __expf(v[s].x - M);
    rowstats[idx] = make_float2(M, 1.0f / S);
}

// ---------------------------------------------------------------------------
// Fused normalize + ctx GEMM (S prefetch deepened to 2 iterations).
// ---------------------------------------------------------------------------
__global__ __launch_bounds__(256)
void ctx_fused(const float2* __restrict__ rowstats,
               float* __restrict__ attn,
               const float* __restrict__ vt,
               float* __restrict__ ctx)
{
    constexpr int BM = 128, BN = 64, WM = 32, WN = 32;
    constexpr int WARPS_N = BN / WN;
    constexpr int MS = WM / 16, NS = WN / 8;
    constexpr int ASZ = BM * 16, BSZ = BN * 16;

    __shared__ __align__(16) float As[2 * ASZ];
    __shared__ __align__(16) float Bs[3 * BSZ];
    __shared__ float2 rs[BM];

    const int z = blockIdx.y;
    const int b = z >> 4, h = z & 15;
    const int bm = blockIdx.x * BM;
    float* Sp = attn + ((size_t)z * LQ + bm) * LK;
    const float* Vb = vt + ((size_t)b * E_ + h * DH) * LK;
    float* Cp = ctx + ((size_t)b * LQ + bm) * E_ + h * DH;

    const int tid = threadIdx.x, warp = tid >> 5, lane = tid & 31;
    const int wm = (warp / WARPS_N) * WM, wn = (warp % WARPS_N) * WN;

    if (tid < BM) rs[tid] = rowstats[(size_t)z * LQ + bm + tid];

    const unsigned as0 = (unsigned)__cvta_generic_to_shared(As);
    const unsigned bs0 = (unsigned)__cvta_generic_to_shared(Bs);
    const int ld_r = tid >> 2, ld_c = tid & 3;
    const int ph0 = ld_c ^ ((ld_r >> 1) & 3);
    const int ph1 = ld_c ^ (((ld_r + 64) >> 1) & 3);

    auto loadB = [&](int buf, int k0) {
        int ph = ld_c ^ ((ld_r >> 1) & 3);
        cp_async16(bs0 + (unsigned)(buf * BSZ + ld_r * 16 + ph * 4) * 4u,
                   Vb + (size_t)ld_r * LK + k0 + ld_c * 4);
    };

    loadB(0, 0);  cp_commit();
    loadB(1, 16); cp_commit();

    // 2-deep register prefetch of raw scores S
    const float* Sr0 = Sp + (size_t)ld_r * LK + ld_c * 4;
    const float* Sr1 = Sp + (size_t)(ld_r + 64) * LK + ld_c * 4;
    float4 s0 = *(const float4*)Sr0;            // S[t=0]
    float4 s1 = *(const float4*)Sr1;
    float4 n0 = *(const float4*)(Sr0 + 16);     // S[t=1]
    float4 n1 = *(const float4*)(Sr1 + 16);

    __syncthreads();
    const float2 st0 = rs[ld_r];
    const float2 st1 = rs[ld_r + 64];

    float acc[MS][NS][4];
    #pragma unroll
    for (int i = 0; i < MS; i++)
        #pragma unroll
        for (int j = 0; j < NS; j++)
            #pragma unroll
            for (int r = 0; r < 4; r++) acc[i][j][r] = 0.f;

    const int a_row = (lane & 7) + ((lane >> 3) & 1) * 8;
    const int a_ch  = lane >> 4;
    const int b_row = (lane & 7) + ((lane >= 16) ? 8 : 0);
    const int b_ch  = (lane >> 3) & 1;

    const int nk = LK >> 4;
    #pragma unroll 2
    for (int t = 0; t < nk; t++) {
        const int abuf = t & 1;
        float4 p0, p1;
        p0.x = round_tf32(__expf(s0.x - st0.x) * st0.y);
        p0.y = round_tf32(__expf(s0.y - st0.x) * st0.y);
        p0.z = round_tf32(__expf(s0.z - st0.x) * st0.y);
        p0.w = round_tf32(__expf(s0.w - st0.x) * st0.y);
        p1.x = round_tf32(__expf(s1.x - st1.x) * st1.y);
        p1.y = round_tf32(__expf(s1.y - st1.x) * st1.y);
        p1.z = round_tf32(__expf(s1.z - st1.x) * st1.y);
        p1.w = round_tf32(__expf(s1.w - st1.x) * st1.y);
        *(float4*)&As[abuf * ASZ + ld_r * 16 + ph0 * 4]        = p0;
        *(float4*)&As[abuf * ASZ + (ld_r + 64) * 16 + ph1 * 4] = p1;
        *(float4*)(Sr0 + (size_t)t * 16) = p0;
        *(float4*)(Sr1 + (size_t)t * 16) = p1;
        // rotate prefetch queue: s <- n, n <- S[t+2]
        s0 = n0; s1 = n1;
        if (t + 2 < nk) {
            n0 = *(const float4*)(Sr0 + (size_t)(t + 2) * 16);
            n1 = *(const float4*)(Sr1 + (size_t)(t + 2) * 16);
        }
        cp_wait<1>();
        __syncthreads();
        if (t + 2 < nk) loadB((t + 2) % 3, (t + 2) * 16);
        cp_commit();

        const int bbuf = t % 3;
        #pragma unroll
        for (int k8 = 0; k8 < 2; k8++) {
            const int cb = k8 * 2;
            unsigned a[MS][4], bfr[NS][2];
            #pragma unroll
            for (int i = 0; i < MS; i++) {
                int r = wm + 16 * i + a_row;
                int ph = (cb + a_ch) ^ ((r >> 1) & 3);
                ldsm4(a[i][0], a[i][1], a[i][2], a[i][3],
                      as0 + (unsigned)(abuf * ASZ + r * 16 + ph * 4) * 4u);
            }
            #pragma unroll
            for (int j = 0; j < NS / 2; j++) {
                int r = wn + 16 * j + b_row;
                int ph = (cb + b_ch) ^ ((r >> 1) & 3);
                ldsm4(bfr[2*j][0], bfr[2*j][1], bfr[2*j+1][0], bfr[2*j+1][1],
                      bs0 + (unsigned)(bbuf * BSZ + r * 16 + ph * 4) * 4u);
            }
            #pragma unroll
            for (int i = 0; i < MS; i++)
                #pragma unroll
                for (int j = 0; j < NS; j++)
                    mma_tf32(acc[i][j], a[i], bfr[j]);
        }
    }

    #pragma unroll
    for (int i = 0; i < MS; i++) {
        const int r = wm + 16 * i + (lane >> 2);
        #pragma unroll
        for (int j = 0; j < NS; j++) {
            const int cn = wn + 8 * j + 2 * (lane & 3);
            float v0 = round_tf32(acc[i][j][0]);
            float v1 = round_tf32(acc[i][j][1]);
            float v2 = round_tf32(acc[i][j][2]);
            float v3 = round_tf32(acc[i][j][3]);
            *(float2*)&Cp[(size_t)r * E_ + cn]       = make_float2(v0, v1);
            *(float2*)&Cp[(size_t)(r + 8) * E_ + cn] = make_float2(v2, v3);
        }
    }
}

// ---------------------------------------------------------------------------
// Per-batch transpose of V (float4 vectorized): vt[b][n][k] = v[b][k][n]
// ---------------------------------------------------------------------------
__global__ __launch_bounds__(256)
void transpose_v(const float* __restrict__ v, float* __restrict__ vt)
{
    __shared__ float t[32][129];
    const int b  = blockIdx.z;
    const int k0 = blockIdx.x * 32;
    const int n0 = blockIdx.y * 128;
    const int tx = threadIdx.x;        // 0..31
    const int ty = threadIdx.y;        // 0..7

    #pragma unroll
    for (int i = ty; i < 32; i += 8) {
        float4 val = *(const float4*)&v[((size_t)b * LK + k0 + i) * E_ + n0 + tx * 4];
        t[i][tx * 4 + 0] = val.x;
        t[i][tx * 4 + 1] = val.y;
        t[i][tx * 4 + 2] = val.z;
        t[i][tx * 4 + 3] = val.w;
    }
    __syncthreads();

    #pragma unroll
    for (int i = ty; i < 128; i += 8)
        vt[((size_t)b * E_ + n0 + i) * LK + k0 + tx] = t[tx][i];
}

// ---------------------------------------------------------------------------
// out = LayerNorm(a + b) * g + beta
// ---------------------------------------------------------------------------
template<int ROUND>
__global__ __launch_bounds__(256)
void ln_residual(const float* __restrict__ A, const float* __restrict__ Bx,
                 const float* __restrict__ g, const float* __restrict__ be,
                 float* __restrict__ out)
{
    const size_t row = blockIdx.x;
    const int t = threadIdx.x;

    float4 a = ((const float4*)(A  + row * E_))[t];
    float4 b = ((const float4*)(Bx + row * E_))[t];
    float4 x = make_float4(a.x + b.x, a.y + b.y, a.z + b.z, a.w + b.w);

    float s  = x.x + x.y + x.z + x.w;
    float ss = x.x*x.x + x.y*x.y + x.z*x.z + x.w*x.w;

    __shared__ float rs_[8], rss[8];
    #pragma unroll
    for (int o = 16; o > 0; o >>= 1) {
        s  += __shfl_xor_sync(0xffffffffu, s,  o);
        ss += __shfl_xor_sync(0xffffffffu, ss, o);
    }
    if ((t & 31) == 0) { rs_[t >> 5] = s; rss[t >> 5] = ss; }
    __syncthreads();
    s = 0.f; ss = 0.f;
    #pragma unroll
    for (int i = 0; i < 8; i++) { s += rs_[i]; ss += rss[i]; }

    const float mean = s * (1.0f / E_);
    const float var  = ss * (1.0f / E_) - mean * mean;
    const float inv  = rsqrtf(var + 1e-5f);

    float4 gg = ((const float4*)g)[t];
    float4 bb = ((const float4*)be)[t];
    float4 o;
    o.x = (x.x - mean) * inv * gg.x + bb.x;
    o.y = (x.y - mean) * inv * gg.y + bb.y;
    o.z = (x.z - mean) * inv * gg.z + bb.z;
    o.w = (x.w - mean) * inv * gg.w + bb.w;
    if (ROUND) {
        o.x = round_tf32(o.x); o.y = round_tf32(o.y);
        o.z = round_tf32(o.z); o.w = round_tf32(o.w);
    }
    ((float4*)(out + row * E_))[t] = o;
}

// ---------------------------------------------------------------------------
extern "C" void kernel_launch(void* const* d_in, const int* in_sizes, int n_in,
                              void* d_out, int out_size)
{
    const float* query = (const float*)d_in[0];
    const float* keyv  = (const float*)d_in[1];
    const float* wq = (const float*)d_in[2];
    const float* wk = (const float*)d_in[3];
    const float* wv = (const float*)d_in[4];
    const float* bq = (const float*)d_in[5];
    const float* bk = (const float*)d_in[6];
    const float* bv = (const float*)d_in[7];
    const float* wo = (const float*)d_in[8];
    const float* bo = (const float*)d_in[9];
    const float* g1 = (const float*)d_in[10];
    const float* be1 = (const float*)d_in[11];
    const float* w1 = (const float*)d_in[12];
    const float* b1 = (const float*)d_in[13];
    const float* w2 = (const float*)d_in[14];
    const float* b2 = (const float*)d_in[15];
    const float* g2 = (const float*)d_in[16];
    const float* be2 = (const float*)d_in[17];

    float* out = (float*)d_out;
    float* q3_out = out;
    float* attn   = out + (size_t)MQ * E_;

    float *gq, *gk, *gv, *gvt, *gctx, *gao, *gq2, *gf1, *gf2;
    float *rq, *rkv, *rwq, *rwk, *rwv, *rwo, *rw1, *rw2;
    float2 *sst, *rst;
    cudaGetSymbolAddress((void**)&gq,  g_q);
    cudaGetSymbolAddress((void**)&gk,  g_k);
    cudaGetSymbolAddress((void**)&gv,  g_v);
    cudaGetSymbolAddress((void**)&gvt, g_vt);
    cudaGetSymbolAddress((void**)&gctx, g_ctx);
    cudaGetSymbolAddress((void**)&gao, g_attnout);
    cudaGetSymbolAddress((void**)&gq2, g_q2);
    cudaGetSymbolAddress((void**)&gf1, g_ffn1);
    cudaGetSymbolAddress((void**)&gf2, g_ffn2);
    cudaGetSymbolAddress((void**)&rq,  r_query);
    cudaGetSymbolAddress((void**)&rkv, r_kv);
    cudaGetSymbolAddress((void**)&rwq, r_wq);
    cudaGetSymbolAddress((void**)&rwk, r_wk);
    cudaGetSymbolAddress((void**)&rwv, r_wv);
    cudaGetSymbolAddress((void**)&rwo, r_wo);
    cudaGetSymbolAddress((void**)&rw1, r_w1);
    cudaGetSymbolAddress((void**)&rw2, r_w2);
    cudaGetSymbolAddress((void**)&sst, g_sstats);
    cudaGetSymbolAddress((void**)&rst, g_rowstats);

    // one-time setup: smem attrs + side streams/events for capture forks
    static cudaStream_t s1 = nullptr, s2 = nullptr;
    static cudaEvent_t e0, e1, e2;
    if (!s1) {
        cudaFuncSetAttribute(tf32_gemm<128,128,64,32,0>,
                             cudaFuncAttributeMaxDynamicSharedMemorySize, 98304);
        cudaFuncSetAttribute(tf32_gemm<128,128,64,32,1>,
                             cudaFuncAttributeMaxDynamicSharedMemorySize, 98304);
        cudaFuncSetAttribute(tf32_gemm<128,64,32,32,0>,
                             cudaFuncAttributeMaxDynamicSharedMemorySize, 73728);
        cudaFuncSetAttribute(tf32_gemm<128,64,32,32,1>,
                             cudaFuncAttributeMaxDynamicSharedMemorySize, 73728);
        cudaStreamCreateWithFlags(&s1, cudaStreamNonBlocking);
        cudaStreamCreateWithFlags(&s2, cudaStreamNonBlocking);
        cudaEventCreateWithFlags(&e0, cudaEventDisableTiming);
        cudaEventCreateWithFlags(&e1, cudaEventDisableTiming);
        cudaEventCreateWithFlags(&e2, cudaEventDisableTiming);
    }
    const int GS128 = 98304;
    const int GS64  = 73728;

    // ---- prepass: round all external GEMM inputs to tf32 (one kernel) ----
    RCArgs rc;
    rc.src[0] = (const float4*)query; rc.dst[0] = (float4*)rq;
    rc.src[1] = (const float4*)keyv;  rc.dst[1] = (float4*)rkv;
    rc.src[2] = (const float4*)wq;    rc.dst[2] = (float4*)rwq;
    rc.src[3] = (const float4*)wk;    rc.dst[3] = (float4*)rwk;
    rc.src[4] = (const float4*)wv;    rc.dst[4] = (float4*)rwv;
    rc.src[5] = (const float4*)wo;    rc.dst[5] = (float4*)rwo;
    rc.src[6] = (const float4*)w1;    rc.dst[6] = (float4*)rw1;
    rc.src[7] = (const float4*)w2;    rc.dst[7] = (float4*)rw2;
    const int rc_total = RC_N0 + RC_N1 + 4*RC_NW + 2*RC_NF;
    round_copy_all<<<2048, 256>>>(rc, rc_total);

    // fork: default = K proj, s1 = V proj + transpose, s2 = Q proj
    cudaEventRecord(e0, 0);
    cudaStreamWaitEvent(s1, e0, 0);
    cudaStreamWaitEvent(s2, e0, 0);

    tf32_gemm<128,128,64,32,1><<<dim3(E_/128, MK/128), 256, GS128>>>(
        rkv, E_,  rwk, E_,  bk,  gk, E_,  E_, 1.f, 0);

    tf32_gemm<128,128,64,32,1><<<dim3(E_/128, MK/128), 256, GS128, s1>>>(
        rkv, E_,  rwv, E_,  bv,  gv, E_,  E_, 1.f, 0);
    transpose_v<<<dim3(LK/32, E_/128, B_), dim3(32, 8), 0, s1>>>(gv, gvt);
    cudaEventRecord(e1, s1);

    tf32_gemm<128,64,32,32,1><<<dim3(E_/64, MQ/128), 256, GS64, s2>>>(
        rq,  E_,  rwq, E_,  bq,  gq, E_,  E_, 1.f, 0);
    cudaEventRecord(e2, s2);

    // join: scores needs Q (s2) and K (default)
    cudaStreamWaitEvent(0, e2, 0);
    scores_stats<<<dim3(LK/128, LQ/128, B_*H_), 256>>>(gq, gk, attn, sst);
    rowcombine<<<(B_*H_*LQ)/256, 256>>>(sst, rst);

    // ctx needs transpose (s1)
    cudaStreamWaitEvent(0, e1, 0);
    ctx_fused<<<dim3(LQ/128, B_*H_), 256>>>(rst, attn, gvt, gctx);

    // ---- output projection + LN1 ----
    tf32_gemm<128,64,32,32,0><<<dim3(E_/64, MQ/128), 256, GS64>>>(
        gctx, E_,  rwo, E_,  bo,  gao, E_,  E_, 1.f, 0);
    ln_residual<1><<<MQ, 256>>>(query, gao, g1, be1, gq2);

    // ---- FFN + LN2 ----
    tf32_gemm<128,128,64,32,1><<<dim3(F_/128, MQ/128), 256, GS128>>>(
        gq2, E_,  rw1, E_,  b1,  gf1, F_,  E_, 1.f, 1);
    tf32_gemm<128,64,32,32,0><<<dim3(E_/64, MQ/128), 256, GS64>>>(
        gf1, F_,  rw2, F_,  b2,  gf2, E_,  F_, 1.f, 0);
    ln_residual<0><<<MQ, 256>>>(gq2, gf2, g2, be2, q3_out);
}

// round 14
// speedup vs baseline: 1.5784x; 1.0160x over previous
#include <cuda_runtime.h>
#include <cstddef>

// Problem constants
#define B_  4
#define LQ  512
#define LK  2048
#define E_  1024
#define H_  16
#define DH  64
#define F_  4096
#define MQ  (B_*LQ)    // 2048
#define MK  (B_*LK)    // 8192

// ---------------- scratch (device globals; no allocation allowed) ----------
__device__ float g_q[MQ * E_];
__device__ float g_k[MK * E_];
__device__ float g_v[MK * E_];
__device__ float g_vt[MK * E_];
__device__ float g_ctx[MQ * E_];
__device__ float g_attnout[MQ * E_];
__device__ float g_q2[MQ * E_];
__device__ float g_ffn1[MQ * F_];
__device__ float g_ffn2[MQ * E_];
// tf32-rounded copies of external inputs
__device__ float r_query[MQ * E_];
__device__ float r_kv[MK * E_];
__device__ float r_wq[E_ * E_];
__device__ float r_wk[E_ * E_];
__device__ float r_wv[E_ * E_];
__device__ float r_wo[E_ * E_];
__device__ float r_w1[F_ * E_];
__device__ float r_w2[E_ * F_];
// softmax statistics
__device__ float2 g_sstats[64 * 16 * 512];
__device__ float2 g_rowstats[64 * 512];

// ---------------------------------------------------------------------------
// helpers
// ---------------------------------------------------------------------------
__device__ __forceinline__ unsigned cvt_tf32(float x) {
    unsigned r;
    asm("cvt.rna.tf32.f32 %0, %1;" : "=r"(r) : "f"(x));
    return r;
}
__device__ __forceinline__ float round_tf32(float x) {
    return __uint_as_float(cvt_tf32(x));
}

__device__ __forceinline__ void cp_async16(unsigned saddr, const void* gptr) {
    asm volatile("cp.async.cg.shared.global [%0], [%1], 16;" :: "r"(saddr), "l"(gptr));
}
__device__ __forceinline__ void cp_commit() {
    asm volatile("cp.async.commit_group;");
}
template<int N>
__device__ __forceinline__ void cp_wait() {
    asm volatile("cp.async.wait_group %0;" :: "n"(N));
}

__device__ __forceinline__ void ldsm4(unsigned &r0, unsigned &r1,
                                      unsigned &r2, unsigned &r3, unsigned addr) {
    asm volatile("ldmatrix.sync.aligned.m8n8.x4.shared.b16 {%0,%1,%2,%3}, [%4];"
                 : "=r"(r0), "=r"(r1), "=r"(r2), "=r"(r3) : "r"(addr));
}

__device__ __forceinline__ void mma_tf32(float c[4], const unsigned a[4],
                                         const unsigned b[2]) {
    asm volatile(
        "mma.sync.aligned.m16n8k8.row.col.f32.tf32.tf32.f32 "
        "{%0,%1,%2,%3}, {%4,%5,%6,%7}, {%8,%9}, {%0,%1,%2,%3};"
        : "+f"(c[0]), "+f"(c[1]), "+f"(c[2]), "+f"(c[3])
        : "r"(a[0]), "r"(a[1]), "r"(a[2]), "r"(a[3]), "r"(b[0]), "r"(b[1]));
}

// ---------------------------------------------------------------------------
// tf32 round-copy over a list of segments (front / late instances)
// ---------------------------------------------------------------------------
struct RCArgs {
    const float4* src[5];
    float4*       dst[5];
    int           off[6];   // prefix offsets in float4 units; off[nseg]=total
    int           nseg;
};

__global__ __launch_bounds__(256)
void round_copy_seg(RCArgs rc)
{
    const int total = rc.off[rc.nseg];
    for (int i = blockIdx.x * blockDim.x + threadIdx.x; i < total;
         i += gridDim.x * blockDim.x) {
        int seg = 0;
        #pragma unroll
        for (int s = 1; s < 5; s++) if (s < rc.nseg && i >= rc.off[s]) seg = s;
        int j = i - rc.off[seg];
        float4 v = rc.src[seg][j];
        v.x = round_tf32(v.x); v.y = round_tf32(v.y);
        v.z = round_tf32(v.z); v.w = round_tf32(v.w);
        rc.dst[seg][j] = v;
    }
}

// ---------------------------------------------------------------------------
// Pipelined NT GEMM, tf32 tensor cores, BK=32, 3 stages, ONE sync per k-iter.
// Inputs pre-rounded to tf32.
// ---------------------------------------------------------------------------
template<int BM, int BN, int WM, int WN, int ROUND>
__global__ __launch_bounds__(256)
void tf32_gemm(const float* __restrict__ A, int lda,
               const float* __restrict__ B, int ldb,
               const float* __restrict__ bias,
               float* __restrict__ C, int ldc,
               int K, float scale, int relu)
{
    constexpr int WARPS_N = BN / WN;
    constexpr int MS = WM / 16, NS = WN / 8;
    constexpr int ASZ = BM * 32;
    constexpr int BSZ = BN * 32;

    extern __shared__ __align__(16) float sm[];
    float* As = sm;
    float* Bs = sm + 3 * ASZ;

    const int bm = blockIdx.y * BM, bn = blockIdx.x * BN;
    const int tid = threadIdx.x, warp = tid >> 5, lane = tid & 31;
    const int wm = (warp / WARPS_N) * WM, wn = (warp % WARPS_N) * WN;

    const unsigned as0 = (unsigned)__cvta_generic_to_shared(As);
    const unsigned bs0 = (unsigned)__cvta_generic_to_shared(Bs);

    const int ld_r = tid >> 3;
    const int ld_c = tid & 7;

    auto load_stage = [&](int buf, int k0) {
        #pragma unroll
        for (int i = 0; i < BM / 32; i++) {
            int r = ld_r + i * 32;
            int ph = ld_c ^ (r & 7);
            cp_async16(as0 + (unsigned)(buf * ASZ + r * 32 + ph * 4) * 4u,
                       A + (size_t)(bm + r) * lda + k0 + ld_c * 4);
        }
        #pragma unroll
        for (int i = 0; i < BN / 32; i++) {
            int r = ld_r + i * 32;
            int ph = ld_c ^ (r & 7);
            cp_async16(bs0 + (unsigned)(buf * BSZ + r * 32 + ph * 4) * 4u,
                       B + (size_t)(bn + r) * ldb + k0 + ld_c * 4);
        }
    };

    float acc[MS][NS][4];
    #pragma unroll
    for (int i = 0; i < MS; i++)
        #pragma unroll
        for (int j = 0; j < NS; j++)
            #pragma unroll
            for (int r = 0; r < 4; r++) acc[i][j][r] = 0.f;

    const int a_row = (lane & 7) + ((lane >> 3) & 1) * 8;
    const int a_ch  = lane >> 4;
    const int b_row = (lane & 7) + ((lane >= 16) ? 8 : 0);
    const int b_ch  = (lane >> 3) & 1;

    const int nk = K >> 5;
    load_stage(0, 0);  cp_commit();
    load_stage(1, 32); cp_commit();

    for (int ks = 0; ks < nk; ks++) {
        cp_wait<1>();
        __syncthreads();
        const int buf = ks % 3;
        if (ks + 2 < nk) load_stage((ks + 2) % 3, (ks + 2) << 5);
        cp_commit();

        #pragma unroll
        for (int k8 = 0; k8 < 4; k8++) {
            const int cb = k8 * 2;
            unsigned a[MS][4], b[NS][2];
            #pragma unroll
            for (int i = 0; i < MS; i++) {
                int r = wm + 16 * i + a_row;
                int ph = (cb + a_ch) ^ (r & 7);
                ldsm4(a[i][0], a[i][1], a[i][2], a[i][3],
                      as0 + (unsigned)(buf * ASZ + r * 32 + ph * 4) * 4u);
            }
            #pragma unroll
            for (int j = 0; j < NS / 2; j++) {
                int r = wn + 16 * j + b_row;
                int ph = (cb + b_ch) ^ (r & 7);
                ldsm4(b[2*j][0], b[2*j][1], b[2*j+1][0], b[2*j+1][1],
                      bs0 + (unsigned)(buf * BSZ + r * 32 + ph * 4) * 4u);
            }
            #pragma unroll
            for (int i = 0; i < MS; i++)
                #pragma unroll
                for (int j = 0; j < NS; j++)
                    mma_tf32(acc[i][j], a[i], b[j]);
        }
    }

    #pragma unroll
    for (int i = 0; i < MS; i++) {
        const int r = bm + wm + 16 * i + (lane >> 2);
        #pragma unroll
        for (int j = 0; j < NS; j++) {
            const int cn = bn + wn + 8 * j + 2 * (lane & 3);
            float bx = 0.f, by = 0.f;
            if (bias) { float2 bb = *(const float2*)&bias[cn]; bx = bb.x; by = bb.y; }
            float v0 = acc[i][j][0] * scale + bx;
            float v1 = acc[i][j][1] * scale + by;
            float v2 = acc[i][j][2] * scale + bx;
            float v3 = acc[i][j][3] * scale + by;
            if (relu) {
                v0 = fmaxf(v0, 0.f); v1 = fmaxf(v1, 0.f);
                v2 = fmaxf(v2, 0.f); v3 = fmaxf(v3, 0.f);
            }
            if (ROUND) {
                v0 = round_tf32(v0); v1 = round_tf32(v1);
                v2 = round_tf32(v2); v3 = round_tf32(v3);
            }
            *(float2*)&C[(size_t)r * ldc + cn]       = make_float2(v0, v1);
            *(float2*)&C[(size_t)(r + 8) * ldc + cn] = make_float2(v2, v3);
        }
    }
}

// ---------------------------------------------------------------------------
// Scores GEMM + per-slab softmax statistics.
// ---------------------------------------------------------------------------
__global__ __launch_bounds__(256)
void scores_stats(const float* __restrict__ q, const float* __restrict__ k,
                  float* __restrict__ attn, float2* __restrict__ sstats)
{
    constexpr int BM = 128, BN = 128, WM = 64, WN = 32;
    constexpr int WARPS_N = BN / WN;
    constexpr int MS = WM / 16, NS = WN / 8;
    constexpr int ASZ = BM * 16, BSZ = BN * 16;

    __shared__ __align__(16) float As[3 * ASZ];
    __shared__ __align__(16) float Bs[3 * BSZ];

    const int z = blockIdx.z;
    const int b = z >> 4, h = z & 15;
    const float* A = q + (size_t)b * LQ * E_ + h * DH;
    const float* B = k + (size_t)b * LK * E_ + h * DH;
    float* C = attn + (size_t)z * LQ * LK;

    const int bm = blockIdx.y * BM, bn = blockIdx.x * BN;
    const int tid = threadIdx.x, warp = tid >> 5, lane = tid & 31;
    const int wm = (warp / WARPS_N) * WM, wn = (warp % WARPS_N) * WN;

    const unsigned as0 = (unsigned)__cvta_generic_to_shared(As);
    const unsigned bs0 = (unsigned)__cvta_generic_to_shared(Bs);
    const int ld_r = tid >> 2, ld_c = tid & 3;

    auto load_stage = [&](int buf, int k0) {
        #pragma unroll
        for (int i = 0; i < 2; i++) {
            int r = ld_r + i * 64;
            int ph = ld_c ^ ((r >> 1) & 3);
            cp_async16(as0 + (unsigned)(buf * ASZ + r * 16 + ph * 4) * 4u,
                       A + (size_t)(bm + r) * E_ + k0 + ld_c * 4);
            cp_async16(bs0 + (unsigned)(buf * BSZ + r * 16 + ph * 4) * 4u,
                       B + (size_t)(bn + r) * E_ + k0 + ld_c * 4);
        }
    };

    float acc[MS][NS][4];
    #pragma unroll
    for (int i = 0; i < MS; i++)
        #pragma unroll
        for (int j = 0; j < NS; j++)
            #pragma unroll
            for (int r = 0; r < 4; r++) acc[i][j][r] = 0.f;

    const int a_row = (lane & 7) + ((lane >> 3) & 1) * 8;
    const int a_ch  = lane >> 4;
    const int b_row = (lane & 7) + ((lane >= 16) ? 8 : 0);
    const int b_ch  = (lane >> 3) & 1;

    const int nk = DH >> 4;
    load_stage(0, 0);  cp_commit();
    load_stage(1, 16); cp_commit();

    for (int ks = 0; ks < nk; ks++) {
        cp_wait<1>();
        __syncthreads();
        const int buf = ks % 3;
        if (ks + 2 < nk) load_stage((ks + 2) % 3, (ks + 2) << 4);
        cp_commit();

        #pragma unroll
        for (int k8 = 0; k8 < 2; k8++) {
            const int cb = k8 * 2;
            unsigned a[MS][4], bfr[NS][2];
            #pragma unroll
            for (int i = 0; i < MS; i++) {
                int r = wm + 16 * i + a_row;
                int ph = (cb + a_ch) ^ ((r >> 1) & 3);
                ldsm4(a[i][0], a[i][1], a[i][2], a[i][3],
                      as0 + (unsigned)(buf * ASZ + r * 16 + ph * 4) * 4u);
            }
            #pragma unroll
            for (int j = 0; j < NS / 2; j++) {
                int r = wn + 16 * j + b_row;
                int ph = (cb + b_ch) ^ ((r >> 1) & 3);
                ldsm4(bfr[2*j][0], bfr[2*j][1], bfr[2*j+1][0], bfr[2*j+1][1],
                      bs0 + (unsigned)(buf * BSZ + r * 16 + ph * 4) * 4u);
            }
            #pragma unroll
            for (int i = 0; i < MS; i++)
                #pragma unroll
                for (int j = 0; j < NS; j++)
                    mma_tf32(acc[i][j], a[i], bfr[j]);
        }
        __syncthreads();
    }

    #pragma unroll
    for (int i = 0; i < MS; i++)
        #pragma unroll
        for (int j = 0; j < NS; j++)
            #pragma unroll
            for (int r = 0; r < 4; r++) acc[i][j][r] *= 0.125f;

    #pragma unroll
    for (int i = 0; i < MS; i++) {
        const int r = bm + wm + 16 * i + (lane >> 2);
        #pragma unroll
        for (int j = 0; j < NS; j++) {
            const int cn = bn + wn + 8 * j + 2 * (lane & 3);
            *(float2*)&C[(size_t)r * LK + cn]       = make_float2(acc[i][j][0], acc[i][j][1]);
            *(float2*)&C[(size_t)(r + 8) * LK + cn] = make_float2(acc[i][j][2], acc[i][j][3]);
        }
    }

    float* sm_m = As;
    float* sm_s = As + 512;
    __syncthreads();

    const int ng = warp % WARPS_N;
    #pragma unroll
    for (int i = 0; i < MS; i++) {
        #pragma unroll
        for (int hh = 0; hh < 2; hh++) {
            float v[8];
            #pragma unroll
            for (int j = 0; j < NS; j++) {
                v[2*j]   = acc[i][j][2*hh];
                v[2*j+1] = acc[i][j][2*hh+1];
            }
            float m = v[0];
            #pragma unroll
            for (int e = 1; e < 8; e++) m = fmaxf(m, v[e]);
            m = fmaxf(m, __shfl_xor_sync(0xffffffffu, m, 1));
            m = fmaxf(m, __shfl_xor_sync(0xffffffffu, m, 2));
            float se = 0.f;
            #pragma unroll
            for (int e = 0; e < 8; e++) se += __expf(v[e] - m);
            se += __shfl_xor_sync(0xffffffffu, se, 1);
            se += __shfl_xor_sync(0xffffffffu, se, 2);
            if ((lane & 3) == 0) {
                int row = wm + 16 * i + (lane >> 2) + 8 * hh;
                sm_m[ng * 128 + row] = m;
                sm_s[ng * 128 + row] = se;
            }
        }
    }
    __syncthreads();

    if (tid < 128) {
        float m0 = sm_m[tid], m1 = sm_m[128 + tid];
        float m2 = sm_m[256 + tid], m3 = sm_m[384 + tid];
        float M = fmaxf(fmaxf(m0, m1), fmaxf(m2, m3));
        float S = sm_s[tid]       * __expf(m0 - M)
                + sm_s[128 + tid] * __expf(m1 - M)
                + sm_s[256 + tid] * __expf(m2 - M)
                + sm_s[384 + tid] * __expf(m3 - M);
        sstats[((size_t)z * 16 + blockIdx.x) * LQ + bm + tid] = make_float2(M, S);
    }
}

// ---------------------------------------------------------------------------
// Combine 16 slab stats per row -> (M, 1/S)
// ---------------------------------------------------------------------------
__global__ __launch_bounds__(256)
void rowcombine(const float2* __restrict__ sstats, float2* __restrict__ rowstats)
{
    int idx = blockIdx.x * 256 + threadIdx.x;
    int z = idx >> 9, row = idx & 511;
    const float2* p = sstats + (size_t)z * 16 * LQ + row;
    float2 v[16];
    #pragma unroll
    for (int s = 0; s < 16; s++) v[s] = p[(size_t)s * LQ];
    float M = v[0].x;
    #pragma unroll
    for (int s = 1; s < 16; s++) M = fmaxf(M, v[s].x);
    float S = 0.f;
    #pragma unroll
    for (int s = 0; s < 16; s++) S += v[s].y * __expf(v[s].x - M);
    rowstats[idx] = make_float2(M, 1.0f / S);
}

// ---------------------------------------------------------------------------
// Fused normalize + ctx GEMM (S prefetch 2 deep).
// ---------------------------------------------------------------------------
__global__ __launch_bounds__(256)
void ctx_fused(const float2* __restrict__ rowstats,
               float* __restrict__ attn,
               const float* __restrict__ vt,
               float* __restrict__ ctx)
{
    constexpr int BM = 128, BN = 64, WM = 32, WN = 32;
    constexpr int WARPS_N = BN / WN;
    constexpr int MS = WM / 16, NS = WN / 8;
    constexpr int ASZ = BM * 16, BSZ = BN * 16;

    __shared__ __align__(16) float As[2 * ASZ];
    __shared__ __align__(16) float Bs[3 * BSZ];
    __shared__ float2 rs[BM];

    const int z = blockIdx.y;
    const int b = z >> 4, h = z & 15;
    const int bm = blockIdx.x * BM;
    float* Sp = attn + ((size_t)z * LQ + bm) * LK;
    const float* Vb = vt + ((size_t)b * E_ + h * DH) * LK;
    float* Cp = ctx + ((size_t)b * LQ + bm) * E_ + h * DH;

    const int tid = threadIdx.x, warp = tid >> 5, lane = tid & 31;
    const int wm = (warp / WARPS_N) * WM, wn = (warp % WARPS_N) * WN;

    if (tid < BM) rs[tid] = rowstats[(size_t)z * LQ + bm + tid];

    const unsigned as0 = (unsigned)__cvta_generic_to_shared(As);
    const unsigned bs0 = (unsigned)__cvta_generic_to_shared(Bs);
    const int ld_r = tid >> 2, ld_c = tid & 3;
    const int ph0 = ld_c ^ ((ld_r >> 1) & 3);
    const int ph1 = ld_c ^ (((ld_r + 64) >> 1) & 3);

    auto loadB = [&](int buf, int k0) {
        int ph = ld_c ^ ((ld_r >> 1) & 3);
        cp_async16(bs0 + (unsigned)(buf * BSZ + ld_r * 16 + ph * 4) * 4u,
                   Vb + (size_t)ld_r * LK + k0 + ld_c * 4);
    };

    loadB(0, 0);  cp_commit();
    loadB(1, 16); cp_commit();

    // 2-deep register prefetch of raw scores S
    const float* Sr0 = Sp + (size_t)ld_r * LK + ld_c * 4;
    const float* Sr1 = Sp + (size_t)(ld_r + 64) * LK + ld_c * 4;
    float4 s0 = *(const float4*)Sr0;
    float4 s1 = *(const float4*)Sr1;
    float4 n0 = *(const float4*)(Sr0 + 16);
    float4 n1 = *(const float4*)(Sr1 + 16);

    __syncthreads();
    const float2 st0 = rs[ld_r];
    const float2 st1 = rs[ld_r + 64];

    float acc[MS][NS][4];
    #pragma unroll
    for (int i = 0; i < MS; i++)
        #pragma unroll
        for (int j = 0; j < NS; j++)
            #pragma unroll
            for (int r = 0; r < 4; r++) acc[i][j][r] = 0.f;

    const int a_row = (lane & 7) + ((lane >> 3) & 1) * 8;
    const int a_ch  = lane >> 4;
    const int b_row = (lane & 7) + ((lane >= 16) ? 8 : 0);
    const int b_ch  = (lane >> 3) & 1;

    const int nk = LK >> 4;
    #pragma unroll 2
    for (int t = 0; t < nk; t++) {
        const int abuf = t & 1;
        float4 p0, p1;
        p0.x = round_tf32(__expf(s0.x - st0.x) * st0.y);
        p0.y = round_tf32(__expf(s0.y - st0.x) * st0.y);
        p0.z = round_tf32(__expf(s0.z - st0.x) * st0.y);
        p0.w = round_tf32(__expf(s0.w - st0.x) * st0.y);
        p1.x = round_tf32(__expf(s1.x - st1.x) * st1.y);
        p1.y = round_tf32(__expf(s1.y - st1.x) * st1.y);
        p1.z = round_tf32(__expf(s1.z - st1.x) * st1.y);
        p1.w = round_tf32(__expf(s1.w - st1.x) * st1.y);
        *(float4*)&As[abuf * ASZ + ld_r * 16 + ph0 * 4]        = p0;
        *(float4*)&As[abuf * ASZ + (ld_r + 64) * 16 + ph1 * 4] = p1;
        *(float4*)(Sr0 + (size_t)t * 16) = p0;
        *(float4*)(Sr1 + (size_t)t * 16) = p1;
        s0 = n0; s1 = n1;
        if (t + 2 < nk) {
            n0 = *(const float4*)(Sr0 + (size_t)(t + 2) * 16);
            n1 = *(const float4*)(Sr1 + (size_t)(t + 2) * 16);
        }
        cp_wait<1>();
        __syncthreads();
        if (t + 2 < nk) loadB((t + 2) % 3, (t + 2) * 16);
        cp_commit();

        const int bbuf = t % 3;
        #pragma unroll
        for (int k8 = 0; k8 < 2; k8++) {
            const int cb = k8 * 2;
            unsigned a[MS][4], bfr[NS][2];
            #pragma unroll
            for (int i = 0; i < MS; i++) {
                int r = wm + 16 * i + a_row;
                int ph = (cb + a_ch) ^ ((r >> 1) & 3);
                ldsm4(a[i][0], a[i][1], a[i][2], a[i][3],
                      as0 + (unsigned)(abuf * ASZ + r * 16 + ph * 4) * 4u);
            }
            #pragma unroll
            for (int j = 0; j < NS / 2; j++) {
                int r = wn + 16 * j + b_row;
                int ph = (cb + b_ch) ^ ((r >> 1) & 3);
                ldsm4(bfr[2*j][0], bfr[2*j][1], bfr[2*j+1][0], bfr[2*j+1][1],
                      bs0 + (unsigned)(bbuf * BSZ + r * 16 + ph * 4) * 4u);
            }
            #pragma unroll
            for (int i = 0; i < MS; i++)
                #pragma unroll
                for (int j = 0; j < NS; j++)
                    mma_tf32(acc[i][j], a[i], bfr[j]);
        }
    }

    #pragma unroll
    for (int i = 0; i < MS; i++) {
        const int r = wm + 16 * i + (lane >> 2);
        #pragma unroll
        for (int j = 0; j < NS; j++) {
            const int cn = wn + 8 * j + 2 * (lane & 3);
            float v0 = round_tf32(acc[i][j][0]);
            float v1 = round_tf32(acc[i][j][1]);
            float v2 = round_tf32(acc[i][j][2]);
            float v3 = round_tf32(acc[i][j][3]);
            *(float2*)&Cp[(size_t)r * E_ + cn]       = make_float2(v0, v1);
            *(float2*)&Cp[(size_t)(r + 8) * E_ + cn] = make_float2(v2, v3);
        }
    }
}

// ---------------------------------------------------------------------------
// Per-batch transpose of V (float4 vectorized): vt[b][n][k] = v[b][k][n]
// ---------------------------------------------------------------------------
__global__ __launch_bounds__(256)
void transpose_v(const float* __restrict__ v, float* __restrict__ vt)
{
    __shared__ float t[32][129];
    const int b  = blockIdx.z;
    const int k0 = blockIdx.x * 32;
    const int n0 = blockIdx.y * 128;
    const int tx = threadIdx.x;
    const int ty = threadIdx.y;

    #pragma unroll
    for (int i = ty; i < 32; i += 8) {
        float4 val = *(const float4*)&v[((size_t)b * LK + k0 + i) * E_ + n0 + tx * 4];
        t[i][tx * 4 + 0] = val.x;
        t[i][tx * 4 + 1] = val.y;
        t[i][tx * 4 + 2] = val.z;
        t[i][tx * 4 + 3] = val.w;
    }
    __syncthreads();

    #pragma unroll
    for (int i = ty; i < 128; i += 8)
        vt[((size_t)b * E_ + n0 + i) * LK + k0 + tx] = t[tx][i];
}

// ---------------------------------------------------------------------------
// out = LayerNorm(a + b) * g + beta
// ---------------------------------------------------------------------------
template<int ROUND>
__global__ __launch_bounds__(256)
void ln_residual(const float* __restrict__ A, const float* __restrict__ Bx,
                 const float* __restrict__ g, const float* __restrict__ be,
                 float* __restrict__ out)
{
    const size_t row = blockIdx.x;
    const int t = threadIdx.x;

    float4 a = ((const float4*)(A  + row * E_))[t];
    float4 b = ((const float4*)(Bx + row * E_))[t];
    float4 x = make_float4(a.x + b.x, a.y + b.y, a.z + b.z, a.w + b.w);

    float s  = x.x + x.y + x.z + x.w;
    float ss = x.x*x.x + x.y*x.y + x.z*x.z + x.w*x.w;

    __shared__ float rs_[8], rss[8];
    #pragma unroll
    for (int o = 16; o > 0; o >>= 1) {
        s  += __shfl_xor_sync(0xffffffffu, s,  o);
        ss += __shfl_xor_sync(0xffffffffu, ss, o);
    }
    if ((t & 31) == 0) { rs_[t >> 5] = s; rss[t >> 5] = ss; }
    __syncthreads();
    s = 0.f; ss = 0.f;
    #pragma unroll
    for (int i = 0; i < 8; i++) { s += rs_[i]; ss += rss[i]; }

    const float mean = s * (1.0f / E_);
    const float var  = ss * (1.0f / E_) - mean * mean;
    const float inv  = rsqrtf(var + 1e-5f);

    float4 gg = ((const float4*)g)[t];
    float4 bb = ((const float4*)be)[t];
    float4 o;
    o.x = (x.x - mean) * inv * gg.x + bb.x;
    o.y = (x.y - mean) * inv * gg.y + bb.y;
    o.z = (x.z - mean) * inv * gg.z + bb.z;
    o.w = (x.w - mean) * inv * gg.w + bb.w;
    if (ROUND) {
        o.x = round_tf32(o.x); o.y = round_tf32(o.y);
        o.z = round_tf32(o.z); o.w = round_tf32(o.w);
    }
    ((float4*)(out + row * E_))[t] = o;
}

// ---------------------------------------------------------------------------
extern "C" void kernel_launch(void* const* d_in, const int* in_sizes, int n_in,
                              void* d_out, int out_size)
{
    const float* query = (const float*)d_in[0];
    const float* keyv  = (const float*)d_in[1];
    const float* wq = (const float*)d_in[2];
    const float* wk = (const float*)d_in[3];
    const float* wv = (const float*)d_in[4];
    const float* bq = (const float*)d_in[5];
    const float* bk = (const float*)d_in[6];
    const float* bv = (const float*)d_in[7];
    const float* wo = (const float*)d_in[8];
    const float* bo = (const float*)d_in[9];
    const float* g1 = (const float*)d_in[10];
    const float* be1 = (const float*)d_in[11];
    const float* w1 = (const float*)d_in[12];
    const float* b1 = (const float*)d_in[13];
    const float* w2 = (const float*)d_in[14];
    const float* b2 = (const float*)d_in[15];
    const float* g2 = (const float*)d_in[16];
    const float* be2 = (const float*)d_in[17];

    float* out = (float*)d_out;
    float* q3_out = out;
    float* attn   = out + (size_t)MQ * E_;

    float *gq, *gk, *gv, *gvt, *gctx, *gao, *gq2, *gf1, *gf2;
    float *rq, *rkv, *rwq, *rwk, *rwv, *rwo, *rw1, *rw2;
    float2 *sst, *rst;
    cudaGetSymbolAddress((void**)&gq,  g_q);
    cudaGetSymbolAddress((void**)&gk,  g_k);
    cudaGetSymbolAddress((void**)&gv,  g_v);
    cudaGetSymbolAddress((void**)&gvt, g_vt);
    cudaGetSymbolAddress((void**)&gctx, g_ctx);
    cudaGetSymbolAddress((void**)&gao, g_attnout);
    cudaGetSymbolAddress((void**)&gq2, g_q2);
    cudaGetSymbolAddress((void**)&gf1, g_ffn1);
    cudaGetSymbolAddress((void**)&gf2, g_ffn2);
    cudaGetSymbolAddress((void**)&rq,  r_query);
    cudaGetSymbolAddress((void**)&rkv, r_kv);
    cudaGetSymbolAddress((void**)&rwq, r_wq);
    cudaGetSymbolAddress((void**)&rwk, r_wk);
    cudaGetSymbolAddress((void**)&rwv, r_wv);
    cudaGetSymbolAddress((void**)&rwo, r_wo);
    cudaGetSymbolAddress((void**)&rw1, r_w1);
    cudaGetSymbolAddress((void**)&rw2, r_w2);
    cudaGetSymbolAddress((void**)&sst, g_sstats);
    cudaGetSymbolAddress((void**)&rst, g_rowstats);

    // one-time setup
    static cudaStream_t s1 = nullptr, s2 = nullptr;
    static cudaEvent_t e0, e1, e2, e3;
    if (!s1) {
        cudaFuncSetAttribute(tf32_gemm<128,128,64,32,0>,
                             cudaFuncAttributeMaxDynamicSharedMemorySize, 98304);
        cudaFuncSetAttribute(tf32_gemm<128,128,64,32,1>,
                             cudaFuncAttributeMaxDynamicSharedMemorySize, 98304);
        cudaFuncSetAttribute(tf32_gemm<128,64,32,32,0>,
                             cudaFuncAttributeMaxDynamicSharedMemorySize, 73728);
        cudaFuncSetAttribute(tf32_gemm<128,64,32,32,1>,
                             cudaFuncAttributeMaxDynamicSharedMemorySize, 73728);
        cudaStreamCreateWithFlags(&s1, cudaStreamNonBlocking);
        cudaStreamCreateWithFlags(&s2, cudaStreamNonBlocking);
        cudaEventCreateWithFlags(&e0, cudaEventDisableTiming);
        cudaEventCreateWithFlags(&e1, cudaEventDisableTiming);
        cudaEventCreateWithFlags(&e2, cudaEventDisableTiming);
        cudaEventCreateWithFlags(&e3, cudaEventDisableTiming);
    }
    const int GS128 = 98304;
    const int GS64  = 73728;

    // ---- front prepass: only what Q/K/V projections need (168 MB) ----
    {
        RCArgs rc;
        rc.src[0] = (const float4*)query; rc.dst[0] = (float4*)rq;
        rc.src[1] = (const float4*)keyv;  rc.dst[1] = (float4*)rkv;
        rc.src[2] = (const float4*)wq;    rc.dst[2] = (float4*)rwq;
        rc.src[3] = (const float4*)wk;    rc.dst[3] = (float4*)rwk;
        rc.src[4] = (const float4*)wv;    rc.dst[4] = (float4*)rwv;
        rc.off[0] = 0;
        rc.off[1] = MQ*E_/4;
        rc.off[2] = rc.off[1] + MK*E_/4;
        rc.off[3] = rc.off[2] + E_*E_/4;
        rc.off[4] = rc.off[3] + E_*E_/4;
        rc.off[5] = rc.off[4] + E_*E_/4;
        rc.nseg = 5;
        round_copy_seg<<<2048, 256>>>(rc);
    }

    // fork: default = K proj, s1 = V proj + transpose + late prepass, s2 = Q proj
    cudaEventRecord(e0, 0);
    cudaStreamWaitEvent(s1, e0, 0);
    cudaStreamWaitEvent(s2, e0, 0);

    tf32_gemm<128,128,64,32,1><<<dim3(E_/128, MK/128), 256, GS128>>>(
        rkv, E_,  rwk, E_,  bk,  gk, E_,  E_, 1.f, 0);

    tf32_gemm<128,128,64,32,1><<<dim3(E_/128, MK/128), 256, GS128, s1>>>(
        rkv, E_,  rwv, E_,  bv,  gv, E_,  E_, 1.f, 0);
    transpose_v<<<dim3(LK/32, E_/128, B_), dim3(32, 8), 0, s1>>>(gv, gvt);
    cudaEventRecord(e1, s1);

    // late prepass (wo, w1, w2 = 208 MB) on s1 — hidden under scores/ctx
    {
        RCArgs rc;
        rc.src[0] = (const float4*)wo; rc.dst[0] = (float4*)rwo;
        rc.src[1] = (const float4*)w1; rc.dst[1] = (float4*)rw1;
        rc.src[2] = (const float4*)w2; rc.dst[2] = (float4*)rw2;
        rc.off[0] = 0;
        rc.off[1] = E_*E_/4;
        rc.off[2] = rc.off[1] + F_*E_/4;
        rc.off[3] = rc.off[2] + E_*F_/4;
        rc.off[4] = rc.off[3];
        rc.off[5] = rc.off[3];
        rc.nseg = 3;
        round_copy_seg<<<1024, 256, 0, s1>>>(rc);
    }
    cudaEventRecord(e3, s1);

    tf32_gemm<128,64,32,32,1><<<dim3(E_/64, MQ/128), 256, GS64, s2>>>(
        rq,  E_,  rwq, E_,  bq,  gq, E_,  E_, 1.f, 0);
    cudaEventRecord(e2, s2);

    // join: scores needs Q (s2) and K (default)
    cudaStreamWaitEvent(0, e2, 0);
    scores_stats<<<dim3(LK/128, LQ/128, B_*H_), 256>>>(gq, gk, attn, sst);
    rowcombine<<<(B_*H_*LQ)/256, 256>>>(sst, rst);

    // ctx needs transpose (s1: e1)
    cudaStreamWaitEvent(0, e1, 0);
    ctx_fused<<<dim3(LQ/128, B_*H_), 256>>>(rst, attn, gvt, gctx);

    // ---- output projection + LN1 (needs late weights: e3) ----
    cudaStreamWaitEvent(0, e3, 0);
    tf32_gemm<128,64,32,32,0><<<dim3(E_/64, MQ/128), 256, GS64>>>(
        gctx, E_,  rwo, E_,  bo,  gao, E_,  E_, 1.f, 0);
    ln_residual<1><<<MQ, 256>>>(query, gao, g1, be1, gq2);

    // ---- FFN + LN2 ----
    tf32_gemm<128,128,64,32,1><<<dim3(F_/128, MQ/128), 256, GS128>>>(
        gq2, E_,  rw1, E_,  b1,  gf1, F_,  E_, 1.f, 1);
    tf32_gemm<128,64,32,32,0><<<dim3(E_/64, MQ/128), 256, GS64>>>(
        gf1, F_,  rw2, F_,  b2,  gf2, E_,  F_, 1.f, 0);
    ln_residual<0><<<MQ, 256>>>(gq2, gf2, g2, be2, q3_out);
}

// round 15
// speedup vs baseline: 1.6125x; 1.0216x over previous
#include <cuda_runtime.h>
#include <cstddef>

// Problem constants
#define B_  4
#define LQ  512
#define LK  2048
#define E_  1024
#define H_  16
#define DH  64
#define F_  4096
#define MQ  (B_*LQ)    // 2048
#define MK  (B_*LK)    // 8192

// ---------------- scratch (device globals; no allocation allowed) ----------
__device__ float g_q[MQ * E_];
__device__ float g_k[MK * E_];
__device__ float g_v[MK * E_];
__device__ float g_vt[MK * E_];
__device__ float g_ctx[MQ * E_];
__device__ float g_attnout[MQ * E_];
__device__ float g_q2[MQ * E_];
__device__ float g_ffn1[MQ * F_];
__device__ float g_ffn2[MQ * E_];
// tf32-rounded copies of external weights
__device__ float r_wq[E_ * E_];
__device__ float r_wk[E_ * E_];
__device__ float r_wv[E_ * E_];
__device__ float r_wo[E_ * E_];
__device__ float r_w1[F_ * E_];
__device__ float r_w2[E_ * F_];
// softmax statistics
__device__ float2 g_sstats[64 * 16 * 512];
__device__ float2 g_rowstats[64 * 512];

// ---------------------------------------------------------------------------
// helpers
// ---------------------------------------------------------------------------
__device__ __forceinline__ unsigned cvt_tf32(float x) {
    unsigned r;
    asm("cvt.rna.tf32.f32 %0, %1;" : "=r"(r) : "f"(x));
    return r;
}
__device__ __forceinline__ float round_tf32(float x) {
    return __uint_as_float(cvt_tf32(x));
}

__device__ __forceinline__ void cp_async16(unsigned saddr, const void* gptr) {
    asm volatile("cp.async.cg.shared.global [%0], [%1], 16;" :: "r"(saddr), "l"(gptr));
}
__device__ __forceinline__ void cp_commit() {
    asm volatile("cp.async.commit_group;");
}
template<int N>
__device__ __forceinline__ void cp_wait() {
    asm volatile("cp.async.wait_group %0;" :: "n"(N));
}

__device__ __forceinline__ void ldsm4(unsigned &r0, unsigned &r1,
                                      unsigned &r2, unsigned &r3, unsigned addr) {
    asm volatile("ldmatrix.sync.aligned.m8n8.x4.shared.b16 {%0,%1,%2,%3}, [%4];"
                 : "=r"(r0), "=r"(r1), "=r"(r2), "=r"(r3) : "r"(addr));
}

__device__ __forceinline__ void mma_tf32(float c[4], const unsigned a[4],
                                         const unsigned b[2]) {
    asm volatile(
        "mma.sync.aligned.m16n8k8.row.col.f32.tf32.tf32.f32 "
        "{%0,%1,%2,%3}, {%4,%5,%6,%7}, {%8,%9}, {%0,%1,%2,%3};"
        : "+f"(c[0]), "+f"(c[1]), "+f"(c[2]), "+f"(c[3])
        : "r"(a[0]), "r"(a[1]), "r"(a[2]), "r"(a[3]), "r"(b[0]), "r"(b[1]));
}

// ---------------------------------------------------------------------------
// tf32 round-copy over a list of segments (front / late instances)
// ---------------------------------------------------------------------------
struct RCArgs {
    const float4* src[5];
    float4*       dst[5];
    int           off[6];   // prefix offsets in float4 units; off[nseg]=total
    int           nseg;
};

__global__ __launch_bounds__(256)
void round_copy_seg(RCArgs rc)
{
    const int total = rc.off[rc.nseg];
    for (int i = blockIdx.x * blockDim.x + threadIdx.x; i < total;
         i += gridDim.x * blockDim.x) {
        int seg = 0;
        #pragma unroll
        for (int s = 1; s < 5; s++) if (s < rc.nseg && i >= rc.off[s]) seg = s;
        int j = i - rc.off[seg];
        float4 v = rc.src[seg][j];
        v.x = round_tf32(v.x); v.y = round_tf32(v.y);
        v.z = round_tf32(v.z); v.w = round_tf32(v.w);
        rc.dst[seg][j] = v;
    }
}

// ---------------------------------------------------------------------------
// Pipelined NT GEMM, tf32 tensor cores, BK=32, 3 stages, ONE sync per k-iter.
// A may be raw fp32 (mma truncates to tf32); B pre-rounded.
// ---------------------------------------------------------------------------
template<int BM, int BN, int WM, int WN, int ROUND>
__global__ __launch_bounds__(256)
void tf32_gemm(const float* __restrict__ A, int lda,
               const float* __restrict__ B, int ldb,
               const float* __restrict__ bias,
               float* __restrict__ C, int ldc,
               int K, float scale, int relu)
{
    constexpr int WARPS_N = BN / WN;
    constexpr int MS = WM / 16, NS = WN / 8;
    constexpr int ASZ = BM * 32;
    constexpr int BSZ = BN * 32;

    extern __shared__ __align__(16) float sm[];
    float* As = sm;
    float* Bs = sm + 3 * ASZ;

    const int bm = blockIdx.y * BM, bn = blockIdx.x * BN;
    const int tid = threadIdx.x, warp = tid >> 5, lane = tid & 31;
    const int wm = (warp / WARPS_N) * WM, wn = (warp % WARPS_N) * WN;

    const unsigned as0 = (unsigned)__cvta_generic_to_shared(As);
    const unsigned bs0 = (unsigned)__cvta_generic_to_shared(Bs);

    const int ld_r = tid >> 3;
    const int ld_c = tid & 7;

    auto load_stage = [&](int buf, int k0) {
        #pragma unroll
        for (int i = 0; i < BM / 32; i++) {
            int r = ld_r + i * 32;
            int ph = ld_c ^ (r & 7);
            cp_async16(as0 + (unsigned)(buf * ASZ + r * 32 + ph * 4) * 4u,
                       A + (size_t)(bm + r) * lda + k0 + ld_c * 4);
        }
        #pragma unroll
        for (int i = 0; i < BN / 32; i++) {
            int r = ld_r + i * 32;
            int ph = ld_c ^ (r & 7);
            cp_async16(bs0 + (unsigned)(buf * BSZ + r * 32 + ph * 4) * 4u,
                       B + (size_t)(bn + r) * ldb + k0 + ld_c * 4);
        }
    };

    float acc[MS][NS][4];
    #pragma unroll
    for (int i = 0; i < MS; i++)
        #pragma unroll
        for (int j = 0; j < NS; j++)
            #pragma unroll
            for (int r = 0; r < 4; r++) acc[i][j][r] = 0.f;

    const int a_row = (lane & 7) + ((lane >> 3) & 1) * 8;
    const int a_ch  = lane >> 4;
    const int b_row = (lane & 7) + ((lane >= 16) ? 8 : 0);
    const int b_ch  = (lane >> 3) & 1;

    const int nk = K >> 5;
    load_stage(0, 0);  cp_commit();
    load_stage(1, 32); cp_commit();

    for (int ks = 0; ks < nk; ks++) {
        cp_wait<1>();
        __syncthreads();
        const int buf = ks % 3;
        if (ks + 2 < nk) load_stage((ks + 2) % 3, (ks + 2) << 5);
        cp_commit();

        #pragma unroll
        for (int k8 = 0; k8 < 4; k8++) {
            const int cb = k8 * 2;
            unsigned a[MS][4], b[NS][2];
            #pragma unroll
            for (int i = 0; i < MS; i++) {
                int r = wm + 16 * i + a_row;
                int ph = (cb + a_ch) ^ (r & 7);
                ldsm4(a[i][0], a[i][1], a[i][2], a[i][3],
                      as0 + (unsigned)(buf * ASZ + r * 32 + ph * 4) * 4u);
            }
            #pragma unroll
            for (int j = 0; j < NS / 2; j++) {
                int r = wn + 16 * j + b_row;
                int ph = (cb + b_ch) ^ (r & 7);
                ldsm4(b[2*j][0], b[2*j][1], b[2*j+1][0], b[2*j+1][1],
                      bs0 + (unsigned)(buf * BSZ + r * 32 + ph * 4) * 4u);
            }
            #pragma unroll
            for (int i = 0; i < MS; i++)
                #pragma unroll
                for (int j = 0; j < NS; j++)
                    mma_tf32(acc[i][j], a[i], b[j]);
        }
    }

    #pragma unroll
    for (int i = 0; i < MS; i++) {
        const int r = bm + wm + 16 * i + (lane >> 2);
        #pragma unroll
        for (int j = 0; j < NS; j++) {
            const int cn = bn + wn + 8 * j + 2 * (lane & 3);
            float bx = 0.f, by = 0.f;
            if (bias) { float2 bb = *(const float2*)&bias[cn]; bx = bb.x; by = bb.y; }
            float v0 = acc[i][j][0] * scale + bx;
            float v1 = acc[i][j][1] * scale + by;
            float v2 = acc[i][j][2] * scale + bx;
            float v3 = acc[i][j][3] * scale + by;
            if (relu) {
                v0 = fmaxf(v0, 0.f); v1 = fmaxf(v1, 0.f);
                v2 = fmaxf(v2, 0.f); v3 = fmaxf(v3, 0.f);
            }
            if (ROUND) {
                v0 = round_tf32(v0); v1 = round_tf32(v1);
                v2 = round_tf32(v2); v3 = round_tf32(v3);
            }
            *(float2*)&C[(size_t)r * ldc + cn]       = make_float2(v0, v1);
            *(float2*)&C[(size_t)(r + 8) * ldc + cn] = make_float2(v2, v3);
        }
    }
}

// ---------------------------------------------------------------------------
// Scores GEMM + per-slab softmax statistics.
// ---------------------------------------------------------------------------
__global__ __launch_bounds__(256)
void scores_stats(const float* __restrict__ q, const float* __restrict__ k,
                  float* __restrict__ attn, float2* __restrict__ sstats)
{
    constexpr int BM = 128, BN = 128, WM = 64, WN = 32;
    constexpr int WARPS_N = BN / WN;
    constexpr int MS = WM / 16, NS = WN / 8;
    constexpr int ASZ = BM * 16, BSZ = BN * 16;

    __shared__ __align__(16) float As[3 * ASZ];
    __shared__ __align__(16) float Bs[3 * BSZ];

    const int z = blockIdx.z;
    const int b = z >> 4, h = z & 15;
    const float* A = q + (size_t)b * LQ * E_ + h * DH;
    const float* B = k + (size_t)b * LK * E_ + h * DH;
    float* C = attn + (size_t)z * LQ * LK;

    const int bm = blockIdx.y * BM, bn = blockIdx.x * BN;
    const int tid = threadIdx.x, warp = tid >> 5, lane = tid & 31;
    const int wm = (warp / WARPS_N) * WM, wn = (warp % WARPS_N) * WN;

    const unsigned as0 = (unsigned)__cvta_generic_to_shared(As);
    const unsigned bs0 = (unsigned)__cvta_generic_to_shared(Bs);
    const int ld_r = tid >> 2, ld_c = tid & 3;

    auto load_stage = [&](int buf, int k0) {
        #pragma unroll
        for (int i = 0; i < 2; i++) {
            int r = ld_r + i * 64;
            int ph = ld_c ^ ((r >> 1) & 3);
            cp_async16(as0 + (unsigned)(buf * ASZ + r * 16 + ph * 4) * 4u,
                       A + (size_t)(bm + r) * E_ + k0 + ld_c * 4);
            cp_async16(bs0 + (unsigned)(buf * BSZ + r * 16 + ph * 4) * 4u,
                       B + (size_t)(bn + r) * E_ + k0 + ld_c * 4);
        }
    };

    float acc[MS][NS][4];
    #pragma unroll
    for (int i = 0; i < MS; i++)
        #pragma unroll
        for (int j = 0; j < NS; j++)
            #pragma unroll
            for (int r = 0; r < 4; r++) acc[i][j][r] = 0.f;

    const int a_row = (lane & 7) + ((lane >> 3) & 1) * 8;
    const int a_ch  = lane >> 4;
    const int b_row = (lane & 7) + ((lane >= 16) ? 8 : 0);
    const int b_ch  = (lane >> 3) & 1;

    const int nk = DH >> 4;
    load_stage(0, 0);  cp_commit();
    load_stage(1, 16); cp_commit();

    for (int ks = 0; ks < nk; ks++) {
        cp_wait<1>();
        __syncthreads();
        const int buf = ks % 3;
        if (ks + 2 < nk) load_stage((ks + 2) % 3, (ks + 2) << 4);
        cp_commit();

        #pragma unroll
        for (int k8 = 0; k8 < 2; k8++) {
            const int cb = k8 * 2;
            unsigned a[MS][4], bfr[NS][2];
            #pragma unroll
            for (int i = 0; i < MS; i++) {
                int r = wm + 16 * i + a_row;
                int ph = (cb + a_ch) ^ ((r >> 1) & 3);
                ldsm4(a[i][0], a[i][1], a[i][2], a[i][3],
                      as0 + (unsigned)(buf * ASZ + r * 16 + ph * 4) * 4u);
            }
            #pragma unroll
            for (int j = 0; j < NS / 2; j++) {
                int r = wn + 16 * j + b_row;
                int ph = (cb + b_ch) ^ ((r >> 1) & 3);
                ldsm4(bfr[2*j][0], bfr[2*j][1], bfr[2*j+1][0], bfr[2*j+1][1],
                      bs0 + (unsigned)(buf * BSZ + r * 16 + ph * 4) * 4u);
            }
            #pragma unroll
            for (int i = 0; i < MS; i++)
                #pragma unroll
                for (int j = 0; j < NS; j++)
                    mma_tf32(acc[i][j], a[i], bfr[j]);
        }
        __syncthreads();
    }

    #pragma unroll
    for (int i = 0; i < MS; i++)
        #pragma unroll
        for (int j = 0; j < NS; j++)
            #pragma unroll
            for (int r = 0; r < 4; r++) acc[i][j][r] *= 0.125f;

    #pragma unroll
    for (int i = 0; i < MS; i++) {
        const int r = bm + wm + 16 * i + (lane >> 2);
        #pragma unroll
        for (int j = 0; j < NS; j++) {
            const int cn = bn + wn + 8 * j + 2 * (lane & 3);
            *(float2*)&C[(size_t)r * LK + cn]       = make_float2(acc[i][j][0], acc[i][j][1]);
            *(float2*)&C[(size_t)(r + 8) * LK + cn] = make_float2(acc[i][j][2], acc[i][j][3]);
        }
    }

    float* sm_m = As;
    float* sm_s = As + 512;
    __syncthreads();

    const int ng = warp % WARPS_N;
    #pragma unroll
    for (int i = 0; i < MS; i++) {
        #pragma unroll
        for (int hh = 0; hh < 2; hh++) {
            float v[8];
            #pragma unroll
            for (int j = 0; j < NS; j++) {
                v[2*j]   = acc[i][j][2*hh];
                v[2*j+1] = acc[i][j][2*hh+1];
            }
            float m = v[0];
            #pragma unroll
            for (int e = 1; e < 8; e++) m = fmaxf(m, v[e]);
            m = fmaxf(m, __shfl_xor_sync(0xffffffffu, m, 1));
            m = fmaxf(m, __shfl_xor_sync(0xffffffffu, m, 2));
            float se = 0.f;
            #pragma unroll
            for (int e = 0; e < 8; e++) se += __expf(v[e] - m);
            se += __shfl_xor_sync(0xffffffffu, se, 1);
            se += __shfl_xor_sync(0xffffffffu, se, 2);
            if ((lane & 3) == 0) {
                int row = wm + 16 * i + (lane >> 2) + 8 * hh;
                sm_m[ng * 128 + row] = m;
                sm_s[ng * 128 + row] = se;
            }
        }
    }
    __syncthreads();

    if (tid < 128) {
        float m0 = sm_m[tid], m1 = sm_m[128 + tid];
        float m2 = sm_m[256 + tid], m3 = sm_m[384 + tid];
        float M = fmaxf(fmaxf(m0, m1), fmaxf(m2, m3));
        float S = sm_s[tid]       * __expf(m0 - M)
                + sm_s[128 + tid] * __expf(m1 - M)
                + sm_s[256 + tid] * __expf(m2 - M)
                + sm_s[384 + tid] * __expf(m3 - M);
        sstats[((size_t)z * 16 + blockIdx.x) * LQ + bm + tid] = make_float2(M, S);
    }
}

// ---------------------------------------------------------------------------
// Combine 16 slab stats per row -> (M, 1/S)
// ---------------------------------------------------------------------------
__global__ __launch_bounds__(256)
void rowcombine(const float2* __restrict__ sstats, float2* __restrict__ rowstats)
{
    int idx = blockIdx.x * 256 + threadIdx.x;
    int z = idx >> 9, row = idx & 511;
    const float2* p = sstats + (size_t)z * 16 * LQ + row;
    float2 v[16];
    #pragma unroll
    for (int s = 0; s < 16; s++) v[s] = p[(size_t)s * LQ];
    float M = v[0].x;
    #pragma unroll
    for (int s = 1; s < 16; s++) M = fmaxf(M, v[s].x);
    float S = 0.f;
    #pragma unroll
    for (int s = 0; s < 16; s++) S += v[s].y * __expf(v[s].x - M);
    rowstats[idx] = make_float2(M, 1.0f / S);
}

// ---------------------------------------------------------------------------
// Fused normalize + ctx GEMM (S prefetch 2 deep).
// ---------------------------------------------------------------------------
__global__ __launch_bounds__(256)
void ctx_fused(const float2* __restrict__ rowstats,
               float* __restrict__ attn,
               const float* __restrict__ vt,
               float* __restrict__ ctx)
{
    constexpr int BM = 128, BN = 64, WM = 32, WN = 32;
    constexpr int WARPS_N = BN / WN;
    constexpr int MS = WM / 16, NS = WN / 8;
    constexpr int ASZ = BM * 16, BSZ = BN * 16;

    __shared__ __align__(16) float As[2 * ASZ];
    __shared__ __align__(16) float Bs[3 * BSZ];
    __shared__ float2 rs[BM];

    const int z = blockIdx.y;
    const int b = z >> 4, h = z & 15;
    const int bm = blockIdx.x * BM;
    float* Sp = attn + ((size_t)z * LQ + bm) * LK;
    const float* Vb = vt + ((size_t)b * E_ + h * DH) * LK;
    float* Cp = ctx + ((size_t)b * LQ + bm) * E_ + h * DH;

    const int tid = threadIdx.x, warp = tid >> 5, lane = tid & 31;
    const int wm = (warp / WARPS_N) * WM, wn = (warp % WARPS_N) * WN;

    if (tid < BM) rs[tid] = rowstats[(size_t)z * LQ + bm + tid];

    const unsigned as0 = (unsigned)__cvta_generic_to_shared(As);
    const unsigned bs0 = (unsigned)__cvta_generic_to_shared(Bs);
    const int ld_r = tid >> 2, ld_c = tid & 3;
    const int ph0 = ld_c ^ ((ld_r >> 1) & 3);
    const int ph1 = ld_c ^ (((ld_r + 64) >> 1) & 3);

    auto loadB = [&](int buf, int k0) {
        int ph = ld_c ^ ((ld_r >> 1) & 3);
        cp_async16(bs0 + (unsigned)(buf * BSZ + ld_r * 16 + ph * 4) * 4u,
                   Vb + (size_t)ld_r * LK + k0 + ld_c * 4);
    };

    loadB(0, 0);  cp_commit();
    loadB(1, 16); cp_commit();

    const float* Sr0 = Sp + (size_t)ld_r * LK + ld_c * 4;
    const float* Sr1 = Sp + (size_t)(ld_r + 64) * LK + ld_c * 4;
    float4 s0 = *(const float4*)Sr0;
    float4 s1 = *(const float4*)Sr1;
    float4 n0 = *(const float4*)(Sr0 + 16);
    float4 n1 = *(const float4*)(Sr1 + 16);

    __syncthreads();
    const float2 st0 = rs[ld_r];
    const float2 st1 = rs[ld_r + 64];

    float acc[MS][NS][4];
    #pragma unroll
    for (int i = 0; i < MS; i++)
        #pragma unroll
        for (int j = 0; j < NS; j++)
            #pragma unroll
            for (int r = 0; r < 4; r++) acc[i][j][r] = 0.f;

    const int a_row = (lane & 7) + ((lane >> 3) & 1) * 8;
    const int a_ch  = lane >> 4;
    const int b_row = (lane & 7) + ((lane >= 16) ? 8 : 0);
    const int b_ch  = (lane >> 3) & 1;

    const int nk = LK >> 4;
    #pragma unroll 2
    for (int t = 0; t < nk; t++) {
        const int abuf = t & 1;
        float4 p0, p1;
        p0.x = round_tf32(__expf(s0.x - st0.x) * st0.y);
        p0.y = round_tf32(__expf(s0.y - st0.x) * st0.y);
        p0.z = round_tf32(__expf(s0.z - st0.x) * st0.y);
        p0.w = round_tf32(__expf(s0.w - st0.x) * st0.y);
        p1.x = round_tf32(__expf(s1.x - st1.x) * st1.y);
        p1.y = round_tf32(__expf(s1.y - st1.x) * st1.y);
        p1.z = round_tf32(__expf(s1.z - st1.x) * st1.y);
        p1.w = round_tf32(__expf(s1.w - st1.x) * st1.y);
        *(float4*)&As[abuf * ASZ + ld_r * 16 + ph0 * 4]        = p0;
        *(float4*)&As[abuf * ASZ + (ld_r + 64) * 16 + ph1 * 4] = p1;
        *(float4*)(Sr0 + (size_t)t * 16) = p0;
        *(float4*)(Sr1 + (size_t)t * 16) = p1;
        s0 = n0; s1 = n1;
        if (t + 2 < nk) {
            n0 = *(const float4*)(Sr0 + (size_t)(t + 2) * 16);
            n1 = *(const float4*)(Sr1 + (size_t)(t + 2) * 16);
        }
        cp_wait<1>();
        __syncthreads();
        if (t + 2 < nk) loadB((t + 2) % 3, (t + 2) * 16);
        cp_commit();

        const int bbuf = t % 3;
        #pragma unroll
        for (int k8 = 0; k8 < 2; k8++) {
            const int cb = k8 * 2;
            unsigned a[MS][4], bfr[NS][2];
            #pragma unroll
            for (int i = 0; i < MS; i++) {
                int r = wm + 16 * i + a_row;
                int ph = (cb + a_ch) ^ ((r >> 1) & 3);
                ldsm4(a[i][0], a[i][1], a[i][2], a[i][3],
                      as0 + (unsigned)(abuf * ASZ + r * 16 + ph * 4) * 4u);
            }
            #pragma unroll
            for (int j = 0; j < NS / 2; j++) {
                int r = wn + 16 * j + b_row;
                int ph = (cb + b_ch) ^ ((r >> 1) & 3);
                ldsm4(bfr[2*j][0], bfr[2*j][1], bfr[2*j+1][0], bfr[2*j+1][1],
                      bs0 + (unsigned)(bbuf * BSZ + r * 16 + ph * 4) * 4u);
            }
            #pragma unroll
            for (int i = 0; i < MS; i++)
                #pragma unroll
                for (int j = 0; j < NS; j++)
                    mma_tf32(acc[i][j], a[i], bfr[j]);
        }
    }

    #pragma unroll
    for (int i = 0; i < MS; i++) {
        const int r = wm + 16 * i + (lane >> 2);
        #pragma unroll
        for (int j = 0; j < NS; j++) {
            const int cn = wn + 8 * j + 2 * (lane & 3);
            float v0 = round_tf32(acc[i][j][0]);
            float v1 = round_tf32(acc[i][j][1]);
            float v2 = round_tf32(acc[i][j][2]);
            float v3 = round_tf32(acc[i][j][3]);
            *(float2*)&Cp[(size_t)r * E_ + cn]       = make_float2(v0, v1);
            *(float2*)&Cp[(size_t)(r + 8) * E_ + cn] = make_float2(v2, v3);
        }
    }
}

// ---------------------------------------------------------------------------
// Per-batch transpose of V (float4 vectorized): vt[b][n][k] = v[b][k][n]
// ---------------------------------------------------------------------------
__global__ __launch_bounds__(256)
void transpose_v(const float* __restrict__ v, float* __restrict__ vt)
{
    __shared__ float t[32][129];
    const int b  = blockIdx.z;
    const int k0 = blockIdx.x * 32;
    const int n0 = blockIdx.y * 128;
    const int tx = threadIdx.x;
    const int ty = threadIdx.y;

    #pragma unroll
    for (int i = ty; i < 32; i += 8) {
        float4 val = *(const float4*)&v[((size_t)b * LK + k0 + i) * E_ + n0 + tx * 4];
        t[i][tx * 4 + 0] = val.x;
        t[i][tx * 4 + 1] = val.y;
        t[i][tx * 4 + 2] = val.z;
        t[i][tx * 4 + 3] = val.w;
    }
    __syncthreads();

    #pragma unroll
    for (int i = ty; i < 128; i += 8)
        vt[((size_t)b * E_ + n0 + i) * LK + k0 + tx] = t[tx][i];
}

// ---------------------------------------------------------------------------
// out = LayerNorm(a + b) * g + beta
// ---------------------------------------------------------------------------
template<int ROUND>
__global__ __launch_bounds__(256)
void ln_residual(const float* __restrict__ A, const float* __restrict__ Bx,
                 const float* __restrict__ g, const float* __restrict__ be,
                 float* __restrict__ out)
{
    const size_t row = blockIdx.x;
    const int t = threadIdx.x;

    float4 a = ((const float4*)(A  + row * E_))[t];
    float4 b = ((const float4*)(Bx + row * E_))[t];
    float4 x = make_float4(a.x + b.x, a.y + b.y, a.z + b.z, a.w + b.w);

    float s  = x.x + x.y + x.z + x.w;
    float ss = x.x*x.x + x.y*x.y + x.z*x.z + x.w*x.w;

    __shared__ float rs_[8], rss[8];
    #pragma unroll
    for (int o = 16; o > 0; o >>= 1) {
        s  += __shfl_xor_sync(0xffffffffu, s,  o);
        ss += __shfl_xor_sync(0xffffffffu, ss, o);
    }
    if ((t & 31) == 0) { rs_[t >> 5] = s; rss[t >> 5] = ss; }
    __syncthreads();
    s = 0.f; ss = 0.f;
    #pragma unroll
    for (int i = 0; i < 8; i++) { s += rs_[i]; ss += rss[i]; }

    const float mean = s * (1.0f / E_);
    const float var  = ss * (1.0f / E_) - mean * mean;
    const float inv  = rsqrtf(var + 1e-5f);

    float4 gg = ((const float4*)g)[t];
    float4 bb = ((const float4*)be)[t];
    float4 o;
    o.x = (x.x - mean) * inv * gg.x + bb.x;
    o.y = (x.y - mean) * inv * gg.y + bb.y;
    o.z = (x.z - mean) * inv * gg.z + bb.z;
    o.w = (x.w - mean) * inv * gg.w + bb.w;
    if (ROUND) {
        o.x = round_tf32(o.x); o.y = round_tf32(o.y);
        o.z = round_tf32(o.z); o.w = round_tf32(o.w);
    }
    ((float4*)(out + row * E_))[t] = o;
}

// ---------------------------------------------------------------------------
extern "C" void kernel_launch(void* const* d_in, const int* in_sizes, int n_in,
                              void* d_out, int out_size)
{
    const float* query = (const float*)d_in[0];
    const float* keyv  = (const float*)d_in[1];
    const float* wq = (const float*)d_in[2];
    const float* wk = (const float*)d_in[3];
    const float* wv = (const float*)d_in[4];
    const float* bq = (const float*)d_in[5];
    const float* bk = (const float*)d_in[6];
    const float* bv = (const float*)d_in[7];
    const float* wo = (const float*)d_in[8];
    const float* bo = (const float*)d_in[9];
    const float* g1 = (const float*)d_in[10];
    const float* be1 = (const float*)d_in[11];
    const float* w1 = (const float*)d_in[12];
    const float* b1 = (const float*)d_in[13];
    const float* w2 = (const float*)d_in[14];
    const float* b2 = (const float*)d_in[15];
    const float* g2 = (const float*)d_in[16];
    const float* be2 = (const float*)d_in[17];

    float* out = (float*)d_out;
    float* q3_out = out;
    float* attn   = out + (size_t)MQ * E_;

    float *gq, *gk, *gv, *gvt, *gctx, *gao, *gq2, *gf1, *gf2;
    float *rwq, *rwk, *rwv, *rwo, *rw1, *rw2;
    float2 *sst, *rst;
    cudaGetSymbolAddress((void**)&gq,  g_q);
    cudaGetSymbolAddress((void**)&gk,  g_k);
    cudaGetSymbolAddress((void**)&gv,  g_v);
    cudaGetSymbolAddress((void**)&gvt, g_vt);
    cudaGetSymbolAddress((void**)&gctx, g_ctx);
    cudaGetSymbolAddress((void**)&gao, g_attnout);
    cudaGetSymbolAddress((void**)&gq2, g_q2);
    cudaGetSymbolAddress((void**)&gf1, g_ffn1);
    cudaGetSymbolAddress((void**)&gf2, g_ffn2);
    cudaGetSymbolAddress((void**)&rwq, r_wq);
    cudaGetSymbolAddress((void**)&rwk, r_wk);
    cudaGetSymbolAddress((void**)&rwv, r_wv);
    cudaGetSymbolAddress((void**)&rwo, r_wo);
    cudaGetSymbolAddress((void**)&rw1, r_w1);
    cudaGetSymbolAddress((void**)&rw2, r_w2);
    cudaGetSymbolAddress((void**)&sst, g_sstats);
    cudaGetSymbolAddress((void**)&rst, g_rowstats);

    // one-time setup
    static cudaStream_t s1 = nullptr, s2 = nullptr;
    static cudaEvent_t e0, e1, e2, e3;
    if (!s1) {
        cudaFuncSetAttribute(tf32_gemm<128,128,64,32,0>,
                             cudaFuncAttributeMaxDynamicSharedMemorySize, 98304);
        cudaFuncSetAttribute(tf32_gemm<128,128,64,32,1>,
                             cudaFuncAttributeMaxDynamicSharedMemorySize, 98304);
        cudaFuncSetAttribute(tf32_gemm<128,64,32,32,0>,
                             cudaFuncAttributeMaxDynamicSharedMemorySize, 73728);
        cudaFuncSetAttribute(tf32_gemm<128,64,32,32,1>,
                             cudaFuncAttributeMaxDynamicSharedMemorySize, 73728);
        cudaStreamCreateWithFlags(&s1, cudaStreamNonBlocking);
        cudaStreamCreateWithFlags(&s2, cudaStreamNonBlocking);
        cudaEventCreateWithFlags(&e0, cudaEventDisableTiming);
        cudaEventCreateWithFlags(&e1, cudaEventDisableTiming);
        cudaEventCreateWithFlags(&e2, cudaEventDisableTiming);
        cudaEventCreateWithFlags(&e3, cudaEventDisableTiming);
    }
    const int GS128 = 98304;
    const int GS64  = 73728;

    // ---- front prepass: only QKV WEIGHTS (24 MB); activations fed raw ----
    {
        RCArgs rc;
        rc.src[0] = (const float4*)wq; rc.dst[0] = (float4*)rwq;
        rc.src[1] = (const float4*)wk; rc.dst[1] = (float4*)rwk;
        rc.src[2] = (const float4*)wv; rc.dst[2] = (float4*)rwv;
        rc.off[0] = 0;
        rc.off[1] = E_*E_/4;
        rc.off[2] = rc.off[1] + E_*E_/4;
        rc.off[3] = rc.off[2] + E_*E_/4;
        rc.off[4] = rc.off[3];
        rc.off[5] = rc.off[3];
        rc.nseg = 3;
        round_copy_seg<<<1024, 256>>>(rc);
    }

    // fork: default = K proj, s1 = V proj + transpose + late prepass, s2 = Q proj
    cudaEventRecord(e0, 0);
    cudaStreamWaitEvent(s1, e0, 0);
    cudaStreamWaitEvent(s2, e0, 0);

    tf32_gemm<128,128,64,32,1><<<dim3(E_/128, MK/128), 256, GS128>>>(
        keyv, E_,  rwk, E_,  bk,  gk, E_,  E_, 1.f, 0);

    tf32_gemm<128,128,64,32,1><<<dim3(E_/128, MK/128), 256, GS128, s1>>>(
        keyv, E_,  rwv, E_,  bv,  gv, E_,  E_, 1.f, 0);
    transpose_v<<<dim3(LK/32, E_/128, B_), dim3(32, 8), 0, s1>>>(gv, gvt);
    cudaEventRecord(e1, s1);

    // late prepass (wo, w1, w2 = 208 MB) on s1 — hidden under scores/ctx
    {
        RCArgs rc;
        rc.src[0] = (const float4*)wo; rc.dst[0] = (float4*)rwo;
        rc.src[1] = (const float4*)w1; rc.dst[1] = (float4*)rw1;
        rc.src[2] = (const float4*)w2; rc.dst[2] = (float4*)rw2;
        rc.off[0] = 0;
        rc.off[1] = E_*E_/4;
        rc.off[2] = rc.off[1] + F_*E_/4;
        rc.off[3] = rc.off[2] + E_*F_/4;
        rc.off[4] = rc.off[3];
        rc.off[5] = rc.off[3];
        rc.nseg = 3;
        round_copy_seg<<<1024, 256, 0, s1>>>(rc);
    }
    cudaEventRecord(e3, s1);

    tf32_gemm<128,64,32,32,1><<<dim3(E_/64, MQ/128), 256, GS64, s2>>>(
        query, E_,  rwq, E_,  bq,  gq, E_,  E_, 1.f, 0);
    cudaEventRecord(e2, s2);

    // join: scores needs Q (s2) and K (default)
    cudaStreamWaitEvent(0, e2, 0);
    scores_stats<<<dim3(LK/128, LQ/128, B_*H_), 256>>>(gq, gk, attn, sst);
    rowcombine<<<(B_*H_*LQ)/256, 256>>>(sst, rst);

    // ctx needs transpose (s1: e1)
    cudaStreamWaitEvent(0, e1, 0);
    ctx_fused<<<dim3(LQ/128, B_*H_), 256>>>(rst, attn, gvt, gctx);

    // ---- output projection + LN1 (needs late weights: e3) ----
    cudaStreamWaitEvent(0, e3, 0);
    tf32_gemm<128,64,32,32,0><<<dim3(E_/64, MQ/128), 256, GS64>>>(
        gctx, E_,  rwo, E_,  bo,  gao, E_,  E_, 1.f, 0);
    ln_residual<1><<<MQ, 256>>>(query, gao, g1, be1, gq2);

    // ---- FFN + LN2 ----
    tf32_gemm<128,128,64,32,1><<<dim3(F_/128, MQ/128), 256, GS128>>>(
        gq2, E_,  rw1, E_,  b1,  gf1, F_,  E_, 1.f, 1);
    tf32_gemm<128,64,32,32,0><<<dim3(E_/64, MQ/128), 256, GS64>>>(
        gf1, F_,  rw2, F_,  b2,  gf2, E_,  F_, 1.f, 0);
    ln_residual<0><<<MQ, 256>>>(gq2, gf2, g2, be2, q3_out);
}

// round 16
// speedup vs baseline: 1.6381x; 1.0159x over previous
#include <cuda_runtime.h>
#include <cstddef>

// Problem constants
#define B_  4
#define LQ  512
#define LK  2048
#define E_  1024
#define H_  16
#define DH  64
#define F_  4096
#define MQ  (B_*LQ)    // 2048
#define MK  (B_*LK)    // 8192

// ---------------- scratch (device globals; no allocation allowed) ----------
__device__ float g_q[MQ * E_];
__device__ float g_k[MK * E_];
__device__ float g_v[MK * E_];
__device__ float g_vt[MK * E_];
__device__ float g_ctx[MQ * E_];
__device__ float g_attnout[MQ * E_];
__device__ float g_q2[MQ * E_];
__device__ float g_ffn1[MQ * F_];
__device__ float g_ffn2[MQ * E_];
// tf32-rounded copies of QKV weights (late weights fed raw)
__device__ float r_wq[E_ * E_];
__device__ float r_wk[E_ * E_];
__device__ float r_wv[E_ * E_];
// softmax statistics
__device__ float2 g_sstats[64 * 16 * 512];
__device__ float2 g_rowstats[64 * 512];

// ---------------------------------------------------------------------------
// helpers
// ---------------------------------------------------------------------------
__device__ __forceinline__ unsigned cvt_tf32(float x) {
    unsigned r;
    asm("cvt.rna.tf32.f32 %0, %1;" : "=r"(r) : "f"(x));
    return r;
}
__device__ __forceinline__ float round_tf32(float x) {
    return __uint_as_float(cvt_tf32(x));
}

__device__ __forceinline__ void cp_async16(unsigned saddr, const void* gptr) {
    asm volatile("cp.async.cg.shared.global [%0], [%1], 16;" :: "r"(saddr), "l"(gptr));
}
__device__ __forceinline__ void cp_commit() {
    asm volatile("cp.async.commit_group;");
}
template<int N>
__device__ __forceinline__ void cp_wait() {
    asm volatile("cp.async.wait_group %0;" :: "n"(N));
}

__device__ __forceinline__ void ldsm4(unsigned &r0, unsigned &r1,
                                      unsigned &r2, unsigned &r3, unsigned addr) {
    asm volatile("ldmatrix.sync.aligned.m8n8.x4.shared.b16 {%0,%1,%2,%3}, [%4];"
                 : "=r"(r0), "=r"(r1), "=r"(r2), "=r"(r3) : "r"(addr));
}

__device__ __forceinline__ void mma_tf32(float c[4], const unsigned a[4],
                                         const unsigned b[2]) {
    asm volatile(
        "mma.sync.aligned.m16n8k8.row.col.f32.tf32.tf32.f32 "
        "{%0,%1,%2,%3}, {%4,%5,%6,%7}, {%8,%9}, {%0,%1,%2,%3};"
        : "+f"(c[0]), "+f"(c[1]), "+f"(c[2]), "+f"(c[3])
        : "r"(a[0]), "r"(a[1]), "r"(a[2]), "r"(a[3]), "r"(b[0]), "r"(b[1]));
}

// ---------------------------------------------------------------------------
// tf32 round-copy over a list of segments
// ---------------------------------------------------------------------------
struct RCArgs {
    const float4* src[5];
    float4*       dst[5];
    int           off[6];
    int           nseg;
};

__global__ __launch_bounds__(256)
void round_copy_seg(RCArgs rc)
{
    const int total = rc.off[rc.nseg];
    for (int i = blockIdx.x * blockDim.x + threadIdx.x; i < total;
         i += gridDim.x * blockDim.x) {
        int seg = 0;
        #pragma unroll
        for (int s = 1; s < 5; s++) if (s < rc.nseg && i >= rc.off[s]) seg = s;
        int j = i - rc.off[seg];
        float4 v = rc.src[seg][j];
        v.x = round_tf32(v.x); v.y = round_tf32(v.y);
        v.z = round_tf32(v.z); v.w = round_tf32(v.w);
        rc.dst[seg][j] = v;
    }
}

// ---------------------------------------------------------------------------
// Pipelined NT GEMM, tf32 tensor cores, BK=32, 3 stages, ONE sync per k-iter.
// A and/or B may be raw fp32 (mma truncates to tf32).
// ---------------------------------------------------------------------------
template<int BM, int BN, int WM, int WN, int ROUND>
__global__ __launch_bounds__(256)
void tf32_gemm(const float* __restrict__ A, int lda,
               const float* __restrict__ B, int ldb,
               const float* __restrict__ bias,
               float* __restrict__ C, int ldc,
               int K, float scale, int relu)
{
    constexpr int WARPS_N = BN / WN;
    constexpr int MS = WM / 16, NS = WN / 8;
    constexpr int ASZ = BM * 32;
    constexpr int BSZ = BN * 32;

    extern __shared__ __align__(16) float sm[];
    float* As = sm;
    float* Bs = sm + 3 * ASZ;

    const int bm = blockIdx.y * BM, bn = blockIdx.x * BN;
    const int tid = threadIdx.x, warp = tid >> 5, lane = tid & 31;
    const int wm = (warp / WARPS_N) * WM, wn = (warp % WARPS_N) * WN;

    const unsigned as0 = (unsigned)__cvta_generic_to_shared(As);
    const unsigned bs0 = (unsigned)__cvta_generic_to_shared(Bs);

    const int ld_r = tid >> 3;
    const int ld_c = tid & 7;

    auto load_stage = [&](int buf, int k0) {
        #pragma unroll
        for (int i = 0; i < BM / 32; i++) {
            int r = ld_r + i * 32;
            int ph = ld_c ^ (r & 7);
            cp_async16(as0 + (unsigned)(buf * ASZ + r * 32 + ph * 4) * 4u,
                       A + (size_t)(bm + r) * lda + k0 + ld_c * 4);
        }
        #pragma unroll
        for (int i = 0; i < BN / 32; i++) {
            int r = ld_r + i * 32;
            int ph = ld_c ^ (r & 7);
            cp_async16(bs0 + (unsigned)(buf * BSZ + r * 32 + ph * 4) * 4u,
                       B + (size_t)(bn + r) * ldb + k0 + ld_c * 4);
        }
    };

    float acc[MS][NS][4];
    #pragma unroll
    for (int i = 0; i < MS; i++)
        #pragma unroll
        for (int j = 0; j < NS; j++)
            #pragma unroll
            for (int r = 0; r < 4; r++) acc[i][j][r] = 0.f;

    const int a_row = (lane & 7) + ((lane >> 3) & 1) * 8;
    const int a_ch  = lane >> 4;
    const int b_row = (lane & 7) + ((lane >= 16) ? 8 : 0);
    const int b_ch  = (lane >> 3) & 1;

    const int nk = K >> 5;
    load_stage(0, 0);  cp_commit();
    load_stage(1, 32); cp_commit();

    for (int ks = 0; ks < nk; ks++) {
        cp_wait<1>();
        __syncthreads();
        const int buf = ks % 3;
        if (ks + 2 < nk) load_stage((ks + 2) % 3, (ks + 2) << 5);
        cp_commit();

        #pragma unroll
        for (int k8 = 0; k8 < 4; k8++) {
            const int cb = k8 * 2;
            unsigned a[MS][4], b[NS][2];
            #pragma unroll
            for (int i = 0; i < MS; i++) {
                int r = wm + 16 * i + a_row;
                int ph = (cb + a_ch) ^ (r & 7);
                ldsm4(a[i][0], a[i][1], a[i][2], a[i][3],
                      as0 + (unsigned)(buf * ASZ + r * 32 + ph * 4) * 4u);
            }
            #pragma unroll
            for (int j = 0; j < NS / 2; j++) {
                int r = wn + 16 * j + b_row;
                int ph = (cb + b_ch) ^ (r & 7);
                ldsm4(b[2*j][0], b[2*j][1], b[2*j+1][0], b[2*j+1][1],
                      bs0 + (unsigned)(buf * BSZ + r * 32 + ph * 4) * 4u);
            }
            #pragma unroll
            for (int i = 0; i < MS; i++)
                #pragma unroll
                for (int j = 0; j < NS; j++)
                    mma_tf32(acc[i][j], a[i], b[j]);
        }
    }

    #pragma unroll
    for (int i = 0; i < MS; i++) {
        const int r = bm + wm + 16 * i + (lane >> 2);
        #pragma unroll
        for (int j = 0; j < NS; j++) {
            const int cn = bn + wn + 8 * j + 2 * (lane & 3);
            float bx = 0.f, by = 0.f;
            if (bias) { float2 bb = *(const float2*)&bias[cn]; bx = bb.x; by = bb.y; }
            float v0 = acc[i][j][0] * scale + bx;
            float v1 = acc[i][j][1] * scale + by;
            float v2 = acc[i][j][2] * scale + bx;
            float v3 = acc[i][j][3] * scale + by;
            if (relu) {
                v0 = fmaxf(v0, 0.f); v1 = fmaxf(v1, 0.f);
                v2 = fmaxf(v2, 0.f); v3 = fmaxf(v3, 0.f);
            }
            if (ROUND) {
                v0 = round_tf32(v0); v1 = round_tf32(v1);
                v2 = round_tf32(v2); v3 = round_tf32(v3);
            }
            *(float2*)&C[(size_t)r * ldc + cn]       = make_float2(v0, v1);
            *(float2*)&C[(size_t)(r + 8) * ldc + cn] = make_float2(v2, v3);
        }
    }
}

// ---------------------------------------------------------------------------
// Scores GEMM + per-slab softmax statistics.
// ---------------------------------------------------------------------------
__global__ __launch_bounds__(256)
void scores_stats(const float* __restrict__ q, const float* __restrict__ k,
                  float* __restrict__ attn, float2* __restrict__ sstats)
{
    constexpr int BM = 128, BN = 128, WM = 64, WN = 32;
    constexpr int WARPS_N = BN / WN;
    constexpr int MS = WM / 16, NS = WN / 8;
    constexpr int ASZ = BM * 16, BSZ = BN * 16;

    __shared__ __align__(16) float As[3 * ASZ];
    __shared__ __align__(16) float Bs[3 * BSZ];

    const int z = blockIdx.z;
    const int b = z >> 4, h = z & 15;
    const float* A = q + (size_t)b * LQ * E_ + h * DH;
    const float* B = k + (size_t)b * LK * E_ + h * DH;
    float* C = attn + (size_t)z * LQ * LK;

    const int bm = blockIdx.y * BM, bn = blockIdx.x * BN;
    const int tid = threadIdx.x, warp = tid >> 5, lane = tid & 31;
    const int wm = (warp / WARPS_N) * WM, wn = (warp % WARPS_N) * WN;

    const unsigned as0 = (unsigned)__cvta_generic_to_shared(As);
    const unsigned bs0 = (unsigned)__cvta_generic_to_shared(Bs);
    const int ld_r = tid >> 2, ld_c = tid & 3;

    auto load_stage = [&](int buf, int k0) {
        #pragma unroll
        for (int i = 0; i < 2; i++) {
            int r = ld_r + i * 64;
            int ph = ld_c ^ ((r >> 1) & 3);
            cp_async16(as0 + (unsigned)(buf * ASZ + r * 16 + ph * 4) * 4u,
                       A + (size_t)(bm + r) * E_ + k0 + ld_c * 4);
            cp_async16(bs0 + (unsigned)(buf * BSZ + r * 16 + ph * 4) * 4u,
                       B + (size_t)(bn + r) * E_ + k0 + ld_c * 4);
        }
    };

    float acc[MS][NS][4];
    #pragma unroll
    for (int i = 0; i < MS; i++)
        #pragma unroll
        for (int j = 0; j < NS; j++)
            #pragma unroll
            for (int r = 0; r < 4; r++) acc[i][j][r] = 0.f;

    const int a_row = (lane & 7) + ((lane >> 3) & 1) * 8;
    const int a_ch  = lane >> 4;
    const int b_row = (lane & 7) + ((lane >= 16) ? 8 : 0);
    const int b_ch  = (lane >> 3) & 1;

    const int nk = DH >> 4;
    load_stage(0, 0);  cp_commit();
    load_stage(1, 16); cp_commit();

    for (int ks = 0; ks < nk; ks++) {
        cp_wait<1>();
        __syncthreads();
        const int buf = ks % 3;
        if (ks + 2 < nk) load_stage((ks + 2) % 3, (ks + 2) << 4);
        cp_commit();

        #pragma unroll
        for (int k8 = 0; k8 < 2; k8++) {
            const int cb = k8 * 2;
            unsigned a[MS][4], bfr[NS][2];
            #pragma unroll
            for (int i = 0; i < MS; i++) {
                int r = wm + 16 * i + a_row;
                int ph = (cb + a_ch) ^ ((r >> 1) & 3);
                ldsm4(a[i][0], a[i][1], a[i][2], a[i][3],
                      as0 + (unsigned)(buf * ASZ + r * 16 + ph * 4) * 4u);
            }
            #pragma unroll
            for (int j = 0; j < NS / 2; j++) {
                int r = wn + 16 * j + b_row;
                int ph = (cb + b_ch) ^ ((r >> 1) & 3);
                ldsm4(bfr[2*j][0], bfr[2*j][1], bfr[2*j+1][0], bfr[2*j+1][1],
                      bs0 + (unsigned)(buf * BSZ + r * 16 + ph * 4) * 4u);
            }
            #pragma unroll
            for (int i = 0; i < MS; i++)
                #pragma unroll
                for (int j = 0; j < NS; j++)
                    mma_tf32(acc[i][j], a[i], bfr[j]);
        }
        __syncthreads();
    }

    #pragma unroll
    for (int i = 0; i < MS; i++)
        #pragma unroll
        for (int j = 0; j < NS; j++)
            #pragma unroll
            for (int r = 0; r < 4; r++) acc[i][j][r] *= 0.125f;

    #pragma unroll
    for (int i = 0; i < MS; i++) {
        const int r = bm + wm + 16 * i + (lane >> 2);
        #pragma unroll
        for (int j = 0; j < NS; j++) {
            const int cn = bn + wn + 8 * j + 2 * (lane & 3);
            *(float2*)&C[(size_t)r * LK + cn]       = make_float2(acc[i][j][0], acc[i][j][1]);
            *(float2*)&C[(size_t)(r + 8) * LK + cn] = make_float2(acc[i][j][2], acc[i][j][3]);
        }
    }

    float* sm_m = As;
    float* sm_s = As + 512;
    __syncthreads();

    const int ng = warp % WARPS_N;
    #pragma unroll
    for (int i = 0; i < MS; i++) {
        #pragma unroll
        for (int hh = 0; hh < 2; hh++) {
            float v[8];
            #pragma unroll
            for (int j = 0; j < NS; j++) {
                v[2*j]   = acc[i][j][2*hh];
                v[2*j+1] = acc[i][j][2*hh+1];
            }
            float m = v[0];
            #pragma unroll
            for (int e = 1; e < 8; e++) m = fmaxf(m, v[e]);
            m = fmaxf(m, __shfl_xor_sync(0xffffffffu, m, 1));
            m = fmaxf(m, __shfl_xor_sync(0xffffffffu, m, 2));
            float se = 0.f;
            #pragma unroll
            for (int e = 0; e < 8; e++) se += __expf(v[e] - m);
            se += __shfl_xor_sync(0xffffffffu, se, 1);
            se += __shfl_xor_sync(0xffffffffu, se, 2);
            if ((lane & 3) == 0) {
                int row = wm + 16 * i + (lane >> 2) + 8 * hh;
                sm_m[ng * 128 + row] = m;
                sm_s[ng * 128 + row] = se;
            }
        }
    }
    __syncthreads();

    if (tid < 128) {
        float m0 = sm_m[tid], m1 = sm_m[128 + tid];
        float m2 = sm_m[256 + tid], m3 = sm_m[384 + tid];
        float M = fmaxf(fmaxf(m0, m1), fmaxf(m2, m3));
        float S = sm_s[tid]       * __expf(m0 - M)
                + sm_s[128 + tid] * __expf(m1 - M)
                + sm_s[256 + tid] * __expf(m2 - M)
                + sm_s[384 + tid] * __expf(m3 - M);
        sstats[((size_t)z * 16 + blockIdx.x) * LQ + bm + tid] = make_float2(M, S);
    }
}

// ---------------------------------------------------------------------------
// Combine 16 slab stats per row -> (M, 1/S)
// ---------------------------------------------------------------------------
__global__ __launch_bounds__(256)
void rowcombine(const float2* __restrict__ sstats, float2* __restrict__ rowstats)
{
    int idx = blockIdx.x * 256 + threadIdx.x;
    int z = idx >> 9, row = idx & 511;
    const float2* p = sstats + (size_t)z * 16 * LQ + row;
    float2 v[16];
    #pragma unroll
    for (int s = 0; s < 16; s++) v[s] = p[(size_t)s * LQ];
    float M = v[0].x;
    #pragma unroll
    for (int s = 1; s < 16; s++) M = fmaxf(M, v[s].x);
    float S = 0.f;
    #pragma unroll
    for (int s = 0; s < 16; s++) S += v[s].y * __expf(v[s].x - M);
    rowstats[idx] = make_float2(M, 1.0f / S);
}

// ---------------------------------------------------------------------------
// Fused normalize + ctx GEMM (S prefetch 2 deep).
// ---------------------------------------------------------------------------
__global__ __launch_bounds__(256)
void ctx_fused(const float2* __restrict__ rowstats,
               float* __restrict__ attn,
               const float* __restrict__ vt,
               float* __restrict__ ctx)
{
    constexpr int BM = 128, BN = 64, WM = 32, WN = 32;
    constexpr int WARPS_N = BN / WN;
    constexpr int MS = WM / 16, NS = WN / 8;
    constexpr int ASZ = BM * 16, BSZ = BN * 16;

    __shared__ __align__(16) float As[2 * ASZ];
    __shared__ __align__(16) float Bs[3 * BSZ];
    __shared__ float2 rs[BM];

    const int z = blockIdx.y;
    const int b = z >> 4, h = z & 15;
    const int bm = blockIdx.x * BM;
    float* Sp = attn + ((size_t)z * LQ + bm) * LK;
    const float* Vb = vt + ((size_t)b * E_ + h * DH) * LK;
    float* Cp = ctx + ((size_t)b * LQ + bm) * E_ + h * DH;

    const int tid = threadIdx.x, warp = tid >> 5, lane = tid & 31;
    const int wm = (warp / WARPS_N) * WM, wn = (warp % WARPS_N) * WN;

    if (tid < BM) rs[tid] = rowstats[(size_t)z * LQ + bm + tid];

    const unsigned as0 = (unsigned)__cvta_generic_to_shared(As);
    const unsigned bs0 = (unsigned)__cvta_generic_to_shared(Bs);
    const int ld_r = tid >> 2, ld_c = tid & 3;
    const int ph0 = ld_c ^ ((ld_r >> 1) & 3);
    const int ph1 = ld_c ^ (((ld_r + 64) >> 1) & 3);

    auto loadB = [&](int buf, int k0) {
        int ph = ld_c ^ ((ld_r >> 1) & 3);
        cp_async16(bs0 + (unsigned)(buf * BSZ + ld_r * 16 + ph * 4) * 4u,
                   Vb + (size_t)ld_r * LK + k0 + ld_c * 4);
    };

    loadB(0, 0);  cp_commit();
    loadB(1, 16); cp_commit();

    const float* Sr0 = Sp + (size_t)ld_r * LK + ld_c * 4;
    const float* Sr1 = Sp + (size_t)(ld_r + 64) * LK + ld_c * 4;
    float4 s0 = *(const float4*)Sr0;
    float4 s1 = *(const float4*)Sr1;
    float4 n0 = *(const float4*)(Sr0 + 16);
    float4 n1 = *(const float4*)(Sr1 + 16);

    __syncthreads();
    const float2 st0 = rs[ld_r];
    const float2 st1 = rs[ld_r + 64];

    float acc[MS][NS][4];
    #pragma unroll
    for (int i = 0; i < MS; i++)
        #pragma unroll
        for (int j = 0; j < NS; j++)
            #pragma unroll
            for (int r = 0; r < 4; r++) acc[i][j][r] = 0.f;

    const int a_row = (lane & 7) + ((lane >> 3) & 1) * 8;
    const int a_ch  = lane >> 4;
    const int b_row = (lane & 7) + ((lane >= 16) ? 8 : 0);
    const int b_ch  = (lane >> 3) & 1;

    const int nk = LK >> 4;
    #pragma unroll 2
    for (int t = 0; t < nk; t++) {
        const int abuf = t & 1;
        float4 p0, p1;
        p0.x = round_tf32(__expf(s0.x - st0.x) * st0.y);
        p0.y = round_tf32(__expf(s0.y - st0.x) * st0.y);
        p0.z = round_tf32(__expf(s0.z - st0.x) * st0.y);
        p0.w = round_tf32(__expf(s0.w - st0.x) * st0.y);
        p1.x = round_tf32(__expf(s1.x - st1.x) * st1.y);
        p1.y = round_tf32(__expf(s1.y - st1.x) * st1.y);
        p1.z = round_tf32(__expf(s1.z - st1.x) * st1.y);
        p1.w = round_tf32(__expf(s1.w - st1.x) * st1.y);
        *(float4*)&As[abuf * ASZ + ld_r * 16 + ph0 * 4]        = p0;
        *(float4*)&As[abuf * ASZ + (ld_r + 64) * 16 + ph1 * 4] = p1;
        *(float4*)(Sr0 + (size_t)t * 16) = p0;
        *(float4*)(Sr1 + (size_t)t * 16) = p1;
        s0 = n0; s1 = n1;
        if (t + 2 < nk) {
            n0 = *(const float4*)(Sr0 + (size_t)(t + 2) * 16);
            n1 = *(const float4*)(Sr1 + (size_t)(t + 2) * 16);
        }
        cp_wait<1>();
        __syncthreads();
        if (t + 2 < nk) loadB((t + 2) % 3, (t + 2) * 16);
        cp_commit();

        const int bbuf = t % 3;
        #pragma unroll
        for (int k8 = 0; k8 < 2; k8++) {
            const int cb = k8 * 2;
            unsigned a[MS][4], bfr[NS][2];
            #pragma unroll
            for (int i = 0; i < MS; i++) {
                int r = wm + 16 * i + a_row;
                int ph = (cb + a_ch) ^ ((r >> 1) & 3);
                ldsm4(a[i][0], a[i][1], a[i][2], a[i][3],
                      as0 + (unsigned)(abuf * ASZ + r * 16 + ph * 4) * 4u);
            }
            #pragma unroll
            for (int j = 0; j < NS / 2; j++) {
                int r = wn + 16 * j + b_row;
                int ph = (cb + b_ch) ^ ((r >> 1) & 3);
                ldsm4(bfr[2*j][0], bfr[2*j][1], bfr[2*j+1][0], bfr[2*j+1][1],
                      bs0 + (unsigned)(bbuf * BSZ + r * 16 + ph * 4) * 4u);
            }
            #pragma unroll
            for (int i = 0; i < MS; i++)
                #pragma unroll
                for (int j = 0; j < NS; j++)
                    mma_tf32(acc[i][j], a[i], bfr[j]);
        }
    }

    #pragma unroll
    for (int i = 0; i < MS; i++) {
        const int r = wm + 16 * i + (lane >> 2);
        #pragma unroll
        for (int j = 0; j < NS; j++) {
            const int cn = wn + 8 * j + 2 * (lane & 3);
            float v0 = round_tf32(acc[i][j][0]);
            float v1 = round_tf32(acc[i][j][1]);
            float v2 = round_tf32(acc[i][j][2]);
            float v3 = round_tf32(acc[i][j][3]);
            *(float2*)&Cp[(size_t)r * E_ + cn]       = make_float2(v0, v1);
            *(float2*)&Cp[(size_t)(r + 8) * E_ + cn] = make_float2(v2, v3);
        }
    }
}

// ---------------------------------------------------------------------------
// Per-batch transpose of V (float4 vectorized): vt[b][n][k] = v[b][k][n]
// ---------------------------------------------------------------------------
__global__ __launch_bounds__(256)
void transpose_v(const float* __restrict__ v, float* __restrict__ vt)
{
    __shared__ float t[32][129];
    const int b  = blockIdx.z;
    const int k0 = blockIdx.x * 32;
    const int n0 = blockIdx.y * 128;
    const int tx = threadIdx.x;
    const int ty = threadIdx.y;

    #pragma unroll
    for (int i = ty; i < 32; i += 8) {
        float4 val = *(const float4*)&v[((size_t)b * LK + k0 + i) * E_ + n0 + tx * 4];
        t[i][tx * 4 + 0] = val.x;
        t[i][tx * 4 + 1] = val.y;
        t[i][tx * 4 + 2] = val.z;
        t[i][tx * 4 + 3] = val.w;
    }
    __syncthreads();

    #pragma unroll
    for (int i = ty; i < 128; i += 8)
        vt[((size_t)b * E_ + n0 + i) * LK + k0 + tx] = t[tx][i];
}

// ---------------------------------------------------------------------------
// out = LayerNorm(a + b) * g + beta
// ---------------------------------------------------------------------------
template<int ROUND>
__global__ __launch_bounds__(256)
void ln_residual(const float* __restrict__ A, const float* __restrict__ Bx,
                 const float* __restrict__ g, const float* __restrict__ be,
                 float* __restrict__ out)
{
    const size_t row = blockIdx.x;
    const int t = threadIdx.x;

    float4 a = ((const float4*)(A  + row * E_))[t];
    float4 b = ((const float4*)(Bx + row * E_))[t];
    float4 x = make_float4(a.x + b.x, a.y + b.y, a.z + b.z, a.w + b.w);

    float s  = x.x + x.y + x.z + x.w;
    float ss = x.x*x.x + x.y*x.y + x.z*x.z + x.w*x.w;

    __shared__ float rs_[8], rss[8];
    #pragma unroll
    for (int o = 16; o > 0; o >>= 1) {
        s  += __shfl_xor_sync(0xffffffffu, s,  o);
        ss += __shfl_xor_sync(0xffffffffu, ss, o);
    }
    if ((t & 31) == 0) { rs_[t >> 5] = s; rss[t >> 5] = ss; }
    __syncthreads();
    s = 0.f; ss = 0.f;
    #pragma unroll
    for (int i = 0; i < 8; i++) { s += rs_[i]; ss += rss[i]; }

    const float mean = s * (1.0f / E_);
    const float var  = ss * (1.0f / E_) - mean * mean;
    const float inv  = rsqrtf(var + 1e-5f);

    float4 gg = ((const float4*)g)[t];
    float4 bb = ((const float4*)be)[t];
    float4 o;
    o.x = (x.x - mean) * inv * gg.x + bb.x;
    o.y = (x.y - mean) * inv * gg.y + bb.y;
    o.z = (x.z - mean) * inv * gg.z + bb.z;
    o.w = (x.w - mean) * inv * gg.w + bb.w;
    if (ROUND) {
        o.x = round_tf32(o.x); o.y = round_tf32(o.y);
        o.z = round_tf32(o.z); o.w = round_tf32(o.w);
    }
    ((float4*)(out + row * E_))[t] = o;
}

// ---------------------------------------------------------------------------
extern "C" void kernel_launch(void* const* d_in, const int* in_sizes, int n_in,
                              void* d_out, int out_size)
{
    const float* query = (const float*)d_in[0];
    const float* keyv  = (const float*)d_in[1];
    const float* wq = (const float*)d_in[2];
    const float* wk = (const float*)d_in[3];
    const float* wv = (const float*)d_in[4];
    const float* bq = (const float*)d_in[5];
    const float* bk = (const float*)d_in[6];
    const float* bv = (const float*)d_in[7];
    const float* wo = (const float*)d_in[8];
    const float* bo = (const float*)d_in[9];
    const float* g1 = (const float*)d_in[10];
    const float* be1 = (const float*)d_in[11];
    const float* w1 = (const float*)d_in[12];
    const float* b1 = (const float*)d_in[13];
    const float* w2 = (const float*)d_in[14];
    const float* b2 = (const float*)d_in[15];
    const float* g2 = (const float*)d_in[16];
    const float* be2 = (const float*)d_in[17];

    float* out = (float*)d_out;
    float* q3_out = out;
    float* attn   = out + (size_t)MQ * E_;

    float *gq, *gk, *gv, *gvt, *gctx, *gao, *gq2, *gf1, *gf2;
    float *rwq, *rwk, *rwv;
    float2 *sst, *rst;
    cudaGetSymbolAddress((void**)&gq,  g_q);
    cudaGetSymbolAddress((void**)&gk,  g_k);
    cudaGetSymbolAddress((void**)&gv,  g_v);
    cudaGetSymbolAddress((void**)&gvt, g_vt);
    cudaGetSymbolAddress((void**)&gctx, g_ctx);
    cudaGetSymbolAddress((void**)&gao, g_attnout);
    cudaGetSymbolAddress((void**)&gq2, g_q2);
    cudaGetSymbolAddress((void**)&gf1, g_ffn1);
    cudaGetSymbolAddress((void**)&gf2, g_ffn2);
    cudaGetSymbolAddress((void**)&rwq, r_wq);
    cudaGetSymbolAddress((void**)&rwk, r_wk);
    cudaGetSymbolAddress((void**)&rwv, r_wv);
    cudaGetSymbolAddress((void**)&sst, g_sstats);
    cudaGetSymbolAddress((void**)&rst, g_rowstats);

    // one-time setup
    static cudaStream_t s1 = nullptr, s2 = nullptr;
    static cudaEvent_t e0, e1, e2;
    if (!s1) {
        cudaFuncSetAttribute(tf32_gemm<128,128,64,32,0>,
                             cudaFuncAttributeMaxDynamicSharedMemorySize, 98304);
        cudaFuncSetAttribute(tf32_gemm<128,128,64,32,1>,
                             cudaFuncAttributeMaxDynamicSharedMemorySize, 98304);
        cudaFuncSetAttribute(tf32_gemm<128,64,32,32,0>,
                             cudaFuncAttributeMaxDynamicSharedMemorySize, 73728);
        cudaFuncSetAttribute(tf32_gemm<128,64,32,32,1>,
                             cudaFuncAttributeMaxDynamicSharedMemorySize, 73728);
        cudaStreamCreateWithFlags(&s1, cudaStreamNonBlocking);
        cudaStreamCreateWithFlags(&s2, cudaStreamNonBlocking);
        cudaEventCreateWithFlags(&e0, cudaEventDisableTiming);
        cudaEventCreateWithFlags(&e1, cudaEventDisableTiming);
        cudaEventCreateWithFlags(&e2, cudaEventDisableTiming);
    }
    const int GS128 = 98304;
    const int GS64  = 73728;

    // ---- front prepass: only QKV weights (24 MB); everything else raw ----
    {
        RCArgs rc;
        rc.src[0] = (const float4*)wq; rc.dst[0] = (float4*)rwq;
        rc.src[1] = (const float4*)wk; rc.dst[1] = (float4*)rwk;
        rc.src[2] = (const float4*)wv; rc.dst[2] = (float4*)rwv;
        rc.off[0] = 0;
        rc.off[1] = E_*E_/4;
        rc.off[2] = rc.off[1] + E_*E_/4;
        rc.off[3] = rc.off[2] + E_*E_/4;
        rc.off[4] = rc.off[3];
        rc.off[5] = rc.off[3];
        rc.nseg = 3;
        round_copy_seg<<<1024, 256>>>(rc);
    }

    // fork: default = K proj, s1 = V proj + transpose, s2 = Q proj
    cudaEventRecord(e0, 0);
    cudaStreamWaitEvent(s1, e0, 0);
    cudaStreamWaitEvent(s2, e0, 0);

    tf32_gemm<128,128,64,32,1><<<dim3(E_/128, MK/128), 256, GS128>>>(
        keyv, E_,  rwk, E_,  bk,  gk, E_,  E_, 1.f, 0);

    tf32_gemm<128,128,64,32,1><<<dim3(E_/128, MK/128), 256, GS128, s1>>>(
        keyv, E_,  rwv, E_,  bv,  gv, E_,  E_, 1.f, 0);
    transpose_v<<<dim3(LK/32, E_/128, B_), dim3(32, 8), 0, s1>>>(gv, gvt);
    cudaEventRecord(e1, s1);

    tf32_gemm<128,64,32,32,1><<<dim3(E_/64, MQ/128), 256, GS64, s2>>>(
        query, E_,  rwq, E_,  bq,  gq, E_,  E_, 1.f, 0);
    cudaEventRecord(e2, s2);

    // join: scores needs Q (s2) and K (default)
    cudaStreamWaitEvent(0, e2, 0);
    scores_stats<<<dim3(LK/128, LQ/128, B_*H_), 256>>>(gq, gk, attn, sst);
    rowcombine<<<(B_*H_*LQ)/256, 256>>>(sst, rst);

    // ctx needs transpose (s1: e1)
    cudaStreamWaitEvent(0, e1, 0);
    ctx_fused<<<dim3(LQ/128, B_*H_), 256>>>(rst, attn, gvt, gctx);

    // ---- output projection + LN1 (raw wo; mma truncates) ----
    tf32_gemm<128,64,32,32,0><<<dim3(E_/64, MQ/128), 256, GS64>>>(
        gctx, E_,  wo, E_,  bo,  gao, E_,  E_, 1.f, 0);
    ln_residual<1><<<MQ, 256>>>(query, gao, g1, be1, gq2);

    // ---- FFN + LN2 (raw w1/w2) ----
    tf32_gemm<128,128,64,32,1><<<dim3(F_/128, MQ/128), 256, GS128>>>(
        gq2, E_,  w1, E_,  b1,  gf1, F_,  E_, 1.f, 1);
    tf32_gemm<128,64,32,32,0><<<dim3(E_/64, MQ/128), 256, GS64>>>(
        gf1, F_,  w2, F_,  b2,  gf2, E_,  F_, 1.f, 0);
    ln_residual<0><<<MQ, 256>>>(gq2, gf2, g2, be2, q3_out);
}

// round 17
// speedup vs baseline: 1.6972x; 1.0361x over previous
#include <cuda_runtime.h>
#include <cstddef>

// Problem constants
#define B_  4
#define LQ  512
#define LK  2048
#define E_  1024
#define H_  16
#define DH  64
#define F_  4096
#define MQ  (B_*LQ)    // 2048
#define MK  (B_*LK)    // 8192

// ---------------- scratch (device globals; no allocation allowed) ----------
__device__ float g_q[MQ * E_];
__device__ float g_k[MK * E_];
__device__ float g_v[MK * E_];
__device__ float g_vt[MK * E_];
__device__ float g_ctx[MQ * E_];
__device__ float g_attnout[MQ * E_];
__device__ float g_q2[MQ * E_];
__device__ float g_ffn1[MQ * F_];
__device__ float g_ffn2[MQ * E_];
// softmax statistics
__device__ float2 g_sstats[64 * 16 * 512];
__device__ float2 g_rowstats[64 * 512];

// ---------------------------------------------------------------------------
// helpers
// ---------------------------------------------------------------------------
__device__ __forceinline__ unsigned cvt_tf32(float x) {
    unsigned r;
    asm("cvt.rna.tf32.f32 %0, %1;" : "=r"(r) : "f"(x));
    return r;
}
__device__ __forceinline__ float round_tf32(float x) {
    return __uint_as_float(cvt_tf32(x));
}

__device__ __forceinline__ void cp_async16(unsigned saddr, const void* gptr) {
    asm volatile("cp.async.cg.shared.global [%0], [%1], 16;" :: "r"(saddr), "l"(gptr));
}
__device__ __forceinline__ void cp_commit() {
    asm volatile("cp.async.commit_group;");
}
template<int N>
__device__ __forceinline__ void cp_wait() {
    asm volatile("cp.async.wait_group %0;" :: "n"(N));
}

__device__ __forceinline__ void ldsm4(unsigned &r0, unsigned &r1,
                                      unsigned &r2, unsigned &r3, unsigned addr) {
    asm volatile("ldmatrix.sync.aligned.m8n8.x4.shared.b16 {%0,%1,%2,%3}, [%4];"
                 : "=r"(r0), "=r"(r1), "=r"(r2), "=r"(r3) : "r"(addr));
}

__device__ __forceinline__ void mma_tf32(float c[4], const unsigned a[4],
                                         const unsigned b[2]) {
    asm volatile(
        "mma.sync.aligned.m16n8k8.row.col.f32.tf32.tf32.f32 "
        "{%0,%1,%2,%3}, {%4,%5,%6,%7}, {%8,%9}, {%0,%1,%2,%3};"
        : "+f"(c[0]), "+f"(c[1]), "+f"(c[2]), "+f"(c[3])
        : "r"(a[0]), "r"(a[1]), "r"(a[2]), "r"(a[3]), "r"(b[0]), "r"(b[1]));
}

// ---------------------------------------------------------------------------
// Pipelined NT GEMM, tf32 tensor cores, BK=32, 3 stages, ONE sync per k-iter.
// A and B may be raw fp32 (mma truncates to tf32).
// ---------------------------------------------------------------------------
template<int BM, int BN, int WM, int WN, int ROUND>
__global__ __launch_bounds__(256)
void tf32_gemm(const float* __restrict__ A, int lda,
               const float* __restrict__ B, int ldb,
               const float* __restrict__ bias,
               float* __restrict__ C, int ldc,
               int K, float scale, int relu)
{
    constexpr int WARPS_N = BN / WN;
    constexpr int MS = WM / 16, NS = WN / 8;
    constexpr int ASZ = BM * 32;
    constexpr int BSZ = BN * 32;

    extern __shared__ __align__(16) float sm[];
    float* As = sm;
    float* Bs = sm + 3 * ASZ;

    const int bm = blockIdx.y * BM, bn = blockIdx.x * BN;
    const int tid = threadIdx.x, warp = tid >> 5, lane = tid & 31;
    const int wm = (warp / WARPS_N) * WM, wn = (warp % WARPS_N) * WN;

    const unsigned as0 = (unsigned)__cvta_generic_to_shared(As);
    const unsigned bs0 = (unsigned)__cvta_generic_to_shared(Bs);

    const int ld_r = tid >> 3;
    const int ld_c = tid & 7;

    auto load_stage = [&](int buf, int k0) {
        #pragma unroll
        for (int i = 0; i < BM / 32; i++) {
            int r = ld_r + i * 32;
            int ph = ld_c ^ (r & 7);
            cp_async16(as0 + (unsigned)(buf * ASZ + r * 32 + ph * 4) * 4u,
                       A + (size_t)(bm + r) * lda + k0 + ld_c * 4);
        }
        #pragma unroll
        for (int i = 0; i < BN / 32; i++) {
            int r = ld_r + i * 32;
            int ph = ld_c ^ (r & 7);
            cp_async16(bs0 + (unsigned)(buf * BSZ + r * 32 + ph * 4) * 4u,
                       B + (size_t)(bn + r) * ldb + k0 + ld_c * 4);
        }
    };

    float acc[MS][NS][4];
    #pragma unroll
    for (int i = 0; i < MS; i++)
        #pragma unroll
        for (int j = 0; j < NS; j++)
            #pragma unroll
            for (int r = 0; r < 4; r++) acc[i][j][r] = 0.f;

    const int a_row = (lane & 7) + ((lane >> 3) & 1) * 8;
    const int a_ch  = lane >> 4;
    const int b_row = (lane & 7) + ((lane >= 16) ? 8 : 0);
    const int b_ch  = (lane >> 3) & 1;

    const int nk = K >> 5;
    load_stage(0, 0);  cp_commit();
    load_stage(1, 32); cp_commit();

    for (int ks = 0; ks < nk; ks++) {
        cp_wait<1>();
        __syncthreads();
        const int buf = ks % 3;
        if (ks + 2 < nk) load_stage((ks + 2) % 3, (ks + 2) << 5);
        cp_commit();

        #pragma unroll
        for (int k8 = 0; k8 < 4; k8++) {
            const int cb = k8 * 2;
            unsigned a[MS][4], b[NS][2];
            #pragma unroll
            for (int i = 0; i < MS; i++) {
                int r = wm + 16 * i + a_row;
                int ph = (cb + a_ch) ^ (r & 7);
                ldsm4(a[i][0], a[i][1], a[i][2], a[i][3],
                      as0 + (unsigned)(buf * ASZ + r * 32 + ph * 4) * 4u);
            }
            #pragma unroll
            for (int j = 0; j < NS / 2; j++) {
                int r = wn + 16 * j + b_row;
                int ph = (cb + b_ch) ^ (r & 7);
                ldsm4(b[2*j][0], b[2*j][1], b[2*j+1][0], b[2*j+1][1],
                      bs0 + (unsigned)(buf * BSZ + r * 32 + ph * 4) * 4u);
            }
            #pragma unroll
            for (int i = 0; i < MS; i++)
                #pragma unroll
                for (int j = 0; j < NS; j++)
                    mma_tf32(acc[i][j], a[i], b[j]);
        }
    }

    #pragma unroll
    for (int i = 0; i < MS; i++) {
        const int r = bm + wm + 16 * i + (lane >> 2);
        #pragma unroll
        for (int j = 0; j < NS; j++) {
            const int cn = bn + wn + 8 * j + 2 * (lane & 3);
            float bx = 0.f, by = 0.f;
            if (bias) { float2 bb = *(const float2*)&bias[cn]; bx = bb.x; by = bb.y; }
            float v0 = acc[i][j][0] * scale + bx;
            float v1 = acc[i][j][1] * scale + by;
            float v2 = acc[i][j][2] * scale + bx;
            float v3 = acc[i][j][3] * scale + by;
            if (relu) {
                v0 = fmaxf(v0, 0.f); v1 = fmaxf(v1, 0.f);
                v2 = fmaxf(v2, 0.f); v3 = fmaxf(v3, 0.f);
            }
            if (ROUND) {
                v0 = round_tf32(v0); v1 = round_tf32(v1);
                v2 = round_tf32(v2); v3 = round_tf32(v3);
            }
            *(float2*)&C[(size_t)r * ldc + cn]       = make_float2(v0, v1);
            *(float2*)&C[(size_t)(r + 8) * ldc + cn] = make_float2(v2, v3);
        }
    }
}

// ---------------------------------------------------------------------------
// Scores GEMM + per-slab softmax statistics.
// ---------------------------------------------------------------------------
__global__ __launch_bounds__(256)
void scores_stats(const float* __restrict__ q, const float* __restrict__ k,
                  float* __restrict__ attn, float2* __restrict__ sstats)
{
    constexpr int BM = 128, BN = 128, WM = 64, WN = 32;
    constexpr int WARPS_N = BN / WN;
    constexpr int MS = WM / 16, NS = WN / 8;
    constexpr int ASZ = BM * 16, BSZ = BN * 16;

    __shared__ __align__(16) float As[3 * ASZ];
    __shared__ __align__(16) float Bs[3 * BSZ];

    const int z = blockIdx.z;
    const int b = z >> 4, h = z & 15;
    const float* A = q + (size_t)b * LQ * E_ + h * DH;
    const float* B = k + (size_t)b * LK * E_ + h * DH;
    float* C = attn + (size_t)z * LQ * LK;

    const int bm = blockIdx.y * BM, bn = blockIdx.x * BN;
    const int tid = threadIdx.x, warp = tid >> 5, lane = tid & 31;
    const int wm = (warp / WARPS_N) * WM, wn = (warp % WARPS_N) * WN;

    const unsigned as0 = (unsigned)__cvta_generic_to_shared(As);
    const unsigned bs0 = (unsigned)__cvta_generic_to_shared(Bs);
    const int ld_r = tid >> 2, ld_c = tid & 3;

    auto load_stage = [&](int buf, int k0) {
        #pragma unroll
        for (int i = 0; i < 2; i++) {
            int r = ld_r + i * 64;
            int ph = ld_c ^ ((r >> 1) & 3);
            cp_async16(as0 + (unsigned)(buf * ASZ + r * 16 + ph * 4) * 4u,
                       A + (size_t)(bm + r) * E_ + k0 + ld_c * 4);
            cp_async16(bs0 + (unsigned)(buf * BSZ + r * 16 + ph * 4) * 4u,
                       B + (size_t)(bn + r) * E_ + k0 + ld_c * 4);
        }
    };

    float acc[MS][NS][4];
    #pragma unroll
    for (int i = 0; i < MS; i++)
        #pragma unroll
        for (int j = 0; j < NS; j++)
            #pragma unroll
            for (int r = 0; r < 4; r++) acc[i][j][r] = 0.f;

    const int a_row = (lane & 7) + ((lane >> 3) & 1) * 8;
    const int a_ch  = lane >> 4;
    const int b_row = (lane & 7) + ((lane >= 16) ? 8 : 0);
    const int b_ch  = (lane >> 3) & 1;

    const int nk = DH >> 4;
    load_stage(0, 0);  cp_commit();
    load_stage(1, 16); cp_commit();

    for (int ks = 0; ks < nk; ks++) {
        cp_wait<1>();
        __syncthreads();
        const int buf = ks % 3;
        if (ks + 2 < nk) load_stage((ks + 2) % 3, (ks + 2) << 4);
        cp_commit();

        #pragma unroll
        for (int k8 = 0; k8 < 2; k8++) {
            const int cb = k8 * 2;
            unsigned a[MS][4], bfr[NS][2];
            #pragma unroll
            for (int i = 0; i < MS; i++) {
                int r = wm + 16 * i + a_row;
                int ph = (cb + a_ch) ^ ((r >> 1) & 3);
                ldsm4(a[i][0], a[i][1], a[i][2], a[i][3],
                      as0 + (unsigned)(buf * ASZ + r * 16 + ph * 4) * 4u);
            }
            #pragma unroll
            for (int j = 0; j < NS / 2; j++) {
                int r = wn + 16 * j + b_row;
                int ph = (cb + b_ch) ^ ((r >> 1) & 3);
                ldsm4(bfr[2*j][0], bfr[2*j][1], bfr[2*j+1][0], bfr[2*j+1][1],
                      bs0 + (unsigned)(buf * BSZ + r * 16 + ph * 4) * 4u);
            }
            #pragma unroll
            for (int i = 0; i < MS; i++)
                #pragma unroll
                for (int j = 0; j < NS; j++)
                    mma_tf32(acc[i][j], a[i], bfr[j]);
        }
        __syncthreads();
    }

    #pragma unroll
    for (int i = 0; i < MS; i++)
        #pragma unroll
        for (int j = 0; j < NS; j++)
            #pragma unroll
            for (int r = 0; r < 4; r++) acc[i][j][r] *= 0.125f;

    #pragma unroll
    for (int i = 0; i < MS; i++) {
        const int r = bm + wm + 16 * i + (lane >> 2);
        #pragma unroll
        for (int j = 0; j < NS; j++) {
            const int cn = bn + wn + 8 * j + 2 * (lane & 3);
            *(float2*)&C[(size_t)r * LK + cn]       = make_float2(acc[i][j][0], acc[i][j][1]);
            *(float2*)&C[(size_t)(r + 8) * LK + cn] = make_float2(acc[i][j][2], acc[i][j][3]);
        }
    }

    float* sm_m = As;
    float* sm_s = As + 512;
    __syncthreads();

    const int ng = warp % WARPS_N;
    #pragma unroll
    for (int i = 0; i < MS; i++) {
        #pragma unroll
        for (int hh = 0; hh < 2; hh++) {
            float v[8];
            #pragma unroll
            for (int j = 0; j < NS; j++) {
                v[2*j]   = acc[i][j][2*hh];
                v[2*j+1] = acc[i][j][2*hh+1];
            }
            float m = v[0];
            #pragma unroll
            for (int e = 1; e < 8; e++) m = fmaxf(m, v[e]);
            m = fmaxf(m, __shfl_xor_sync(0xffffffffu, m, 1));
            m = fmaxf(m, __shfl_xor_sync(0xffffffffu, m, 2));
            float se = 0.f;
            #pragma unroll
            for (int e = 0; e < 8; e++) se += __expf(v[e] - m);
            se += __shfl_xor_sync(0xffffffffu, se, 1);
            se += __shfl_xor_sync(0xffffffffu, se, 2);
            if ((lane & 3) == 0) {
                int row = wm + 16 * i + (lane >> 2) + 8 * hh;
                sm_m[ng * 128 + row] = m;
                sm_s[ng * 128 + row] = se;
            }
        }
    }
    __syncthreads();

    if (tid < 128) {
        float m0 = sm_m[tid], m1 = sm_m[128 + tid];
        float m2 = sm_m[256 + tid], m3 = sm_m[384 + tid];
        float M = fmaxf(fmaxf(m0, m1), fmaxf(m2, m3));
        float S = sm_s[tid]       * __expf(m0 - M)
                + sm_s[128 + tid] * __expf(m1 - M)
                + sm_s[256 + tid] * __expf(m2 - M)
                + sm_s[384 + tid] * __expf(m3 - M);
        sstats[((size_t)z * 16 + blockIdx.x) * LQ + bm + tid] = make_float2(M, S);
    }
}

// ---------------------------------------------------------------------------
// Combine 16 slab stats per row -> (M, 1/S)
// ---------------------------------------------------------------------------
__global__ __launch_bounds__(256)
void rowcombine(const float2* __restrict__ sstats, float2* __restrict__ rowstats)
{
    int idx = blockIdx.x * 256 + threadIdx.x;
    int z = idx >> 9, row = idx & 511;
    const float2* p = sstats + (size_t)z * 16 * LQ + row;
    float2 v[16];
    #pragma unroll
    for (int s = 0; s < 16; s++) v[s] = p[(size_t)s * LQ];
    float M = v[0].x;
    #pragma unroll
    for (int s = 1; s < 16; s++) M = fmaxf(M, v[s].x);
    float S = 0.f;
    #pragma unroll
    for (int s = 0; s < 16; s++) S += v[s].y * __expf(v[s].x - M);
    rowstats[idx] = make_float2(M, 1.0f / S);
}

// ---------------------------------------------------------------------------
// Fused normalize + ctx GEMM (S prefetch 2 deep).
// ---------------------------------------------------------------------------
__global__ __launch_bounds__(256)
void ctx_fused(const float2* __restrict__ rowstats,
               float* __restrict__ attn,
               const float* __restrict__ vt,
               float* __restrict__ ctx)
{
    constexpr int BM = 128, BN = 64, WM = 32, WN = 32;
    constexpr int WARPS_N = BN / WN;
    constexpr int MS = WM / 16, NS = WN / 8;
    constexpr int ASZ = BM * 16, BSZ = BN * 16;

    __shared__ __align__(16) float As[2 * ASZ];
    __shared__ __align__(16) float Bs[3 * BSZ];
    __shared__ float2 rs[BM];

    const int z = blockIdx.y;
    const int b = z >> 4, h = z & 15;
    const int bm = blockIdx.x * BM;
    float* Sp = attn + ((size_t)z * LQ + bm) * LK;
    const float* Vb = vt + ((size_t)b * E_ + h * DH) * LK;
    float* Cp = ctx + ((size_t)b * LQ + bm) * E_ + h * DH;

    const int tid = threadIdx.x, warp = tid >> 5, lane = tid & 31;
    const int wm = (warp / WARPS_N) * WM, wn = (warp % WARPS_N) * WN;

    if (tid < BM) rs[tid] = rowstats[(size_t)z * LQ + bm + tid];

    const unsigned as0 = (unsigned)__cvta_generic_to_shared(As);
    const unsigned bs0 = (unsigned)__cvta_generic_to_shared(Bs);
    const int ld_r = tid >> 2, ld_c = tid & 3;
    const int ph0 = ld_c ^ ((ld_r >> 1) & 3);
    const int ph1 = ld_c ^ (((ld_r + 64) >> 1) & 3);

    auto loadB = [&](int buf, int k0) {
        int ph = ld_c ^ ((ld_r >> 1) & 3);
        cp_async16(bs0 + (unsigned)(buf * BSZ + ld_r * 16 + ph * 4) * 4u,
                   Vb + (size_t)ld_r * LK + k0 + ld_c * 4);
    };

    loadB(0, 0);  cp_commit();
    loadB(1, 16); cp_commit();

    const float* Sr0 = Sp + (size_t)ld_r * LK + ld_c * 4;
    const float* Sr1 = Sp + (size_t)(ld_r + 64) * LK + ld_c * 4;
    float4 s0 = *(const float4*)Sr0;
    float4 s1 = *(const float4*)Sr1;
    float4 n0 = *(const float4*)(Sr0 + 16);
    float4 n1 = *(const float4*)(Sr1 + 16);

    __syncthreads();
    const float2 st0 = rs[ld_r];
    const float2 st1 = rs[ld_r + 64];

    float acc[MS][NS][4];
    #pragma unroll
    for (int i = 0; i < MS; i++)
        #pragma unroll
        for (int j = 0; j < NS; j++)
            #pragma unroll
            for (int r = 0; r < 4; r++) acc[i][j][r] = 0.f;

    const int a_row = (lane & 7) + ((lane >> 3) & 1) * 8;
    const int a_ch  = lane >> 4;
    const int b_row = (lane & 7) + ((lane >= 16) ? 8 : 0);
    const int b_ch  = (lane >> 3) & 1;

    const int nk = LK >> 4;
    #pragma unroll 2
    for (int t = 0; t < nk; t++) {
        const int abuf = t & 1;
        float4 p0, p1;
        p0.x = round_tf32(__expf(s0.x - st0.x) * st0.y);
        p0.y = round_tf32(__expf(s0.y - st0.x) * st0.y);
        p0.z = round_tf32(__expf(s0.z - st0.x) * st0.y);
        p0.w = round_tf32(__expf(s0.w - st0.x) * st0.y);
        p1.x = round_tf32(__expf(s1.x - st1.x) * st1.y);
        p1.y = round_tf32(__expf(s1.y - st1.x) * st1.y);
        p1.z = round_tf32(__expf(s1.z - st1.x) * st1.y);
        p1.w = round_tf32(__expf(s1.w - st1.x) * st1.y);
        *(float4*)&As[abuf * ASZ + ld_r * 16 + ph0 * 4]        = p0;
        *(float4*)&As[abuf * ASZ + (ld_r + 64) * 16 + ph1 * 4] = p1;
        *(float4*)(Sr0 + (size_t)t * 16) = p0;
        *(float4*)(Sr1 + (size_t)t * 16) = p1;
        s0 = n0; s1 = n1;
        if (t + 2 < nk) {
            n0 = *(const float4*)(Sr0 + (size_t)(t + 2) * 16);
            n1 = *(const float4*)(Sr1 + (size_t)(t + 2) * 16);
        }
        cp_wait<1>();
        __syncthreads();
        if (t + 2 < nk) loadB((t + 2) % 3, (t + 2) * 16);
        cp_commit();

        const int bbuf = t % 3;
        #pragma unroll
        for (int k8 = 0; k8 < 2; k8++) {
            const int cb = k8 * 2;
            unsigned a[MS][4], bfr[NS][2];
            #pragma unroll
            for (int i = 0; i < MS; i++) {
                int r = wm + 16 * i + a_row;
                int ph = (cb + a_ch) ^ ((r >> 1) & 3);
                ldsm4(a[i][0], a[i][1], a[i][2], a[i][3],
                      as0 + (unsigned)(abuf * ASZ + r * 16 + ph * 4) * 4u);
            }
            #pragma unroll
            for (int j = 0; j < NS / 2; j++) {
                int r = wn + 16 * j + b_row;
                int ph = (cb + b_ch) ^ ((r >> 1) & 3);
                ldsm4(bfr[2*j][0], bfr[2*j][1], bfr[2*j+1][0], bfr[2*j+1][1],
                      bs0 + (unsigned)(bbuf * BSZ + r * 16 + ph * 4) * 4u);
            }
            #pragma unroll
            for (int i = 0; i < MS; i++)
                #pragma unroll
                for (int j = 0; j < NS; j++)
                    mma_tf32(acc[i][j], a[i], bfr[j]);
        }
    }

    #pragma unroll
    for (int i = 0; i < MS; i++) {
        const int r = wm + 16 * i + (lane >> 2);
        #pragma unroll
        for (int j = 0; j < NS; j++) {
            const int cn = wn + 8 * j + 2 * (lane & 3);
            float v0 = round_tf32(acc[i][j][0]);
            float v1 = round_tf32(acc[i][j][1]);
            float v2 = round_tf32(acc[i][j][2]);
            float v3 = round_tf32(acc[i][j][3]);
            *(float2*)&Cp[(size_t)r * E_ + cn]       = make_float2(v0, v1);
            *(float2*)&Cp[(size_t)(r + 8) * E_ + cn] = make_float2(v2, v3);
        }
    }
}

// ---------------------------------------------------------------------------
// Per-batch transpose of V (float4 vectorized): vt[b][n][k] = v[b][k][n]
// ---------------------------------------------------------------------------
__global__ __launch_bounds__(256)
void transpose_v(const float* __restrict__ v, float* __restrict__ vt)
{
    __shared__ float t[32][129];
    const int b  = blockIdx.z;
    const int k0 = blockIdx.x * 32;
    const int n0 = blockIdx.y * 128;
    const int tx = threadIdx.x;
    const int ty = threadIdx.y;

    #pragma unroll
    for (int i = ty; i < 32; i += 8) {
        float4 val = *(const float4*)&v[((size_t)b * LK + k0 + i) * E_ + n0 + tx * 4];
        t[i][tx * 4 + 0] = val.x;
        t[i][tx * 4 + 1] = val.y;
        t[i][tx * 4 + 2] = val.z;
        t[i][tx * 4 + 3] = val.w;
    }
    __syncthreads();

    #pragma unroll
    for (int i = ty; i < 128; i += 8)
        vt[((size_t)b * E_ + n0 + i) * LK + k0 + tx] = t[tx][i];
}

// ---------------------------------------------------------------------------
// out = LayerNorm(a + b) * g + beta
// ---------------------------------------------------------------------------
template<int ROUND>
__global__ __launch_bounds__(256)
void ln_residual(const float* __restrict__ A, const float* __restrict__ Bx,
                 const float* __restrict__ g, const float* __restrict__ be,
                 float* __restrict__ out)
{
    const size_t row = blockIdx.x;
    const int t = threadIdx.x;

    float4 a = ((const float4*)(A  + row * E_))[t];
    float4 b = ((const float4*)(Bx + row * E_))[t];
    float4 x = make_float4(a.x + b.x, a.y + b.y, a.z + b.z, a.w + b.w);

    float s  = x.x + x.y + x.z + x.w;
    float ss = x.x*x.x + x.y*x.y + x.z*x.z + x.w*x.w;

    __shared__ float rs_[8], rss[8];
    #pragma unroll
    for (int o = 16; o > 0; o >>= 1) {
        s  += __shfl_xor_sync(0xffffffffu, s,  o);
        ss += __shfl_xor_sync(0xffffffffu, ss, o);
    }
    if ((t & 31) == 0) { rs_[t >> 5] = s; rss[t >> 5] = ss; }
    __syncthreads();
    s = 0.f; ss = 0.f;
    #pragma unroll
    for (int i = 0; i < 8; i++) { s += rs_[i]; ss += rss[i]; }

    const float mean = s * (1.0f / E_);
    const float var  = ss * (1.0f / E_) - mean * mean;
    const float inv  = rsqrtf(var + 1e-5f);

    float4 gg = ((const float4*)g)[t];
    float4 bb = ((const float4*)be)[t];
    float4 o;
    o.x = (x.x - mean) * inv * gg.x + bb.x;
    o.y = (x.y - mean) * inv * gg.y + bb.y;
    o.z = (x.z - mean) * inv * gg.z + bb.z;
    o.w = (x.w - mean) * inv * gg.w + bb.w;
    if (ROUND) {
        o.x = round_tf32(o.x); o.y = round_tf32(o.y);
        o.z = round_tf32(o.z); o.w = round_tf32(o.w);
    }
    ((float4*)(out + row * E_))[t] = o;
}

// ---------------------------------------------------------------------------
extern "C" void kernel_launch(void* const* d_in, const int* in_sizes, int n_in,
                              void* d_out, int out_size)
{
    const float* query = (const float*)d_in[0];
    const float* keyv  = (const float*)d_in[1];
    const float* wq = (const float*)d_in[2];
    const float* wk = (const float*)d_in[3];
    const float* wv = (const float*)d_in[4];
    const float* bq = (const float*)d_in[5];
    const float* bk = (const float*)d_in[6];
    const float* bv = (const float*)d_in[7];
    const float* wo = (const float*)d_in[8];
    const float* bo = (const float*)d_in[9];
    const float* g1 = (const float*)d_in[10];
    const float* be1 = (const float*)d_in[11];
    const float* w1 = (const float*)d_in[12];
    const float* b1 = (const float*)d_in[13];
    const float* w2 = (const float*)d_in[14];
    const float* b2 = (const float*)d_in[15];
    const float* g2 = (const float*)d_in[16];
    const float* be2 = (const float*)d_in[17];

    float* out = (float*)d_out;
    float* q3_out = out;
    float* attn   = out + (size_t)MQ * E_;

    float *gq, *gk, *gv, *gvt, *gctx, *gao, *gq2, *gf1, *gf2;
    float2 *sst, *rst;
    cudaGetSymbolAddress((void**)&gq,  g_q);
    cudaGetSymbolAddress((void**)&gk,  g_k);
    cudaGetSymbolAddress((void**)&gv,  g_v);
    cudaGetSymbolAddress((void**)&gvt, g_vt);
    cudaGetSymbolAddress((void**)&gctx, g_ctx);
    cudaGetSymbolAddress((void**)&gao, g_attnout);
    cudaGetSymbolAddress((void**)&gq2, g_q2);
    cudaGetSymbolAddress((void**)&gf1, g_ffn1);
    cudaGetSymbolAddress((void**)&gf2, g_ffn2);
    cudaGetSymbolAddress((void**)&sst, g_sstats);
    cudaGetSymbolAddress((void**)&rst, g_rowstats);

    // one-time setup
    static cudaStream_t s1 = nullptr, s2 = nullptr;
    static cudaEvent_t e0, e1, e2;
    if (!s1) {
        cudaFuncSetAttribute(tf32_gemm<128,128,64,32,0>,
                             cudaFuncAttributeMaxDynamicSharedMemorySize, 98304);
        cudaFuncSetAttribute(tf32_gemm<128,128,64,32,1>,
                             cudaFuncAttributeMaxDynamicSharedMemorySize, 98304);
        cudaFuncSetAttribute(tf32_gemm<128,64,32,32,0>,
                             cudaFuncAttributeMaxDynamicSharedMemorySize, 73728);
        cudaFuncSetAttribute(tf32_gemm<128,64,32,32,1>,
                             cudaFuncAttributeMaxDynamicSharedMemorySize, 73728);
        cudaStreamCreateWithFlags(&s1, cudaStreamNonBlocking);
        cudaStreamCreateWithFlags(&s2, cudaStreamNonBlocking);
        cudaEventCreateWithFlags(&e0, cudaEventDisableTiming);
        cudaEventCreateWithFlags(&e1, cudaEventDisableTiming);
        cudaEventCreateWithFlags(&e2, cudaEventDisableTiming);
    }
    const int GS128 = 98304;
    const int GS64  = 73728;

    // no prepass: all GEMM inputs fed raw (mma truncates fp32 -> tf32)

    // fork: default = K proj, s1 = V proj + transpose, s2 = Q proj
    cudaEventRecord(e0, 0);
    cudaStreamWaitEvent(s1, e0, 0);
    cudaStreamWaitEvent(s2, e0, 0);

    tf32_gemm<128,128,64,32,1><<<dim3(E_/128, MK/128), 256, GS128>>>(
        keyv, E_,  wk, E_,  bk,  gk, E_,  E_, 1.f, 0);

    tf32_gemm<128,128,64,32,1><<<dim3(E_/128, MK/128), 256, GS128, s1>>>(
        keyv, E_,  wv, E_,  bv,  gv, E_,  E_, 1.f, 0);
    transpose_v<<<dim3(LK/32, E_/128, B_), dim3(32, 8), 0, s1>>>(gv, gvt);
    cudaEventRecord(e1, s1);

    tf32_gemm<128,64,32,32,1><<<dim3(E_/64, MQ/128), 256, GS64, s2>>>(
        query, E_,  wq, E_,  bq,  gq, E_,  E_, 1.f, 0);
    cudaEventRecord(e2, s2);

    // join: scores needs Q (s2) and K (default)
    cudaStreamWaitEvent(0, e2, 0);
    scores_stats<<<dim3(LK/128, LQ/128, B_*H_), 256>>>(gq, gk, attn, sst);
    rowcombine<<<(B_*H_*LQ)/256, 256>>>(sst, rst);

    // ctx needs transpose (s1: e1)
    cudaStreamWaitEvent(0, e1, 0);
    ctx_fused<<<dim3(LQ/128, B_*H_), 256>>>(rst, attn, gvt, gctx);

    // ---- output projection + LN1 (raw wo) ----
    tf32_gemm<128,64,32,32,0><<<dim3(E_/64, MQ/128), 256, GS64>>>(
        gctx, E_,  wo, E_,  bo,  gao, E_,  E_, 1.f, 0);
    ln_residual<1><<<MQ, 256>>>(query, gao, g1, be1, gq2);

    // ---- FFN + LN2 (raw w1/w2) ----
    tf32_gemm<128,128,64,32,1><<<dim3(F_/128, MQ/128), 256, GS128>>>(
        gq2, E_,  w1, E_,  b1,  gf1, F_,  E_, 1.f, 1);
    tf32_gemm<128,64,32,32,0><<<dim3(E_/64, MQ/128), 256, GS64>>>(
        gf1, F_,  w2, F_,  b2,  gf2, E_,  F_, 1.f, 0);
    ln_residual<0><<<MQ, 256>>>(gq2, gf2, g2, be2, q3_out);
}